// round 12
// baseline (speedup 1.0000x reference)
#include <cuda_runtime.h>
#include <cuda_bf16.h>
#include <math.h>
#include <stdint.h>

#define B_ 16
#define C_ 512
#define N_ 4096
#define NSPLIT 8

// ---------------------------------------------------------------------------
// Scratch (device globals; allocation in kernel_launch is forbidden)
// ---------------------------------------------------------------------------
__device__ __align__(1024) __nv_bfloat16 g_Xhi [(size_t)B_ * C_ * N_];
__device__ __align__(1024) __nv_bfloat16 g_Xlo [(size_t)B_ * C_ * N_];
__device__ __align__(1024) __nv_bfloat16 g_XThi[(size_t)B_ * N_ * C_];
__device__ __align__(1024) __nv_bfloat16 g_XTlo[(size_t)B_ * N_ * C_];
__device__ __align__(1024) __nv_bfloat16 g_Ghi [B_ * C_ * C_], g_Glo [B_ * C_ * C_];
__device__ __align__(1024) __nv_bfloat16 g_T1hi[B_ * C_ * C_], g_T1lo[B_ * C_ * C_];
__device__ __align__(1024) __nv_bfloat16 g_AThi[B_ * C_ * C_], g_ATlo[B_ * C_ * C_];
__device__ __align__(1024) __nv_bfloat16 g_Mvhi[B_ * C_ * C_], g_Mvlo[B_ * C_ * C_];
__device__ __align__(1024) __nv_bfloat16 g_Wqhi[C_ * C_], g_Wqlo[C_ * C_];
__device__ __align__(1024) __nv_bfloat16 g_Wkhi[C_ * C_], g_Wklo[C_ * C_];
__device__ __align__(1024) __nv_bfloat16 g_WvThi[C_ * C_], g_WvTlo[C_ * C_];
__device__ float g_S[B_ * C_ * C_];
__device__ __align__(1024) float g_P[(size_t)B_ * 10 * NSPLIT * 16384];   // split-K partials (84MB)
__device__ float g_r[B_ * C_], g_qr[B_ * C_], g_kr[B_ * C_], g_beta[B_ * C_];

// Upper-triangle tile pair table for symmetric GEMM (4x4 -> 10 pairs)
__device__ __constant__ int c_ti[10] = {0,0,0,0,1,1,1,2,2,3};
__device__ __constant__ int c_tj[10] = {0,1,2,3,1,2,3,2,3,3};

// ---------------------------------------------------------------------------
// Helpers
// ---------------------------------------------------------------------------
__device__ __forceinline__ uint32_t smem_u32(const void* p) {
    uint32_t a;
    asm("{ .reg .u64 t; cvta.to.shared.u64 t, %1; cvt.u32.u64 %0, t; }" : "=r"(a) : "l"(p));
    return a;
}
__device__ __forceinline__ uint32_t sw128(uint32_t off) { return off ^ ((off >> 3) & 0x70); }

__device__ __forceinline__ uint32_t cvt2(float lo, float hi) {
    uint32_t r; asm("cvt.rn.bf16x2.f32 %0, %1, %2;" : "=r"(r) : "f"(hi), "f"(lo)); return r;
}
__device__ __forceinline__ float lof(uint32_t h) { return __uint_as_float(h << 16); }
__device__ __forceinline__ float hif(uint32_t h) { return __uint_as_float(h & 0xFFFF0000u); }

#define CP_ASYNC16(dst, src) \
    asm volatile("cp.async.cg.shared.global [%0], [%1], 16;" :: "r"(dst), "l"(src))
#define CP_COMMIT() asm volatile("cp.async.commit_group;")
#define CP_WAIT0()  asm volatile("cp.async.wait_group 0;")
#define CP_WAIT1()  asm volatile("cp.async.wait_group 1;")

#define LDSM4(r0, r1, r2, r3, addr) \
    asm volatile("ldmatrix.sync.aligned.m8n8.x4.shared.b16 {%0,%1,%2,%3}, [%4];" \
                 : "=r"(r0), "=r"(r1), "=r"(r2), "=r"(r3) : "r"(addr))

#define MMA16816(c, a, b) \
    asm volatile("mma.sync.aligned.m16n8k16.row.col.f32.bf16.bf16.f32 " \
                 "{%0,%1,%2,%3},{%4,%5,%6,%7},{%8,%9},{%0,%1,%2,%3};" \
                 : "+f"((c)[0]), "+f"((c)[1]), "+f"((c)[2]), "+f"((c)[3]) \
                 : "r"((a)[0]), "r"((a)[1]), "r"((a)[2]), "r"((a)[3]), \
                   "r"((b)[0]), "r"((b)[1]))

#define GEMM_SMEM 196608      // sym core: 3 stages x 64KB
#define BIG_SMEM  147456      // big core: 3 stages x 48KB (BK=32, hi/lo packed rows)
#define NT 512                // threads per GEMM CTA (16 warps)

// ---------------------------------------------------------------------------
// SYM core (unchanged, measured 64.5% tensor): CTA 128x128, warp 32x32, BK=64,
// 3-stage, prefetch-before-compute, separate hi/lo planes in smem.
// ---------------------------------------------------------------------------
__device__ __forceinline__ void gemm_core(
    const __nv_bfloat16* __restrict__ Ah, const __nv_bfloat16* __restrict__ Al, int lda,
    const __nv_bfloat16* __restrict__ Bh, const __nv_bfloat16* __restrict__ Bl, int ldb,
    int K, uint32_t sb, int tid, int wid, int lane, float acc[2][4][4]) {

    #pragma unroll
    for (int mi = 0; mi < 2; ++mi)
        #pragma unroll
        for (int ni = 0; ni < 4; ++ni)
            #pragma unroll
            for (int e = 0; e < 4; ++e) acc[mi][ni][e] = 0.f;

    const int nit = K >> 6;

    auto load_stage = [&](int s, int k0) {
        const uint32_t S = sb + (uint32_t)s * 65536u;
        #pragma unroll
        for (int j = 0; j < 2; ++j) {
            const int id = tid + NT * j;
            const int row = id >> 3;
            const int c = id & 7;
            const uint32_t off = sw128((uint32_t)row * 128u + (uint32_t)c * 16u);
            const size_t ga = (size_t)row * lda + k0 + c * 8;
            const size_t gb = (size_t)row * ldb + k0 + c * 8;
            CP_ASYNC16(S + off,          Ah + ga);
            CP_ASYNC16(S + 16384 + off,  Al + ga);
            CP_ASYNC16(S + 32768 + off,  Bh + gb);
            CP_ASYNC16(S + 49152 + off,  Bl + gb);
        }
    };

    load_stage(0, 0);
    CP_COMMIT();
    if (nit > 1) { load_stage(1, 64); }
    CP_COMMIT();

    const int m0l = (wid & 3) * 32;
    const int n0l = (wid >> 2) * 32;

    int s = 0;
    for (int it = 0; it < nit; ++it) {
        if (it + 1 < nit) { CP_WAIT1(); } else { CP_WAIT0(); }
        __syncthreads();

        {
            int s2 = s + 2; if (s2 >= 3) s2 -= 3;
            if (it + 2 < nit) load_stage(s2, (it + 2) * 64);
            CP_COMMIT();
        }

        const uint32_t Sa = sb + (uint32_t)s * 65536u;
        const uint32_t Sb = Sa + 32768;

        #pragma unroll
        for (int ks = 0; ks < 4; ++ks) {
            const uint32_t kb = (uint32_t)ks * 32u;
            uint32_t ah[2][4], al[2][4];
            #pragma unroll
            for (int mi = 0; mi < 2; ++mi) {
                const uint32_t ad = Sa + sw128(
                    (uint32_t)(m0l + mi * 16 + (lane & 15)) * 128u + kb + (uint32_t)(lane >> 4) * 16u);
                LDSM4(ah[mi][0], ah[mi][1], ah[mi][2], ah[mi][3], ad);
                LDSM4(al[mi][0], al[mi][1], al[mi][2], al[mi][3], ad + 16384);
            }
            uint32_t bh4[4][2], bl4[4][2];
            #pragma unroll
            for (int np = 0; np < 2; ++np) {
                const uint32_t bd = Sb + sw128(
                    (uint32_t)(n0l + np * 16 + (lane >> 4) * 8 + (lane & 7)) * 128u +
                    kb + (uint32_t)((lane >> 3) & 1) * 16u);
                uint32_t r0, r1, r2, r3;
                LDSM4(r0, r1, r2, r3, bd);
                bh4[np * 2][0] = r0; bh4[np * 2][1] = r1;
                bh4[np * 2 + 1][0] = r2; bh4[np * 2 + 1][1] = r3;
                LDSM4(r0, r1, r2, r3, bd + 16384);
                bl4[np * 2][0] = r0; bl4[np * 2][1] = r1;
                bl4[np * 2 + 1][0] = r2; bl4[np * 2 + 1][1] = r3;
            }
            #pragma unroll
            for (int mi = 0; mi < 2; ++mi)
                #pragma unroll
                for (int ni = 0; ni < 4; ++ni) {
                    MMA16816(acc[mi][ni], ah[mi], bh4[ni]);
                    MMA16816(acc[mi][ni], ah[mi], bl4[ni]);
                    MMA16816(acc[mi][ni], al[mi], bh4[ni]);
                }
        }

        if (++s == 3) s = 0;
    }
}

// ---------------------------------------------------------------------------
// BIG core: CTA 256x128, 16 warps of 64x32, BK=32, 3-stage (48KB/stage),
// prefetch-before-compute. hi/lo packed per 128B row: bytes 0-63 hi, 64-127 lo
// (sw128(x+64) == sw128(x)^64 for in-row x<64). A-lo reloads into A-hi regs.
// Stage layout: A @0 (32KB, 256 rows), B @32768 (16KB, 128 rows).
// ---------------------------------------------------------------------------
__device__ __forceinline__ void gemm_core_big(
    const __nv_bfloat16* __restrict__ Ah, const __nv_bfloat16* __restrict__ Al, int lda,
    const __nv_bfloat16* __restrict__ Bh, const __nv_bfloat16* __restrict__ Bl, int ldb,
    int K, uint32_t sb, int tid, int wid, int lane, float acc[4][4][4]) {

    #pragma unroll
    for (int mi = 0; mi < 4; ++mi)
        #pragma unroll
        for (int ni = 0; ni < 4; ++ni)
            #pragma unroll
            for (int e = 0; e < 4; ++e) acc[mi][ni][e] = 0.f;

    const int nit = K >> 5;   // BK = 32

    auto load_stage = [&](int s, int k0) {
        const uint32_t S = sb + (uint32_t)s * 49152u;
        // A: 256 rows x 8 chunks (c 0-3 hi, 4-7 lo) = 2048
        #pragma unroll
        for (int j = 0; j < 4; ++j) {
            const int id = tid + NT * j;
            const int row = id >> 3;
            const int c = id & 7;
            const uint32_t off = sw128((uint32_t)row * 128u + (uint32_t)c * 16u);
            const __nv_bfloat16* src = ((c & 4) ? Al : Ah) + (size_t)row * lda + k0 + (c & 3) * 8;
            CP_ASYNC16(S + off, src);
        }
        // B: 128 rows x 8 chunks = 1024
        #pragma unroll
        for (int j = 0; j < 2; ++j) {
            const int id = tid + NT * j;
            const int row = id >> 3;
            const int c = id & 7;
            const uint32_t off = sw128((uint32_t)row * 128u + (uint32_t)c * 16u) + 32768u;
            const __nv_bfloat16* src = ((c & 4) ? Bl : Bh) + (size_t)row * ldb + k0 + (c & 3) * 8;
            CP_ASYNC16(S + off, src);
        }
    };

    load_stage(0, 0);
    CP_COMMIT();
    if (nit > 1) { load_stage(1, 32); }
    CP_COMMIT();

    const int m0l = (wid & 3) * 64;     // 4 warps in M over 256
    const int n0l = (wid >> 2) * 32;    // 4 warps in N over 128

    int s = 0;
    for (int it = 0; it < nit; ++it) {
        if (it + 1 < nit) { CP_WAIT1(); } else { CP_WAIT0(); }
        __syncthreads();

        {
            int s2 = s + 2; if (s2 >= 3) s2 -= 3;
            if (it + 2 < nit) load_stage(s2, (it + 2) * 32);
            CP_COMMIT();
        }

        const uint32_t Sa = sb + (uint32_t)s * 49152u;
        const uint32_t Sb = Sa + 32768u;

        #pragma unroll
        for (int ks = 0; ks < 2; ++ks) {
            const uint32_t kb = (uint32_t)ks * 32u;   // k16 step = 32 bytes in hi half
            uint32_t af[4][4];
            uint32_t aad[4];
            #pragma unroll
            for (int mi = 0; mi < 4; ++mi) {
                aad[mi] = Sa + sw128(
                    (uint32_t)(m0l + mi * 16 + (lane & 15)) * 128u + kb + (uint32_t)(lane >> 4) * 16u);
                LDSM4(af[mi][0], af[mi][1], af[mi][2], af[mi][3], aad[mi]);
            }
            uint32_t bh4[4][2], bl4[4][2];
            #pragma unroll
            for (int np = 0; np < 2; ++np) {
                const uint32_t bd = Sb + sw128(
                    (uint32_t)(n0l + np * 16 + (lane >> 4) * 8 + (lane & 7)) * 128u +
                    kb + (uint32_t)((lane >> 3) & 1) * 16u);
                uint32_t r0, r1, r2, r3;
                LDSM4(r0, r1, r2, r3, bd);
                bh4[np * 2][0] = r0; bh4[np * 2][1] = r1;
                bh4[np * 2 + 1][0] = r2; bh4[np * 2 + 1][1] = r3;
                LDSM4(r0, r1, r2, r3, bd ^ 64u);     // lo half of the same rows
                bl4[np * 2][0] = r0; bl4[np * 2][1] = r1;
                bl4[np * 2 + 1][0] = r2; bl4[np * 2 + 1][1] = r3;
            }
            // hi*hi and hi*lo
            #pragma unroll
            for (int mi = 0; mi < 4; ++mi)
                #pragma unroll
                for (int ni = 0; ni < 4; ++ni) {
                    MMA16816(acc[mi][ni], af[mi], bh4[ni]);
                    MMA16816(acc[mi][ni], af[mi], bl4[ni]);
                }
            // reload A-lo into same regs (proven-free in round 11), then lo*hi
            #pragma unroll
            for (int mi = 0; mi < 4; ++mi)
                LDSM4(af[mi][0], af[mi][1], af[mi][2], af[mi][3], aad[mi] ^ 64u);
            #pragma unroll
            for (int mi = 0; mi < 4; ++mi)
                #pragma unroll
                for (int ni = 0; ni < 4; ++ni)
                    MMA16816(acc[mi][ni], af[mi], bh4[ni]);
        }

        if (++s == 3) s = 0;
    }
}

// ---------------------------------------------------------------------------
// General bf16 HMMA GEMM (BIG core). CTA tile 256x128.
// OM: 0 fp32 out, 1 bf16 hi/lo out, 2 fp32 + per-row bias.
// ---------------------------------------------------------------------------
template <int OM>
__global__ void __launch_bounds__(NT, 1)
gemm_mma(const __nv_bfloat16* __restrict__ Ahi, const __nv_bfloat16* __restrict__ Alo,
         int lda, long long sA,
         const __nv_bfloat16* __restrict__ Bhi, const __nv_bfloat16* __restrict__ Blo,
         int ldb, long long sB,
         float* __restrict__ Cf, __nv_bfloat16* __restrict__ Chi,
         __nv_bfloat16* __restrict__ Clo, int ldc, long long sC,
         const float* __restrict__ bias, int K) {
    extern __shared__ char smem[];
    const uint32_t sb = smem_u32(smem);
    const int tid = threadIdx.x;
    const int wid = tid >> 5;
    const int lane = tid & 31;
    const int bz = blockIdx.z;
    const int bm = blockIdx.y * 256;
    const int bn = blockIdx.x * 128;

    float acc[4][4][4];
    gemm_core_big(Ahi + (size_t)bz * sA + (size_t)bm * lda,
                  Alo + (size_t)bz * sA + (size_t)bm * lda, lda,
                  Bhi + (size_t)bz * sB + (size_t)bn * ldb,
                  Blo + (size_t)bz * sB + (size_t)bn * ldb, ldb,
                  K, sb, tid, wid, lane, acc);

    float* Cfb = Cf ? (Cf + (size_t)bz * sC) : nullptr;
    __nv_bfloat16* Chb = Chi ? (Chi + (size_t)bz * sC) : nullptr;
    __nv_bfloat16* Clb = Clo ? (Clo + (size_t)bz * sC) : nullptr;

    const int m0l = (wid & 3) * 64;
    const int n0l = (wid >> 2) * 32;

    #pragma unroll
    for (int mi = 0; mi < 4; ++mi) {
        #pragma unroll
        for (int h = 0; h < 2; ++h) {
            const int row = bm + m0l + mi * 16 + (lane >> 2) + h * 8;
            float bb = 0.f;
            if (OM == 2) bb = bias[bz * C_ + row];
            #pragma unroll
            for (int ni = 0; ni < 4; ++ni) {
                const int col = bn + n0l + ni * 8 + (lane & 3) * 2;
                const float v0 = acc[mi][ni][h * 2 + 0];
                const float v1 = acc[mi][ni][h * 2 + 1];
                if (OM == 1) {
                    const uint32_t hh = cvt2(v0, v1);
                    const uint32_t ll = cvt2(v0 - lof(hh), v1 - hif(hh));
                    *(uint32_t*)(Chb + (size_t)row * ldc + col) = hh;
                    *(uint32_t*)(Clb + (size_t)row * ldc + col) = ll;
                } else {
                    float2 v; v.x = v0 + bb; v.y = v1 + bb;
                    *(float2*)(Cfb + (size_t)row * ldc + col) = v;
                }
            }
        }
    }
}

// ---------------------------------------------------------------------------
// Split-K symmetric GEMM stage 1 (SYM core, unchanged). Grid (10, NSPLIT, B_).
// ---------------------------------------------------------------------------
__global__ void __launch_bounds__(NT, 1)
gemm_sym_k(const __nv_bfloat16* __restrict__ Xhi, const __nv_bfloat16* __restrict__ Xlo,
           float* __restrict__ P) {
    extern __shared__ char smem[];
    const uint32_t sb = smem_u32(smem);
    const int tid = threadIdx.x;
    const int wid = tid >> 5;
    const int lane = tid & 31;
    const int bz = blockIdx.z;
    const int split = blockIdx.y;
    const int ti = c_ti[blockIdx.x];
    const int tj = c_tj[blockIdx.x];
    const int bm = ti * 128;
    const int bn = tj * 128;
    const int k0 = split * (N_ / NSPLIT);

    const size_t xb = (size_t)bz * ((size_t)C_ * N_);
    float acc[2][4][4];
    gemm_core(Xhi + xb + (size_t)bm * N_ + k0, Xlo + xb + (size_t)bm * N_ + k0, N_,
              Xhi + xb + (size_t)bn * N_ + k0, Xlo + xb + (size_t)bn * N_ + k0, N_,
              N_ / NSPLIT, sb, tid, wid, lane, acc);

    float* Pt = P + (((size_t)bz * 10 + blockIdx.x) * NSPLIT + split) * 16384;
    const int m0l = (wid & 3) * 32;
    const int n0l = (wid >> 2) * 32;

    #pragma unroll
    for (int mi = 0; mi < 2; ++mi)
        #pragma unroll
        for (int h = 0; h < 2; ++h) {
            const int row = m0l + mi * 16 + (lane >> 2) + h * 8;
            #pragma unroll
            for (int ni = 0; ni < 4; ++ni) {
                const int col = n0l + ni * 8 + (lane & 3) * 2;
                float2 v;
                v.x = acc[mi][ni][h * 2 + 0];
                v.y = acc[mi][ni][h * 2 + 1];
                *(float2*)(Pt + row * 128 + col) = v;
            }
        }
}

// ---------------------------------------------------------------------------
// Split-K combine (unchanged)
// ---------------------------------------------------------------------------
#define COMB_SMEM (128 * 132 * 4)
__global__ void __launch_bounds__(256, 1)
combine_sym(const float* __restrict__ P,
            __nv_bfloat16* __restrict__ Ghi, __nv_bfloat16* __restrict__ Glo) {
    extern __shared__ char smem[];
    float* st = (float*)smem;
    const int tid = threadIdx.x;
    const int t = blockIdx.x % 10;
    const int bz = blockIdx.x / 10;
    const int ti = c_ti[t];
    const int tj = c_tj[t];
    const int bm = ti * 128;
    const int bn = tj * 128;

    const float* Pb = P + ((size_t)bz * 10 + t) * NSPLIT * 16384;

    #pragma unroll
    for (int j = 0; j < 16; ++j) {
        const int cid = tid + 256 * j;
        const int row = cid >> 5;
        const int c4 = cid & 31;
        float4 s = *(const float4*)(Pb + cid * 4);
        #pragma unroll
        for (int sp = 1; sp < NSPLIT; ++sp) {
            const float4 a = *(const float4*)(Pb + sp * 16384 + cid * 4);
            s.x += a.x; s.y += a.y; s.z += a.z; s.w += a.w;
        }
        float* d = st + row * 132 + c4 * 4;
        d[0] = s.x; d[1] = s.y; d[2] = s.z; d[3] = s.w;
    }
    __syncthreads();

    __nv_bfloat16* Gh = Ghi + (size_t)bz * (C_ * C_);
    __nv_bfloat16* Gl = Glo + (size_t)bz * (C_ * C_);

    #pragma unroll
    for (int j = 0; j < 16; ++j) {
        const int cid = tid + 256 * j;
        const int row = cid >> 5;
        const int c4 = cid & 31;
        const float4 v = *(const float4*)(st + row * 132 + c4 * 4);
        const uint32_t h0 = cvt2(v.x, v.y), h1 = cvt2(v.z, v.w);
        const uint32_t l0 = cvt2(v.x - lof(h0), v.y - hif(h0));
        const uint32_t l1 = cvt2(v.z - lof(h1), v.w - hif(h1));
        const size_t o = (size_t)(bm + row) * C_ + bn + c4 * 4;
        *(uint2*)(Gh + o) = make_uint2(h0, h1);
        *(uint2*)(Gl + o) = make_uint2(l0, l1);
    }

    if (ti != tj) {
        #pragma unroll
        for (int j = 0; j < 16; ++j) {
            const int cid = tid + 256 * j;
            const int mr = cid >> 5;
            const int mc4 = cid & 31;
            float v0 = st[(mc4 * 4 + 0) * 132 + mr];
            float v1 = st[(mc4 * 4 + 1) * 132 + mr];
            float v2 = st[(mc4 * 4 + 2) * 132 + mr];
            float v3 = st[(mc4 * 4 + 3) * 132 + mr];
            const uint32_t h0 = cvt2(v0, v1), h1 = cvt2(v2, v3);
            const uint32_t l0 = cvt2(v0 - lof(h0), v1 - hif(h0));
            const uint32_t l1 = cvt2(v2 - lof(h1), v3 - hif(h1));
            const size_t o = (size_t)(bn + mr) * C_ + bm + mc4 * 4;
            *(uint2*)(Gh + o) = make_uint2(h0, h1);
            *(uint2*)(Gl + o) = make_uint2(l0, l1);
        }
    }
}

// ---------------------------------------------------------------------------
// Fused X prep: Xhi/Xlo + XThi/XTlo in one pass
// ---------------------------------------------------------------------------
__global__ void __launch_bounds__(256)
prep_x(const float* __restrict__ x,
       __nv_bfloat16* __restrict__ xhi, __nv_bfloat16* __restrict__ xlo,
       __nv_bfloat16* __restrict__ xthi, __nv_bfloat16* __restrict__ xtlo) {
    __shared__ float t[32][33];
    const int tx = threadIdx.x & 31, ty = threadIdx.x >> 5;
    const int b = blockIdx.z;
    const int c0 = blockIdx.y * 32;
    const int n0 = blockIdx.x * 32;
    const float* s = x + (size_t)b * C_ * N_;
    __nv_bfloat16* xh = xhi + (size_t)b * C_ * N_;
    __nv_bfloat16* xl = xlo + (size_t)b * C_ * N_;
    __nv_bfloat16* th = xthi + (size_t)b * N_ * C_;
    __nv_bfloat16* tl = xtlo + (size_t)b * N_ * C_;

    #pragma unroll
    for (int k = 0; k < 4; ++k) {
        const int cr = ty + 8 * k;
        const float v = s[(size_t)(c0 + cr) * N_ + n0 + tx];
        t[cr][tx] = v;
        __nv_bfloat16 h = __float2bfloat16(v);
        __nv_bfloat16 l = __float2bfloat16(v - __bfloat162float(h));
        const size_t o = (size_t)(c0 + cr) * N_ + n0 + tx;
        xh[o] = h; xl[o] = l;
    }
    __syncthreads();
    #pragma unroll
    for (int k = 0; k < 4; ++k) {
        const int i = ty + 8 * k;
        const float v = t[tx][i];
        __nv_bfloat16 h = __float2bfloat16(v);
        __nv_bfloat16 l = __float2bfloat16(v - __bfloat162float(h));
        const size_t o = (size_t)(n0 + i) * C_ + c0 + tx;
        th[o] = h; tl[o] = l;
    }
}

// ---------------------------------------------------------------------------
// Fused Wq + Wk split
// ---------------------------------------------------------------------------
__global__ void __launch_bounds__(256)
split_qk(const float* __restrict__ wq, const float* __restrict__ wk,
         __nv_bfloat16* __restrict__ qhi, __nv_bfloat16* __restrict__ qlo,
         __nv_bfloat16* __restrict__ khi, __nv_bfloat16* __restrict__ klo,
         long long n4) {
    long long i = (long long)blockIdx.x * blockDim.x + threadIdx.x;
    const long long stride = (long long)gridDim.x * blockDim.x;
    for (; i < n4; i += stride) {
        float4 v = ((const float4*)wq)[i];
        uint32_t h0 = cvt2(v.x, v.y), h1 = cvt2(v.z, v.w);
        uint32_t l0 = cvt2(v.x - lof(h0), v.y - hif(h0));
        uint32_t l1 = cvt2(v.z - lof(h1), v.w - hif(h1));
        ((uint2*)qhi)[i] = make_uint2(h0, h1);
        ((uint2*)qlo)[i] = make_uint2(l0, l1);
        v = ((const float4*)wk)[i];
        h0 = cvt2(v.x, v.y); h1 = cvt2(v.z, v.w);
        l0 = cvt2(v.x - lof(h0), v.y - hif(h0));
        l1 = cvt2(v.z - lof(h1), v.w - hif(h1));
        ((uint2*)khi)[i] = make_uint2(h0, h1);
        ((uint2*)klo)[i] = make_uint2(l0, l1);
    }
}

// ---------------------------------------------------------------------------
// r[b,c] = sum_n X[b,c,n]
// ---------------------------------------------------------------------------
__global__ void __launch_bounds__(256) row_sum_kernel(const float* __restrict__ x,
                                                      float* __restrict__ r) {
    const int row = blockIdx.x;
    const float4* xr = (const float4*)(x + (size_t)row * N_);
    float s = 0.f;
    for (int i = threadIdx.x; i < N_ / 4; i += 256) {
        float4 v = xr[i];
        s += v.x + v.y + v.z + v.w;
    }
    __shared__ float sm[256];
    sm[threadIdx.x] = s;
    __syncthreads();
    #pragma unroll
    for (int off = 128; off > 0; off >>= 1) {
        if (threadIdx.x < off) sm[threadIdx.x] += sm[threadIdx.x + off];
        __syncthreads();
    }
    if (threadIdx.x == 0) r[row] = sm[0];
}

// ---------------------------------------------------------------------------
// qr = Wq r, kr = Wk r (all batches)
// ---------------------------------------------------------------------------
__global__ void __launch_bounds__(256) matvec_qk_kernel(const float* __restrict__ Wq,
                                                        const float* __restrict__ Wk,
                                                        const float* __restrict__ r,
                                                        float* __restrict__ qr,
                                                        float* __restrict__ kr) {
    const int b = blockIdx.y;
    const int warp = threadIdx.x >> 5;
    const int lane = threadIdx.x & 31;
    const int o = blockIdx.x * 8 + warp;
    const float* rb = r + b * C_;
    float sq = 0.f, sk = 0.f;
    for (int i = lane; i < C_; i += 32) {
        float rv = rb[i];
        sq += Wq[(size_t)o * C_ + i] * rv;
        sk += Wk[(size_t)o * C_ + i] * rv;
    }
    #pragma unroll
    for (int off = 16; off > 0; off >>= 1) {
        sq += __shfl_down_sync(0xFFFFFFFFu, sq, off);
        sk += __shfl_down_sync(0xFFFFFFFFu, sk, off);
    }
    if (lane == 0) { qr[b * C_ + o] = sq; kr[b * C_ + o] = sk; }
}

// ---------------------------------------------------------------------------
// Transpose + bf16 split (for Wv)
// ---------------------------------------------------------------------------
__global__ void __launch_bounds__(256)
transpose_cvt(const float* __restrict__ s, __nv_bfloat16* __restrict__ dhi,
              __nv_bfloat16* __restrict__ dlo, int R, int Cc) {
    __shared__ float t[32][33];
    const int tx = threadIdx.x & 31, ty = threadIdx.x >> 5;
    const int r0 = blockIdx.y * 32, c0 = blockIdx.x * 32;
    #pragma unroll
    for (int k = 0; k < 4; ++k)
        t[ty + 8 * k][tx] = s[(size_t)(r0 + ty + 8 * k) * Cc + c0 + tx];
    __syncthreads();
    #pragma unroll
    for (int k = 0; k < 4; ++k) {
        const int i = ty + 8 * k;
        const float v = t[tx][i];
        __nv_bfloat16 h = __float2bfloat16(v);
        __nv_bfloat16 l = __float2bfloat16(v - __bfloat162float(h));
        const size_t o = (size_t)(c0 + i) * R + r0 + tx;
        dhi[o] = h; dlo[o] = l;
    }
}

// ---------------------------------------------------------------------------
// Softmax with rank-1 bias corrections; attn -> bf16 hi/lo planes + beta
// ---------------------------------------------------------------------------
__global__ void __launch_bounds__(256)
softmax_beta_kernel(const float* __restrict__ S,
                    const float* __restrict__ qr, const float* __restrict__ kr,
                    const float* __restrict__ bq, const float* __restrict__ bk,
                    const float* __restrict__ bv,
                    __nv_bfloat16* __restrict__ Ahi, __nv_bfloat16* __restrict__ Alo,
                    float* __restrict__ beta) {
    __shared__ float sm[256];
    const int row = blockIdx.x;
    const int b = row >> 9;
    const int c = row & (C_ - 1);
    const float* Sr = S + (size_t)row * C_;
    const float* krb = kr + b * C_;
    const float qrc = qr[row];
    const float bqc = bq[c];
    const float scale = rsqrtf((float)C_);
    const int t = threadIdx.x;

    float v[2];
    float mx = -1e30f;
    #pragma unroll
    for (int u = 0; u < 2; ++u) {
        const int d = t + u * 256;
        float s = (Sr[d] + qrc * bk[d] + bqc * krb[d] + (float)N_ * bqc * bk[d]) * scale;
        v[u] = s;
        mx = fmaxf(mx, s);
    }
    sm[t] = mx; __syncthreads();
    #pragma unroll
    for (int off = 128; off > 0; off >>= 1) {
        if (t < off) sm[t] = fmaxf(sm[t], sm[t + off]);
        __syncthreads();
    }
    mx = sm[0];
    __syncthreads();

    float sum = 0.f;
    #pragma unroll
    for (int u = 0; u < 2; ++u) { v[u] = expf(v[u] - mx); sum += v[u]; }
    sm[t] = sum; __syncthreads();
    #pragma unroll
    for (int off = 128; off > 0; off >>= 1) {
        if (t < off) sm[t] += sm[t + off];
        __syncthreads();
    }
    const float inv = 1.f / sm[0];
    __syncthreads();

    float bc = 0.f;
    #pragma unroll
    for (int u = 0; u < 2; ++u) {
        const int d = t + u * 256;
        const float p = v[u] * inv;
        __nv_bfloat16 h = __float2bfloat16(p);
        __nv_bfloat16 l = __float2bfloat16(p - __bfloat162float(h));
        Ahi[(size_t)row * C_ + d] = h;
        Alo[(size_t)row * C_ + d] = l;
        bc += p * bv[d];
    }
    sm[t] = bc; __syncthreads();
    #pragma unroll
    for (int off = 128; off > 0; off >>= 1) {
        if (t < off) sm[t] += sm[t + off];
        __syncthreads();
    }
    if (t == 0) beta[row] = sm[0];
}

// ---------------------------------------------------------------------------
extern "C" void kernel_launch(void* const* d_in, const int* in_sizes, int n_in,
                              void* d_out, int out_size) {
    const float* x  = (const float*)d_in[0];
    const float* Wq = (const float*)d_in[1];
    const float* bq = (const float*)d_in[2];
    const float* Wk = (const float*)d_in[3];
    const float* bk = (const float*)d_in[4];
    const float* Wv = (const float*)d_in[5];
    const float* bv = (const float*)d_in[6];
    float* out = (float*)d_out;

    __nv_bfloat16 *Xhi, *Xlo, *XThi, *XTlo, *Ghi, *Glo, *T1hi, *T1lo;
    __nv_bfloat16 *AThi, *ATlo, *Mvhi, *Mvlo, *Wqhi, *Wqlo, *Wkhi, *Wklo, *WvThi, *WvTlo;
    float *S, *P, *r, *qr, *kr, *beta;
    cudaGetSymbolAddress((void**)&Xhi, g_Xhi);     cudaGetSymbolAddress((void**)&Xlo, g_Xlo);
    cudaGetSymbolAddress((void**)&XThi, g_XThi);   cudaGetSymbolAddress((void**)&XTlo, g_XTlo);
    cudaGetSymbolAddress((void**)&Ghi, g_Ghi);     cudaGetSymbolAddress((void**)&Glo, g_Glo);
    cudaGetSymbolAddress((void**)&T1hi, g_T1hi);   cudaGetSymbolAddress((void**)&T1lo, g_T1lo);
    cudaGetSymbolAddress((void**)&AThi, g_AThi);   cudaGetSymbolAddress((void**)&ATlo, g_ATlo);
    cudaGetSymbolAddress((void**)&Mvhi, g_Mvhi);   cudaGetSymbolAddress((void**)&Mvlo, g_Mvlo);
    cudaGetSymbolAddress((void**)&Wqhi, g_Wqhi);   cudaGetSymbolAddress((void**)&Wqlo, g_Wqlo);
    cudaGetSymbolAddress((void**)&Wkhi, g_Wkhi);   cudaGetSymbolAddress((void**)&Wklo, g_Wklo);
    cudaGetSymbolAddress((void**)&WvThi, g_WvThi); cudaGetSymbolAddress((void**)&WvTlo, g_WvTlo);
    cudaGetSymbolAddress((void**)&S, g_S);         cudaGetSymbolAddress((void**)&P, g_P);
    cudaGetSymbolAddress((void**)&r, g_r);   cudaGetSymbolAddress((void**)&qr, g_qr);
    cudaGetSymbolAddress((void**)&kr, g_kr); cudaGetSymbolAddress((void**)&beta, g_beta);

    const long long CN = (long long)C_ * N_;
    const long long CC = (long long)C_ * C_;
    const long long NC = (long long)N_ * C_;

    cudaFuncSetAttribute(gemm_mma<0>, cudaFuncAttributeMaxDynamicSharedMemorySize, BIG_SMEM);
    cudaFuncSetAttribute(gemm_mma<1>, cudaFuncAttributeMaxDynamicSharedMemorySize, BIG_SMEM);
    cudaFuncSetAttribute(gemm_mma<2>, cudaFuncAttributeMaxDynamicSharedMemorySize, BIG_SMEM);
    cudaFuncSetAttribute(gemm_sym_k,  cudaFuncAttributeMaxDynamicSharedMemorySize, GEMM_SMEM);
    cudaFuncSetAttribute(combine_sym, cudaFuncAttributeMaxDynamicSharedMemorySize, COMB_SMEM);

    // Launch order keeps gemm_sym_k at index 3 (the slot ncu captures) as a control.
    prep_x<<<dim3(N_ / 32, C_ / 32, B_), 256>>>(x, Xhi, Xlo, XThi, XTlo);            // 0
    row_sum_kernel<<<B_ * C_, 256>>>(x, r);                                          // 1
    split_qk<<<256, 256>>>(Wq, Wk, Wqhi, Wqlo, Wkhi, Wklo, CC / 4);                  // 2

    // G = X X^T, symmetric upper-triangle, split-K=NSPLIT -> fp32 partials
    gemm_sym_k<<<dim3(10, NSPLIT, B_), NT, GEMM_SMEM>>>(Xhi, Xlo, P);                // 3

    combine_sym<<<10 * B_, 256, COMB_SMEM>>>(P, Ghi, Glo);                           // 4
    transpose_cvt<<<dim3(C_ / 32, C_ / 32), 256>>>(Wv, WvThi, WvTlo, C_, C_);        // 5
    matvec_qk_kernel<<<dim3(C_ / 8, B_), 256>>>(Wq, Wk, r, qr, kr);                  // 6

    // T1 = Wq G   (CTA 256x128: grid (N/128, M/256))
    gemm_mma<1><<<dim3(4, 2, B_), NT, BIG_SMEM>>>(
        Wqhi, Wqlo, C_, 0,  Ghi, Glo, C_, CC,
        nullptr, T1hi, T1lo, C_, CC, nullptr, C_);

    // S = T1 Wk^T (fp32 out)
    gemm_mma<0><<<dim3(4, 2, B_), NT, BIG_SMEM>>>(
        T1hi, T1lo, C_, CC,  Wkhi, Wklo, C_, 0,
        S, nullptr, nullptr, C_, CC, nullptr, C_);

    // softmax(+rank-1 corrections) -> attn hl, beta = attn bv
    softmax_beta_kernel<<<B_ * C_, 256>>>(S, qr, kr, bq, bk, bv, AThi, ATlo, beta);

    // Mv = attn Wv (B = WvT rows)
    gemm_mma<1><<<dim3(4, 2, B_), NT, BIG_SMEM>>>(
        AThi, ATlo, C_, CC,  WvThi, WvTlo, C_, 0,
        nullptr, Mvhi, Mvlo, C_, CC, nullptr, C_);

    // out = Mv X + beta (B = XT rows)
    gemm_mma<2><<<dim3(32, 2, B_), NT, BIG_SMEM>>>(
        Mvhi, Mvlo, C_, CC,  XThi, XTlo, C_, NC,
        out, nullptr, nullptr, N_, CN, beta, C_);
}

// round 13
// speedup vs baseline: 1.0801x; 1.0801x over previous
#include <cuda_runtime.h>
#include <cuda_bf16.h>
#include <math.h>
#include <stdint.h>

#define B_ 16
#define C_ 512
#define N_ 4096
#define NSPLIT 8

// ---------------------------------------------------------------------------
// Scratch (device globals; allocation in kernel_launch is forbidden)
// ---------------------------------------------------------------------------
__device__ __align__(1024) __nv_bfloat16 g_Xhi [(size_t)B_ * C_ * N_];
__device__ __align__(1024) __nv_bfloat16 g_Xlo [(size_t)B_ * C_ * N_];
__device__ __align__(1024) __nv_bfloat16 g_XThi[(size_t)B_ * N_ * C_];
__device__ __align__(1024) __nv_bfloat16 g_XTlo[(size_t)B_ * N_ * C_];
__device__ __align__(1024) __nv_bfloat16 g_Ghi [B_ * C_ * C_], g_Glo [B_ * C_ * C_];
__device__ __align__(1024) __nv_bfloat16 g_T1hi[B_ * C_ * C_], g_T1lo[B_ * C_ * C_];
__device__ __align__(1024) __nv_bfloat16 g_AThi[B_ * C_ * C_], g_ATlo[B_ * C_ * C_];
__device__ __align__(1024) __nv_bfloat16 g_Mvhi[B_ * C_ * C_], g_Mvlo[B_ * C_ * C_];
__device__ __align__(1024) __nv_bfloat16 g_Wqhi[C_ * C_], g_Wqlo[C_ * C_];
__device__ __align__(1024) __nv_bfloat16 g_Wkhi[C_ * C_], g_Wklo[C_ * C_];
__device__ __align__(1024) __nv_bfloat16 g_WvThi[C_ * C_], g_WvTlo[C_ * C_];
__device__ float g_S[B_ * C_ * C_];
__device__ __align__(1024) float g_P[(size_t)B_ * 10 * NSPLIT * 16384];   // split-K partials (84MB)
__device__ float g_rp[(size_t)B_ * C_ * 64];    // per-block row partial sums
__device__ float g_r[B_ * C_], g_qr[B_ * C_], g_kr[B_ * C_], g_beta[B_ * C_];

// Upper-triangle tile pair table for symmetric GEMM (4x4 -> 10 pairs)
__device__ __constant__ int c_ti[10] = {0,0,0,0,1,1,1,2,2,3};
__device__ __constant__ int c_tj[10] = {0,1,2,3,1,2,3,2,3,3};

// ---------------------------------------------------------------------------
// Helpers
// ---------------------------------------------------------------------------
__device__ __forceinline__ uint32_t smem_u32(const void* p) {
    uint32_t a;
    asm("{ .reg .u64 t; cvta.to.shared.u64 t, %1; cvt.u32.u64 %0, t; }" : "=r"(a) : "l"(p));
    return a;
}
__device__ __forceinline__ uint32_t sw128(uint32_t off) { return off ^ ((off >> 3) & 0x70); }

__device__ __forceinline__ uint32_t cvt2(float lo, float hi) {
    uint32_t r; asm("cvt.rn.bf16x2.f32 %0, %1, %2;" : "=r"(r) : "f"(hi), "f"(lo)); return r;
}
__device__ __forceinline__ float lof(uint32_t h) { return __uint_as_float(h << 16); }
__device__ __forceinline__ float hif(uint32_t h) { return __uint_as_float(h & 0xFFFF0000u); }

#define CP_ASYNC16(dst, src) \
    asm volatile("cp.async.cg.shared.global [%0], [%1], 16;" :: "r"(dst), "l"(src))
#define CP_COMMIT() asm volatile("cp.async.commit_group;")
#define CP_WAIT0()  asm volatile("cp.async.wait_group 0;")
#define CP_WAIT1()  asm volatile("cp.async.wait_group 1;")

#define LDSM4(r0, r1, r2, r3, addr) \
    asm volatile("ldmatrix.sync.aligned.m8n8.x4.shared.b16 {%0,%1,%2,%3}, [%4];" \
                 : "=r"(r0), "=r"(r1), "=r"(r2), "=r"(r3) : "r"(addr))

#define MMA16816(c, a, b) \
    asm volatile("mma.sync.aligned.m16n8k16.row.col.f32.bf16.bf16.f32 " \
                 "{%0,%1,%2,%3},{%4,%5,%6,%7},{%8,%9},{%0,%1,%2,%3};" \
                 : "+f"((c)[0]), "+f"((c)[1]), "+f"((c)[2]), "+f"((c)[3]) \
                 : "r"((a)[0]), "r"((a)[1]), "r"((a)[2]), "r"((a)[3]), \
                   "r"((b)[0]), "r"((b)[1]))

#define GEMM_SMEM 196608    // 3 stages x (Ahi,Alo,Bhi,Blo) x 16KB
#define NT 512              // threads per GEMM CTA (16 warps)

// ---------------------------------------------------------------------------
// bf16 3-term GEMM mainloop (round-10 measured-best): 512 threads, CTA tile
// 128x128, warp tile 32x32, BK=64, 3-stage cp.async, prefetch-before-compute,
// A-lo reloads into A-hi fragment regs.
// ---------------------------------------------------------------------------
__device__ __forceinline__ void gemm_core(
    const __nv_bfloat16* __restrict__ Ah, const __nv_bfloat16* __restrict__ Al, int lda,
    const __nv_bfloat16* __restrict__ Bh, const __nv_bfloat16* __restrict__ Bl, int ldb,
    int K, uint32_t sb, int tid, int wid, int lane, float acc[2][4][4]) {

    #pragma unroll
    for (int mi = 0; mi < 2; ++mi)
        #pragma unroll
        for (int ni = 0; ni < 4; ++ni)
            #pragma unroll
            for (int e = 0; e < 4; ++e) acc[mi][ni][e] = 0.f;

    const int nit = K >> 6;

    auto load_stage = [&](int s, int k0) {
        const uint32_t S = sb + (uint32_t)s * 65536u;
        #pragma unroll
        for (int j = 0; j < 2; ++j) {
            const int id = tid + NT * j;
            const int row = id >> 3;
            const int c = id & 7;
            const uint32_t off = sw128((uint32_t)row * 128u + (uint32_t)c * 16u);
            const size_t ga = (size_t)row * lda + k0 + c * 8;
            const size_t gb = (size_t)row * ldb + k0 + c * 8;
            CP_ASYNC16(S + off,          Ah + ga);
            CP_ASYNC16(S + 16384 + off,  Al + ga);
            CP_ASYNC16(S + 32768 + off,  Bh + gb);
            CP_ASYNC16(S + 49152 + off,  Bl + gb);
        }
    };

    load_stage(0, 0);
    CP_COMMIT();
    if (nit > 1) { load_stage(1, 64); }
    CP_COMMIT();

    const int m0l = (wid & 3) * 32;
    const int n0l = (wid >> 2) * 32;

    int s = 0;
    for (int it = 0; it < nit; ++it) {
        if (it + 1 < nit) { CP_WAIT1(); } else { CP_WAIT0(); }
        __syncthreads();

        {
            int s2 = s + 2; if (s2 >= 3) s2 -= 3;
            if (it + 2 < nit) load_stage(s2, (it + 2) * 64);
            CP_COMMIT();
        }

        const uint32_t Sa = sb + (uint32_t)s * 65536u;
        const uint32_t Sb = Sa + 32768;

        #pragma unroll
        for (int ks = 0; ks < 4; ++ks) {
            const uint32_t kb = (uint32_t)ks * 32u;
            uint32_t af[2][4];
            uint32_t aaddr[2];
            #pragma unroll
            for (int mi = 0; mi < 2; ++mi) {
                aaddr[mi] = Sa + sw128(
                    (uint32_t)(m0l + mi * 16 + (lane & 15)) * 128u + kb + (uint32_t)(lane >> 4) * 16u);
                LDSM4(af[mi][0], af[mi][1], af[mi][2], af[mi][3], aaddr[mi]);
            }
            uint32_t bh4[4][2], bl4[4][2];
            #pragma unroll
            for (int np = 0; np < 2; ++np) {
                const uint32_t bd = Sb + sw128(
                    (uint32_t)(n0l + np * 16 + (lane >> 4) * 8 + (lane & 7)) * 128u +
                    kb + (uint32_t)((lane >> 3) & 1) * 16u);
                uint32_t r0, r1, r2, r3;
                LDSM4(r0, r1, r2, r3, bd);
                bh4[np * 2][0] = r0; bh4[np * 2][1] = r1;
                bh4[np * 2 + 1][0] = r2; bh4[np * 2 + 1][1] = r3;
                LDSM4(r0, r1, r2, r3, bd + 16384);
                bl4[np * 2][0] = r0; bl4[np * 2][1] = r1;
                bl4[np * 2 + 1][0] = r2; bl4[np * 2 + 1][1] = r3;
            }
            #pragma unroll
            for (int mi = 0; mi < 2; ++mi)
                #pragma unroll
                for (int ni = 0; ni < 4; ++ni) {
                    MMA16816(acc[mi][ni], af[mi], bh4[ni]);
                    MMA16816(acc[mi][ni], af[mi], bl4[ni]);
                }
            #pragma unroll
            for (int mi = 0; mi < 2; ++mi)
                LDSM4(af[mi][0], af[mi][1], af[mi][2], af[mi][3], aaddr[mi] + 16384);
            #pragma unroll
            for (int mi = 0; mi < 2; ++mi)
                #pragma unroll
                for (int ni = 0; ni < 4; ++ni)
                    MMA16816(acc[mi][ni], af[mi], bh4[ni]);
        }

        if (++s == 3) s = 0;
    }
}

// ---------------------------------------------------------------------------
// General bf16 HMMA GEMM. OM: 0 fp32 out, 1 bf16 hi/lo out, 2 fp32 + bias.
// ---------------------------------------------------------------------------
template <int OM>
__global__ void __launch_bounds__(NT, 1)
gemm_mma(const __nv_bfloat16* __restrict__ Ahi, const __nv_bfloat16* __restrict__ Alo,
         int lda, long long sA,
         const __nv_bfloat16* __restrict__ Bhi, const __nv_bfloat16* __restrict__ Blo,
         int ldb, long long sB,
         float* __restrict__ Cf, __nv_bfloat16* __restrict__ Chi,
         __nv_bfloat16* __restrict__ Clo, int ldc, long long sC,
         const float* __restrict__ bias, int K) {
    extern __shared__ char smem[];
    const uint32_t sb = smem_u32(smem);
    const int tid = threadIdx.x;
    const int wid = tid >> 5;
    const int lane = tid & 31;
    const int bz = blockIdx.z;
    const int bm = blockIdx.y * 128;
    const int bn = blockIdx.x * 128;

    float acc[2][4][4];
    gemm_core(Ahi + (size_t)bz * sA + (size_t)bm * lda,
              Alo + (size_t)bz * sA + (size_t)bm * lda, lda,
              Bhi + (size_t)bz * sB + (size_t)bn * ldb,
              Blo + (size_t)bz * sB + (size_t)bn * ldb, ldb,
              K, sb, tid, wid, lane, acc);

    float* Cfb = Cf ? (Cf + (size_t)bz * sC) : nullptr;
    __nv_bfloat16* Chb = Chi ? (Chi + (size_t)bz * sC) : nullptr;
    __nv_bfloat16* Clb = Clo ? (Clo + (size_t)bz * sC) : nullptr;

    const int m0l = (wid & 3) * 32;
    const int n0l = (wid >> 2) * 32;

    #pragma unroll
    for (int mi = 0; mi < 2; ++mi) {
        #pragma unroll
        for (int h = 0; h < 2; ++h) {
            const int row = bm + m0l + mi * 16 + (lane >> 2) + h * 8;
            float bb = 0.f;
            if (OM == 2) bb = bias[bz * C_ + row];
            #pragma unroll
            for (int ni = 0; ni < 4; ++ni) {
                const int col = bn + n0l + ni * 8 + (lane & 3) * 2;
                const float v0 = acc[mi][ni][h * 2 + 0];
                const float v1 = acc[mi][ni][h * 2 + 1];
                if (OM == 1) {
                    const uint32_t hh = cvt2(v0, v1);
                    const uint32_t ll = cvt2(v0 - lof(hh), v1 - hif(hh));
                    *(uint32_t*)(Chb + (size_t)row * ldc + col) = hh;
                    *(uint32_t*)(Clb + (size_t)row * ldc + col) = ll;
                } else {
                    float2 v; v.x = v0 + bb; v.y = v1 + bb;
                    *(float2*)(Cfb + (size_t)row * ldc + col) = v;
                }
            }
        }
    }
}

// ---------------------------------------------------------------------------
// Split-K symmetric GEMM stage 1. Grid (10, NSPLIT, B_). fp32 partial out.
// ---------------------------------------------------------------------------
__global__ void __launch_bounds__(NT, 1)
gemm_sym_k(const __nv_bfloat16* __restrict__ Xhi, const __nv_bfloat16* __restrict__ Xlo,
           float* __restrict__ P) {
    extern __shared__ char smem[];
    const uint32_t sb = smem_u32(smem);
    const int tid = threadIdx.x;
    const int wid = tid >> 5;
    const int lane = tid & 31;
    const int bz = blockIdx.z;
    const int split = blockIdx.y;
    const int ti = c_ti[blockIdx.x];
    const int tj = c_tj[blockIdx.x];
    const int bm = ti * 128;
    const int bn = tj * 128;
    const int k0 = split * (N_ / NSPLIT);

    const size_t xb = (size_t)bz * ((size_t)C_ * N_);
    float acc[2][4][4];
    gemm_core(Xhi + xb + (size_t)bm * N_ + k0, Xlo + xb + (size_t)bm * N_ + k0, N_,
              Xhi + xb + (size_t)bn * N_ + k0, Xlo + xb + (size_t)bn * N_ + k0, N_,
              N_ / NSPLIT, sb, tid, wid, lane, acc);

    float* Pt = P + (((size_t)bz * 10 + blockIdx.x) * NSPLIT + split) * 16384;
    const int m0l = (wid & 3) * 32;
    const int n0l = (wid >> 2) * 32;

    #pragma unroll
    for (int mi = 0; mi < 2; ++mi)
        #pragma unroll
        for (int h = 0; h < 2; ++h) {
            const int row = m0l + mi * 16 + (lane >> 2) + h * 8;
            #pragma unroll
            for (int ni = 0; ni < 4; ++ni) {
                const int col = n0l + ni * 8 + (lane & 3) * 2;
                float2 v;
                v.x = acc[mi][ni][h * 2 + 0];
                v.y = acc[mi][ni][h * 2 + 1];
                *(float2*)(Pt + row * 128 + col) = v;
            }
        }
}

// ---------------------------------------------------------------------------
// Split-K combine: G tile = sum of NSPLIT partials, bf16 hi/lo, direct +
// mirrored (transposed) store via padded smem. Grid (10 * B_), 256 threads.
// ---------------------------------------------------------------------------
#define COMB_SMEM (128 * 132 * 4)
__global__ void __launch_bounds__(256, 1)
combine_sym(const float* __restrict__ P,
            __nv_bfloat16* __restrict__ Ghi, __nv_bfloat16* __restrict__ Glo) {
    extern __shared__ char smem[];
    float* st = (float*)smem;
    const int tid = threadIdx.x;
    const int t = blockIdx.x % 10;
    const int bz = blockIdx.x / 10;
    const int ti = c_ti[t];
    const int tj = c_tj[t];
    const int bm = ti * 128;
    const int bn = tj * 128;

    const float* Pb = P + ((size_t)bz * 10 + t) * NSPLIT * 16384;

    #pragma unroll
    for (int j = 0; j < 16; ++j) {
        const int cid = tid + 256 * j;
        const int row = cid >> 5;
        const int c4 = cid & 31;
        float4 s = *(const float4*)(Pb + cid * 4);
        #pragma unroll
        for (int sp = 1; sp < NSPLIT; ++sp) {
            const float4 a = *(const float4*)(Pb + sp * 16384 + cid * 4);
            s.x += a.x; s.y += a.y; s.z += a.z; s.w += a.w;
        }
        float* d = st + row * 132 + c4 * 4;
        d[0] = s.x; d[1] = s.y; d[2] = s.z; d[3] = s.w;
    }
    __syncthreads();

    __nv_bfloat16* Gh = Ghi + (size_t)bz * (C_ * C_);
    __nv_bfloat16* Gl = Glo + (size_t)bz * (C_ * C_);

    #pragma unroll
    for (int j = 0; j < 16; ++j) {
        const int cid = tid + 256 * j;
        const int row = cid >> 5;
        const int c4 = cid & 31;
        const float4 v = *(const float4*)(st + row * 132 + c4 * 4);
        const uint32_t h0 = cvt2(v.x, v.y), h1 = cvt2(v.z, v.w);
        const uint32_t l0 = cvt2(v.x - lof(h0), v.y - hif(h0));
        const uint32_t l1 = cvt2(v.z - lof(h1), v.w - hif(h1));
        const size_t o = (size_t)(bm + row) * C_ + bn + c4 * 4;
        *(uint2*)(Gh + o) = make_uint2(h0, h1);
        *(uint2*)(Gl + o) = make_uint2(l0, l1);
    }

    if (ti != tj) {
        #pragma unroll
        for (int j = 0; j < 16; ++j) {
            const int cid = tid + 256 * j;
            const int mr = cid >> 5;
            const int mc4 = cid & 31;
            float v0 = st[(mc4 * 4 + 0) * 132 + mr];
            float v1 = st[(mc4 * 4 + 1) * 132 + mr];
            float v2 = st[(mc4 * 4 + 2) * 132 + mr];
            float v3 = st[(mc4 * 4 + 3) * 132 + mr];
            const uint32_t h0 = cvt2(v0, v1), h1 = cvt2(v2, v3);
            const uint32_t l0 = cvt2(v0 - lof(h0), v1 - hif(h0));
            const uint32_t l1 = cvt2(v2 - lof(h1), v3 - hif(h1));
            const size_t o = (size_t)(bn + mr) * C_ + bm + mc4 * 4;
            *(uint2*)(Gh + o) = make_uint2(h0, h1);
            *(uint2*)(Gl + o) = make_uint2(l0, l1);
        }
    }
}

// ---------------------------------------------------------------------------
// Fused X prep v2: 32c x 64n tiles, float2 loads, bf16x2 (uint32) stores for
// BOTH direct and transposed outputs; per-row partial sums to rp via warp
// reduce (warp w covers rows {w, w+8, w+16, w+24} fully -> deterministic).
// Grid (N/64, C/32, B), 256 threads.
// ---------------------------------------------------------------------------
__global__ void __launch_bounds__(256)
prep_x(const float* __restrict__ x,
       __nv_bfloat16* __restrict__ xhi, __nv_bfloat16* __restrict__ xlo,
       __nv_bfloat16* __restrict__ xthi, __nv_bfloat16* __restrict__ xtlo,
       float* __restrict__ rp) {
    __shared__ float t[32][65];
    const int tid = threadIdx.x;
    const int b = blockIdx.z;
    const int c0 = blockIdx.y * 32;
    const int n0 = blockIdx.x * 64;
    const float* s = x + (size_t)b * C_ * N_;
    __nv_bfloat16* xh = xhi + (size_t)b * C_ * N_;
    __nv_bfloat16* xl = xlo + (size_t)b * C_ * N_;
    __nv_bfloat16* th = xthi + (size_t)b * N_ * C_;
    __nv_bfloat16* tl = xtlo + (size_t)b * N_ * C_;

    const int r8 = tid >> 5;       // warp id 0..7
    const int cp = tid & 31;       // column pair index
    #pragma unroll
    for (int k = 0; k < 4; ++k) {
        const int cr = k * 8 + r8;
        const size_t o = (size_t)(c0 + cr) * N_ + n0 + cp * 2;
        const float2 v = *(const float2*)(s + o);
        t[cr][cp * 2]     = v.x;
        t[cr][cp * 2 + 1] = v.y;
        const uint32_t h = cvt2(v.x, v.y);
        const uint32_t l = cvt2(v.x - lof(h), v.y - hif(h));
        *(uint32_t*)(xh + o) = h;
        *(uint32_t*)(xl + o) = l;
        float ps = v.x + v.y;
        #pragma unroll
        for (int off = 16; off > 0; off >>= 1)
            ps += __shfl_down_sync(0xFFFFFFFFu, ps, off);
        if (cp == 0)
            rp[((size_t)b * C_ + c0 + cr) * 64 + blockIdx.x] = ps;
    }
    __syncthreads();

    const int nn0 = tid >> 4;      // 0..15
    const int ccp = tid & 15;      // c pair
    #pragma unroll
    for (int j = 0; j < 4; ++j) {
        const int nn = j * 16 + nn0;
        const float v0 = t[2 * ccp][nn];
        const float v1 = t[2 * ccp + 1][nn];
        const uint32_t h = cvt2(v0, v1);
        const uint32_t l = cvt2(v0 - lof(h), v1 - hif(h));
        const size_t o = (size_t)(n0 + nn) * C_ + c0 + 2 * ccp;
        *(uint32_t*)(th + o) = h;
        *(uint32_t*)(tl + o) = l;
    }
}

// ---------------------------------------------------------------------------
// Reduce row partials: r[row] = sum of rp[row][0..63]. One warp per row.
// ---------------------------------------------------------------------------
__global__ void __launch_bounds__(256)
reduce_r(const float* __restrict__ rp, float* __restrict__ r) {
    const int row = blockIdx.x * 8 + (threadIdx.x >> 5);
    const int lane = threadIdx.x & 31;
    float s = rp[(size_t)row * 64 + lane] + rp[(size_t)row * 64 + 32 + lane];
    #pragma unroll
    for (int off = 16; off > 0; off >>= 1)
        s += __shfl_down_sync(0xFFFFFFFFu, s, off);
    if (lane == 0) r[row] = s;
}

// ---------------------------------------------------------------------------
// Fused Wq + Wk split
// ---------------------------------------------------------------------------
__global__ void __launch_bounds__(256)
split_qk(const float* __restrict__ wq, const float* __restrict__ wk,
         __nv_bfloat16* __restrict__ qhi, __nv_bfloat16* __restrict__ qlo,
         __nv_bfloat16* __restrict__ khi, __nv_bfloat16* __restrict__ klo,
         long long n4) {
    long long i = (long long)blockIdx.x * blockDim.x + threadIdx.x;
    const long long stride = (long long)gridDim.x * blockDim.x;
    for (; i < n4; i += stride) {
        float4 v = ((const float4*)wq)[i];
        uint32_t h0 = cvt2(v.x, v.y), h1 = cvt2(v.z, v.w);
        uint32_t l0 = cvt2(v.x - lof(h0), v.y - hif(h0));
        uint32_t l1 = cvt2(v.z - lof(h1), v.w - hif(h1));
        ((uint2*)qhi)[i] = make_uint2(h0, h1);
        ((uint2*)qlo)[i] = make_uint2(l0, l1);
        v = ((const float4*)wk)[i];
        h0 = cvt2(v.x, v.y); h1 = cvt2(v.z, v.w);
        l0 = cvt2(v.x - lof(h0), v.y - hif(h0));
        l1 = cvt2(v.z - lof(h1), v.w - hif(h1));
        ((uint2*)khi)[i] = make_uint2(h0, h1);
        ((uint2*)klo)[i] = make_uint2(l0, l1);
    }
}

// ---------------------------------------------------------------------------
// qr = Wq r, kr = Wk r (all batches)
// ---------------------------------------------------------------------------
__global__ void __launch_bounds__(256) matvec_qk_kernel(const float* __restrict__ Wq,
                                                        const float* __restrict__ Wk,
                                                        const float* __restrict__ r,
                                                        float* __restrict__ qr,
                                                        float* __restrict__ kr) {
    const int b = blockIdx.y;
    const int warp = threadIdx.x >> 5;
    const int lane = threadIdx.x & 31;
    const int o = blockIdx.x * 8 + warp;
    const float* rb = r + b * C_;
    float sq = 0.f, sk = 0.f;
    for (int i = lane; i < C_; i += 32) {
        float rv = rb[i];
        sq += Wq[(size_t)o * C_ + i] * rv;
        sk += Wk[(size_t)o * C_ + i] * rv;
    }
    #pragma unroll
    for (int off = 16; off > 0; off >>= 1) {
        sq += __shfl_down_sync(0xFFFFFFFFu, sq, off);
        sk += __shfl_down_sync(0xFFFFFFFFu, sk, off);
    }
    if (lane == 0) { qr[b * C_ + o] = sq; kr[b * C_ + o] = sk; }
}

// ---------------------------------------------------------------------------
// Transpose + bf16 split (for Wv)
// ---------------------------------------------------------------------------
__global__ void __launch_bounds__(256)
transpose_cvt(const float* __restrict__ s, __nv_bfloat16* __restrict__ dhi,
              __nv_bfloat16* __restrict__ dlo, int R, int Cc) {
    __shared__ float t[32][33];
    const int tx = threadIdx.x & 31, ty = threadIdx.x >> 5;
    const int r0 = blockIdx.y * 32, c0 = blockIdx.x * 32;
    #pragma unroll
    for (int k = 0; k < 4; ++k)
        t[ty + 8 * k][tx] = s[(size_t)(r0 + ty + 8 * k) * Cc + c0 + tx];
    __syncthreads();
    #pragma unroll
    for (int k = 0; k < 4; ++k) {
        const int i = ty + 8 * k;
        const float v = t[tx][i];
        __nv_bfloat16 h = __float2bfloat16(v);
        __nv_bfloat16 l = __float2bfloat16(v - __bfloat162float(h));
        const size_t o = (size_t)(c0 + i) * R + r0 + tx;
        dhi[o] = h; dlo[o] = l;
    }
}

// ---------------------------------------------------------------------------
// Softmax with rank-1 bias corrections; attn -> bf16 hi/lo planes + beta
// ---------------------------------------------------------------------------
__global__ void __launch_bounds__(256)
softmax_beta_kernel(const float* __restrict__ S,
                    const float* __restrict__ qr, const float* __restrict__ kr,
                    const float* __restrict__ bq, const float* __restrict__ bk,
                    const float* __restrict__ bv,
                    __nv_bfloat16* __restrict__ Ahi, __nv_bfloat16* __restrict__ Alo,
                    float* __restrict__ beta) {
    __shared__ float sm[256];
    const int row = blockIdx.x;
    const int b = row >> 9;
    const int c = row & (C_ - 1);
    const float* Sr = S + (size_t)row * C_;
    const float* krb = kr + b * C_;
    const float qrc = qr[row];
    const float bqc = bq[c];
    const float scale = rsqrtf((float)C_);
    const int t = threadIdx.x;

    float v[2];
    float mx = -1e30f;
    #pragma unroll
    for (int u = 0; u < 2; ++u) {
        const int d = t + u * 256;
        float s = (Sr[d] + qrc * bk[d] + bqc * krb[d] + (float)N_ * bqc * bk[d]) * scale;
        v[u] = s;
        mx = fmaxf(mx, s);
    }
    sm[t] = mx; __syncthreads();
    #pragma unroll
    for (int off = 128; off > 0; off >>= 1) {
        if (t < off) sm[t] = fmaxf(sm[t], sm[t + off]);
        __syncthreads();
    }
    mx = sm[0];
    __syncthreads();

    float sum = 0.f;
    #pragma unroll
    for (int u = 0; u < 2; ++u) { v[u] = expf(v[u] - mx); sum += v[u]; }
    sm[t] = sum; __syncthreads();
    #pragma unroll
    for (int off = 128; off > 0; off >>= 1) {
        if (t < off) sm[t] += sm[t + off];
        __syncthreads();
    }
    const float inv = 1.f / sm[0];
    __syncthreads();

    float bc = 0.f;
    #pragma unroll
    for (int u = 0; u < 2; ++u) {
        const int d = t + u * 256;
        const float p = v[u] * inv;
        __nv_bfloat16 h = __float2bfloat16(p);
        __nv_bfloat16 l = __float2bfloat16(p - __bfloat162float(h));
        Ahi[(size_t)row * C_ + d] = h;
        Alo[(size_t)row * C_ + d] = l;
        bc += p * bv[d];
    }
    sm[t] = bc; __syncthreads();
    #pragma unroll
    for (int off = 128; off > 0; off >>= 1) {
        if (t < off) sm[t] += sm[t + off];
        __syncthreads();
    }
    if (t == 0) beta[row] = sm[0];
}

// ---------------------------------------------------------------------------
extern "C" void kernel_launch(void* const* d_in, const int* in_sizes, int n_in,
                              void* d_out, int out_size) {
    const float* x  = (const float*)d_in[0];
    const float* Wq = (const float*)d_in[1];
    const float* bq = (const float*)d_in[2];
    const float* Wk = (const float*)d_in[3];
    const float* bk = (const float*)d_in[4];
    const float* Wv = (const float*)d_in[5];
    const float* bv = (const float*)d_in[6];
    float* out = (float*)d_out;

    __nv_bfloat16 *Xhi, *Xlo, *XThi, *XTlo, *Ghi, *Glo, *T1hi, *T1lo;
    __nv_bfloat16 *AThi, *ATlo, *Mvhi, *Mvlo, *Wqhi, *Wqlo, *Wkhi, *Wklo, *WvThi, *WvTlo;
    float *S, *P, *rp, *r, *qr, *kr, *beta;
    cudaGetSymbolAddress((void**)&Xhi, g_Xhi);     cudaGetSymbolAddress((void**)&Xlo, g_Xlo);
    cudaGetSymbolAddress((void**)&XThi, g_XThi);   cudaGetSymbolAddress((void**)&XTlo, g_XTlo);
    cudaGetSymbolAddress((void**)&Ghi, g_Ghi);     cudaGetSymbolAddress((void**)&Glo, g_Glo);
    cudaGetSymbolAddress((void**)&T1hi, g_T1hi);   cudaGetSymbolAddress((void**)&T1lo, g_T1lo);
    cudaGetSymbolAddress((void**)&AThi, g_AThi);   cudaGetSymbolAddress((void**)&ATlo, g_ATlo);
    cudaGetSymbolAddress((void**)&Mvhi, g_Mvhi);   cudaGetSymbolAddress((void**)&Mvlo, g_Mvlo);
    cudaGetSymbolAddress((void**)&Wqhi, g_Wqhi);   cudaGetSymbolAddress((void**)&Wqlo, g_Wqlo);
    cudaGetSymbolAddress((void**)&Wkhi, g_Wkhi);   cudaGetSymbolAddress((void**)&Wklo, g_Wklo);
    cudaGetSymbolAddress((void**)&WvThi, g_WvThi); cudaGetSymbolAddress((void**)&WvTlo, g_WvTlo);
    cudaGetSymbolAddress((void**)&S, g_S);         cudaGetSymbolAddress((void**)&P, g_P);
    cudaGetSymbolAddress((void**)&rp, g_rp);       cudaGetSymbolAddress((void**)&r, g_r);
    cudaGetSymbolAddress((void**)&qr, g_qr);
    cudaGetSymbolAddress((void**)&kr, g_kr); cudaGetSymbolAddress((void**)&beta, g_beta);

    const long long CN = (long long)C_ * N_;
    const long long CC = (long long)C_ * C_;
    const long long NC = (long long)N_ * C_;

    cudaFuncSetAttribute(gemm_mma<0>, cudaFuncAttributeMaxDynamicSharedMemorySize, GEMM_SMEM);
    cudaFuncSetAttribute(gemm_mma<1>, cudaFuncAttributeMaxDynamicSharedMemorySize, GEMM_SMEM);
    cudaFuncSetAttribute(gemm_mma<2>, cudaFuncAttributeMaxDynamicSharedMemorySize, GEMM_SMEM);
    cudaFuncSetAttribute(gemm_sym_k,  cudaFuncAttributeMaxDynamicSharedMemorySize, GEMM_SMEM);
    cudaFuncSetAttribute(combine_sym, cudaFuncAttributeMaxDynamicSharedMemorySize, COMB_SMEM);

    // Launch order keeps gemm_sym_k at index 3 (the slot ncu captures).
    prep_x<<<dim3(N_ / 64, C_ / 32, B_), 256>>>(x, Xhi, Xlo, XThi, XTlo, rp);        // 0
    reduce_r<<<B_ * C_ / 8, 256>>>(rp, r);                                           // 1
    split_qk<<<256, 256>>>(Wq, Wk, Wqhi, Wqlo, Wkhi, Wklo, CC / 4);                  // 2

    // G = X X^T, symmetric upper-triangle, split-K=NSPLIT -> fp32 partials
    gemm_sym_k<<<dim3(10, NSPLIT, B_), NT, GEMM_SMEM>>>(Xhi, Xlo, P);                // 3

    combine_sym<<<10 * B_, 256, COMB_SMEM>>>(P, Ghi, Glo);                           // 4
    transpose_cvt<<<dim3(C_ / 32, C_ / 32), 256>>>(Wv, WvThi, WvTlo, C_, C_);        // 5
    matvec_qk_kernel<<<dim3(C_ / 8, B_), 256>>>(Wq, Wk, r, qr, kr);                  // 6

    // T1 = Wq G
    gemm_mma<1><<<dim3(4, 4, B_), NT, GEMM_SMEM>>>(
        Wqhi, Wqlo, C_, 0,  Ghi, Glo, C_, CC,
        nullptr, T1hi, T1lo, C_, CC, nullptr, C_);

    // S = T1 Wk^T (fp32 out)
    gemm_mma<0><<<dim3(4, 4, B_), NT, GEMM_SMEM>>>(
        T1hi, T1lo, C_, CC,  Wkhi, Wklo, C_, 0,
        S, nullptr, nullptr, C_, CC, nullptr, C_);

    // softmax(+rank-1 corrections) -> attn hl, beta = attn bv
    softmax_beta_kernel<<<B_ * C_, 256>>>(S, qr, kr, bq, bk, bv, AThi, ATlo, beta);

    // Mv = attn Wv (B = WvT rows)
    gemm_mma<1><<<dim3(4, 4, B_), NT, GEMM_SMEM>>>(
        AThi, ATlo, C_, CC,  WvThi, WvTlo, C_, 0,
        nullptr, Mvhi, Mvlo, C_, CC, nullptr, C_);

    // out = Mv X + beta (B = XT rows)
    gemm_mma<2><<<dim3(32, 4, B_), NT, GEMM_SMEM>>>(
        Mvhi, Mvlo, C_, CC,  XThi, XTlo, C_, NC,
        out, nullptr, nullptr, N_, CN, beta, C_);
}

// round 14
// speedup vs baseline: 1.2104x; 1.1206x over previous
#include <cuda_runtime.h>
#include <cuda_bf16.h>
#include <cuda_fp16.h>
#include <math.h>
#include <stdint.h>

#define B_ 16
#define C_ 512
#define N_ 4096
#define NSPLIT 8

// ---------------------------------------------------------------------------
// Scratch (device globals; allocation in kernel_launch is forbidden)
// ---------------------------------------------------------------------------
__device__ __align__(1024) __nv_bfloat16 g_Xhi [(size_t)B_ * C_ * N_];
__device__ __align__(1024) __nv_bfloat16 g_Xlo [(size_t)B_ * C_ * N_];
__device__ __align__(1024) __half        g_XTh [(size_t)B_ * N_ * C_];   // fp16 hi plane only
__device__ __align__(1024) __nv_bfloat16 g_Ghi [B_ * C_ * C_], g_Glo [B_ * C_ * C_];
__device__ __align__(1024) __nv_bfloat16 g_T1hi[B_ * C_ * C_], g_T1lo[B_ * C_ * C_];
__device__ __align__(1024) __nv_bfloat16 g_AThi[B_ * C_ * C_], g_ATlo[B_ * C_ * C_];
__device__ __align__(1024) __half        g_Mvh [B_ * C_ * C_], g_Mvl [B_ * C_ * C_];
__device__ __align__(1024) __nv_bfloat16 g_Wqhi[C_ * C_], g_Wqlo[C_ * C_];
__device__ __align__(1024) __nv_bfloat16 g_Wkhi[C_ * C_], g_Wklo[C_ * C_];
__device__ __align__(1024) __nv_bfloat16 g_WvThi[C_ * C_], g_WvTlo[C_ * C_];
__device__ float g_S[B_ * C_ * C_];
__device__ __align__(1024) float g_P[(size_t)B_ * 10 * NSPLIT * 16384];   // split-K partials (84MB)
__device__ float g_rp[(size_t)B_ * C_ * 64];    // per-block row partial sums
__device__ float g_r[B_ * C_], g_qr[B_ * C_], g_kr[B_ * C_], g_beta[B_ * C_];

// Upper-triangle tile pair table for symmetric GEMM (4x4 -> 10 pairs)
__device__ __constant__ int c_ti[10] = {0,0,0,0,1,1,1,2,2,3};
__device__ __constant__ int c_tj[10] = {0,1,2,3,1,2,3,2,3,3};

// ---------------------------------------------------------------------------
// Helpers
// ---------------------------------------------------------------------------
__device__ __forceinline__ uint32_t smem_u32(const void* p) {
    uint32_t a;
    asm("{ .reg .u64 t; cvta.to.shared.u64 t, %1; cvt.u32.u64 %0, t; }" : "=r"(a) : "l"(p));
    return a;
}
__device__ __forceinline__ uint32_t sw128(uint32_t off) { return off ^ ((off >> 3) & 0x70); }

__device__ __forceinline__ uint32_t cvt2(float lo, float hi) {
    uint32_t r; asm("cvt.rn.bf16x2.f32 %0, %1, %2;" : "=r"(r) : "f"(hi), "f"(lo)); return r;
}
__device__ __forceinline__ float lof(uint32_t h) { return __uint_as_float(h << 16); }
__device__ __forceinline__ float hif(uint32_t h) { return __uint_as_float(h & 0xFFFF0000u); }

#define CP_ASYNC16(dst, src) \
    asm volatile("cp.async.cg.shared.global [%0], [%1], 16;" :: "r"(dst), "l"(src))
#define CP_COMMIT() asm volatile("cp.async.commit_group;")
#define CP_WAIT0()  asm volatile("cp.async.wait_group 0;")
#define CP_WAIT1()  asm volatile("cp.async.wait_group 1;")

#define LDSM4(r0, r1, r2, r3, addr) \
    asm volatile("ldmatrix.sync.aligned.m8n8.x4.shared.b16 {%0,%1,%2,%3}, [%4];" \
                 : "=r"(r0), "=r"(r1), "=r"(r2), "=r"(r3) : "r"(addr))

#define MMA16816(c, a, b) \
    asm volatile("mma.sync.aligned.m16n8k16.row.col.f32.bf16.bf16.f32 " \
                 "{%0,%1,%2,%3},{%4,%5,%6,%7},{%8,%9},{%0,%1,%2,%3};" \
                 : "+f"((c)[0]), "+f"((c)[1]), "+f"((c)[2]), "+f"((c)[3]) \
                 : "r"((a)[0]), "r"((a)[1]), "r"((a)[2]), "r"((a)[3]), \
                   "r"((b)[0]), "r"((b)[1]))

#define MMA16816H(c, a, b) \
    asm volatile("mma.sync.aligned.m16n8k16.row.col.f32.f16.f16.f32 " \
                 "{%0,%1,%2,%3},{%4,%5,%6,%7},{%8,%9},{%0,%1,%2,%3};" \
                 : "+f"((c)[0]), "+f"((c)[1]), "+f"((c)[2]), "+f"((c)[3]) \
                 : "r"((a)[0]), "r"((a)[1]), "r"((a)[2]), "r"((a)[3]), \
                   "r"((b)[0]), "r"((b)[1]))

#define GEMM_SMEM 196608    // bf16 3-term core: 3 stages x 64KB
#define OUT_SMEM  147456    // fp16 2-term core: 3 stages x 48KB
#define NT 512              // threads per GEMM CTA (16 warps)

// ---------------------------------------------------------------------------
// bf16 3-term GEMM mainloop (measured-best): CTA 128x128, warp 32x32, BK=64,
// 3-stage cp.async, prefetch-before-compute, A-lo reloads into A-hi regs.
// ---------------------------------------------------------------------------
__device__ __forceinline__ void gemm_core(
    const __nv_bfloat16* __restrict__ Ah, const __nv_bfloat16* __restrict__ Al, int lda,
    const __nv_bfloat16* __restrict__ Bh, const __nv_bfloat16* __restrict__ Bl, int ldb,
    int K, uint32_t sb, int tid, int wid, int lane, float acc[2][4][4]) {

    #pragma unroll
    for (int mi = 0; mi < 2; ++mi)
        #pragma unroll
        for (int ni = 0; ni < 4; ++ni)
            #pragma unroll
            for (int e = 0; e < 4; ++e) acc[mi][ni][e] = 0.f;

    const int nit = K >> 6;

    auto load_stage = [&](int s, int k0) {
        const uint32_t S = sb + (uint32_t)s * 65536u;
        #pragma unroll
        for (int j = 0; j < 2; ++j) {
            const int id = tid + NT * j;
            const int row = id >> 3;
            const int c = id & 7;
            const uint32_t off = sw128((uint32_t)row * 128u + (uint32_t)c * 16u);
            const size_t ga = (size_t)row * lda + k0 + c * 8;
            const size_t gb = (size_t)row * ldb + k0 + c * 8;
            CP_ASYNC16(S + off,          Ah + ga);
            CP_ASYNC16(S + 16384 + off,  Al + ga);
            CP_ASYNC16(S + 32768 + off,  Bh + gb);
            CP_ASYNC16(S + 49152 + off,  Bl + gb);
        }
    };

    load_stage(0, 0);
    CP_COMMIT();
    if (nit > 1) { load_stage(1, 64); }
    CP_COMMIT();

    const int m0l = (wid & 3) * 32;
    const int n0l = (wid >> 2) * 32;

    int s = 0;
    for (int it = 0; it < nit; ++it) {
        if (it + 1 < nit) { CP_WAIT1(); } else { CP_WAIT0(); }
        __syncthreads();

        {
            int s2 = s + 2; if (s2 >= 3) s2 -= 3;
            if (it + 2 < nit) load_stage(s2, (it + 2) * 64);
            CP_COMMIT();
        }

        const uint32_t Sa = sb + (uint32_t)s * 65536u;
        const uint32_t Sb = Sa + 32768;

        #pragma unroll
        for (int ks = 0; ks < 4; ++ks) {
            const uint32_t kb = (uint32_t)ks * 32u;
            uint32_t af[2][4];
            uint32_t aaddr[2];
            #pragma unroll
            for (int mi = 0; mi < 2; ++mi) {
                aaddr[mi] = Sa + sw128(
                    (uint32_t)(m0l + mi * 16 + (lane & 15)) * 128u + kb + (uint32_t)(lane >> 4) * 16u);
                LDSM4(af[mi][0], af[mi][1], af[mi][2], af[mi][3], aaddr[mi]);
            }
            uint32_t bh4[4][2], bl4[4][2];
            #pragma unroll
            for (int np = 0; np < 2; ++np) {
                const uint32_t bd = Sb + sw128(
                    (uint32_t)(n0l + np * 16 + (lane >> 4) * 8 + (lane & 7)) * 128u +
                    kb + (uint32_t)((lane >> 3) & 1) * 16u);
                uint32_t r0, r1, r2, r3;
                LDSM4(r0, r1, r2, r3, bd);
                bh4[np * 2][0] = r0; bh4[np * 2][1] = r1;
                bh4[np * 2 + 1][0] = r2; bh4[np * 2 + 1][1] = r3;
                LDSM4(r0, r1, r2, r3, bd + 16384);
                bl4[np * 2][0] = r0; bl4[np * 2][1] = r1;
                bl4[np * 2 + 1][0] = r2; bl4[np * 2 + 1][1] = r3;
            }
            #pragma unroll
            for (int mi = 0; mi < 2; ++mi)
                #pragma unroll
                for (int ni = 0; ni < 4; ++ni) {
                    MMA16816(acc[mi][ni], af[mi], bh4[ni]);
                    MMA16816(acc[mi][ni], af[mi], bl4[ni]);
                }
            #pragma unroll
            for (int mi = 0; mi < 2; ++mi)
                LDSM4(af[mi][0], af[mi][1], af[mi][2], af[mi][3], aaddr[mi] + 16384);
            #pragma unroll
            for (int mi = 0; mi < 2; ++mi)
                #pragma unroll
                for (int ni = 0; ni < 4; ++ni)
                    MMA16816(acc[mi][ni], af[mi], bh4[ni]);
        }

        if (++s == 3) s = 0;
    }
}

// ---------------------------------------------------------------------------
// General bf16 HMMA GEMM.
// OM: 0 fp32 out, 1 bf16 hi/lo out, 2 fp32 + bias, 3 fp16 hi/lo out.
// ---------------------------------------------------------------------------
template <int OM>
__global__ void __launch_bounds__(NT, 1)
gemm_mma(const __nv_bfloat16* __restrict__ Ahi, const __nv_bfloat16* __restrict__ Alo,
         int lda, long long sA,
         const __nv_bfloat16* __restrict__ Bhi, const __nv_bfloat16* __restrict__ Blo,
         int ldb, long long sB,
         float* __restrict__ Cf, __nv_bfloat16* __restrict__ Chi,
         __nv_bfloat16* __restrict__ Clo, int ldc, long long sC,
         const float* __restrict__ bias, int K) {
    extern __shared__ char smem[];
    const uint32_t sb = smem_u32(smem);
    const int tid = threadIdx.x;
    const int wid = tid >> 5;
    const int lane = tid & 31;
    const int bz = blockIdx.z;
    const int bm = blockIdx.y * 128;
    const int bn = blockIdx.x * 128;

    float acc[2][4][4];
    gemm_core(Ahi + (size_t)bz * sA + (size_t)bm * lda,
              Alo + (size_t)bz * sA + (size_t)bm * lda, lda,
              Bhi + (size_t)bz * sB + (size_t)bn * ldb,
              Blo + (size_t)bz * sB + (size_t)bn * ldb, ldb,
              K, sb, tid, wid, lane, acc);

    float* Cfb = Cf ? (Cf + (size_t)bz * sC) : nullptr;
    __nv_bfloat16* Chb = Chi ? (Chi + (size_t)bz * sC) : nullptr;
    __nv_bfloat16* Clb = Clo ? (Clo + (size_t)bz * sC) : nullptr;

    const int m0l = (wid & 3) * 32;
    const int n0l = (wid >> 2) * 32;

    #pragma unroll
    for (int mi = 0; mi < 2; ++mi) {
        #pragma unroll
        for (int h = 0; h < 2; ++h) {
            const int row = bm + m0l + mi * 16 + (lane >> 2) + h * 8;
            float bb = 0.f;
            if (OM == 2) bb = bias[bz * C_ + row];
            #pragma unroll
            for (int ni = 0; ni < 4; ++ni) {
                const int col = bn + n0l + ni * 8 + (lane & 3) * 2;
                const float v0 = acc[mi][ni][h * 2 + 0];
                const float v1 = acc[mi][ni][h * 2 + 1];
                if (OM == 1) {
                    const uint32_t hh = cvt2(v0, v1);
                    const uint32_t ll = cvt2(v0 - lof(hh), v1 - hif(hh));
                    *(uint32_t*)(Chb + (size_t)row * ldc + col) = hh;
                    *(uint32_t*)(Clb + (size_t)row * ldc + col) = ll;
                } else if (OM == 3) {
                    const __half2 h2 = __floats2half2_rn(v0, v1);
                    const float2 hf = __half22float2(h2);
                    const __half2 l2 = __floats2half2_rn(v0 - hf.x, v1 - hf.y);
                    *(uint32_t*)(Chb + (size_t)row * ldc + col) = *(const uint32_t*)&h2;
                    *(uint32_t*)(Clb + (size_t)row * ldc + col) = *(const uint32_t*)&l2;
                } else {
                    float2 v; v.x = v0 + bb; v.y = v1 + bb;
                    *(float2*)(Cfb + (size_t)row * ldc + col) = v;
                }
            }
        }
    }
}

// ---------------------------------------------------------------------------
// fp16 2-term out-GEMM: D = (A_hi + A_lo) * B_hi^T + bias. CTA 128x128,
// warp 32x32, BK=64, 3-stage (48KB/stage), prefetch-before-compute.
// A = Mv fp16 hi/lo planes, B = XT fp16 hi plane. fp32 out + per-row bias.
// ---------------------------------------------------------------------------
__global__ void __launch_bounds__(NT, 1)
gemm_out(const __half* __restrict__ Ahi, const __half* __restrict__ Alo,
         const __half* __restrict__ Bh,
         float* __restrict__ Cf, const float* __restrict__ bias) {
    extern __shared__ char smem[];
    const uint32_t sb = smem_u32(smem);
    const int tid = threadIdx.x;
    const int wid = tid >> 5;
    const int lane = tid & 31;
    const int bz = blockIdx.z;
    const int bm = blockIdx.y * 128;
    const int bn = blockIdx.x * 128;

    const __half* Ah = Ahi + (size_t)bz * (C_ * C_) + (size_t)bm * C_;
    const __half* Al = Alo + (size_t)bz * (C_ * C_) + (size_t)bm * C_;
    const __half* Bp = Bh + (size_t)bz * ((size_t)N_ * C_) + (size_t)bn * C_;

    float acc[2][4][4];
    #pragma unroll
    for (int mi = 0; mi < 2; ++mi)
        #pragma unroll
        for (int ni = 0; ni < 4; ++ni)
            #pragma unroll
            for (int e = 0; e < 4; ++e) acc[mi][ni][e] = 0.f;

    const int nit = C_ >> 6;   // 8

    auto load_stage = [&](int s, int k0) {
        const uint32_t S = sb + (uint32_t)s * 49152u;
        #pragma unroll
        for (int j = 0; j < 2; ++j) {
            const int id = tid + NT * j;
            const int row = id >> 3;
            const int c = id & 7;
            const uint32_t off = sw128((uint32_t)row * 128u + (uint32_t)c * 16u);
            const size_t ga = (size_t)row * C_ + k0 + c * 8;
            CP_ASYNC16(S + off,          Ah + ga);
            CP_ASYNC16(S + 16384 + off,  Al + ga);
            CP_ASYNC16(S + 32768 + off,  Bp + ga);
        }
    };

    load_stage(0, 0);
    CP_COMMIT();
    load_stage(1, 64);
    CP_COMMIT();

    const int m0l = (wid & 3) * 32;
    const int n0l = (wid >> 2) * 32;

    int s = 0;
    for (int it = 0; it < nit; ++it) {
        if (it + 1 < nit) { CP_WAIT1(); } else { CP_WAIT0(); }
        __syncthreads();

        {
            int s2 = s + 2; if (s2 >= 3) s2 -= 3;
            if (it + 2 < nit) load_stage(s2, (it + 2) * 64);
            CP_COMMIT();
        }

        const uint32_t Sa = sb + (uint32_t)s * 49152u;
        const uint32_t Sb = Sa + 32768u;

        #pragma unroll
        for (int ks = 0; ks < 4; ++ks) {
            const uint32_t kb = (uint32_t)ks * 32u;
            uint32_t ah[2][4], al[2][4];
            #pragma unroll
            for (int mi = 0; mi < 2; ++mi) {
                const uint32_t ad = Sa + sw128(
                    (uint32_t)(m0l + mi * 16 + (lane & 15)) * 128u + kb + (uint32_t)(lane >> 4) * 16u);
                LDSM4(ah[mi][0], ah[mi][1], ah[mi][2], ah[mi][3], ad);
                LDSM4(al[mi][0], al[mi][1], al[mi][2], al[mi][3], ad + 16384);
            }
            uint32_t bh4[4][2];
            #pragma unroll
            for (int np = 0; np < 2; ++np) {
                const uint32_t bd = Sb + sw128(
                    (uint32_t)(n0l + np * 16 + (lane >> 4) * 8 + (lane & 7)) * 128u +
                    kb + (uint32_t)((lane >> 3) & 1) * 16u);
                uint32_t r0, r1, r2, r3;
                LDSM4(r0, r1, r2, r3, bd);
                bh4[np * 2][0] = r0; bh4[np * 2][1] = r1;
                bh4[np * 2 + 1][0] = r2; bh4[np * 2 + 1][1] = r3;
            }
            #pragma unroll
            for (int mi = 0; mi < 2; ++mi)
                #pragma unroll
                for (int ni = 0; ni < 4; ++ni) {
                    MMA16816H(acc[mi][ni], ah[mi], bh4[ni]);
                    MMA16816H(acc[mi][ni], al[mi], bh4[ni]);
                }
        }

        if (++s == 3) s = 0;
    }

    float* Cfb = Cf + (size_t)bz * ((size_t)C_ * N_);
    #pragma unroll
    for (int mi = 0; mi < 2; ++mi) {
        #pragma unroll
        for (int h = 0; h < 2; ++h) {
            const int row = bm + m0l + mi * 16 + (lane >> 2) + h * 8;
            const float bb = bias[bz * C_ + row];
            #pragma unroll
            for (int ni = 0; ni < 4; ++ni) {
                const int col = bn + n0l + ni * 8 + (lane & 3) * 2;
                float2 v;
                v.x = acc[mi][ni][h * 2 + 0] + bb;
                v.y = acc[mi][ni][h * 2 + 1] + bb;
                *(float2*)(Cfb + (size_t)row * N_ + col) = v;
            }
        }
    }
}

// ---------------------------------------------------------------------------
// Split-K symmetric GEMM stage 1. Grid (10, NSPLIT, B_). fp32 partial out.
// ---------------------------------------------------------------------------
__global__ void __launch_bounds__(NT, 1)
gemm_sym_k(const __nv_bfloat16* __restrict__ Xhi, const __nv_bfloat16* __restrict__ Xlo,
           float* __restrict__ P) {
    extern __shared__ char smem[];
    const uint32_t sb = smem_u32(smem);
    const int tid = threadIdx.x;
    const int wid = tid >> 5;
    const int lane = tid & 31;
    const int bz = blockIdx.z;
    const int split = blockIdx.y;
    const int ti = c_ti[blockIdx.x];
    const int tj = c_tj[blockIdx.x];
    const int bm = ti * 128;
    const int bn = tj * 128;
    const int k0 = split * (N_ / NSPLIT);

    const size_t xb = (size_t)bz * ((size_t)C_ * N_);
    float acc[2][4][4];
    gemm_core(Xhi + xb + (size_t)bm * N_ + k0, Xlo + xb + (size_t)bm * N_ + k0, N_,
              Xhi + xb + (size_t)bn * N_ + k0, Xlo + xb + (size_t)bn * N_ + k0, N_,
              N_ / NSPLIT, sb, tid, wid, lane, acc);

    float* Pt = P + (((size_t)bz * 10 + blockIdx.x) * NSPLIT + split) * 16384;
    const int m0l = (wid & 3) * 32;
    const int n0l = (wid >> 2) * 32;

    #pragma unroll
    for (int mi = 0; mi < 2; ++mi)
        #pragma unroll
        for (int h = 0; h < 2; ++h) {
            const int row = m0l + mi * 16 + (lane >> 2) + h * 8;
            #pragma unroll
            for (int ni = 0; ni < 4; ++ni) {
                const int col = n0l + ni * 8 + (lane & 3) * 2;
                float2 v;
                v.x = acc[mi][ni][h * 2 + 0];
                v.y = acc[mi][ni][h * 2 + 1];
                *(float2*)(Pt + row * 128 + col) = v;
            }
        }
}

// ---------------------------------------------------------------------------
// Split-K combine: G tile = sum of NSPLIT partials, bf16 hi/lo, direct +
// mirrored (transposed) store via padded smem. Grid (10 * B_), 256 threads.
// ---------------------------------------------------------------------------
#define COMB_SMEM (128 * 132 * 4)
__global__ void __launch_bounds__(256, 1)
combine_sym(const float* __restrict__ P,
            __nv_bfloat16* __restrict__ Ghi, __nv_bfloat16* __restrict__ Glo) {
    extern __shared__ char smem[];
    float* st = (float*)smem;
    const int tid = threadIdx.x;
    const int t = blockIdx.x % 10;
    const int bz = blockIdx.x / 10;
    const int ti = c_ti[t];
    const int tj = c_tj[t];
    const int bm = ti * 128;
    const int bn = tj * 128;

    const float* Pb = P + ((size_t)bz * 10 + t) * NSPLIT * 16384;

    #pragma unroll
    for (int j = 0; j < 16; ++j) {
        const int cid = tid + 256 * j;
        const int row = cid >> 5;
        const int c4 = cid & 31;
        float4 s = *(const float4*)(Pb + cid * 4);
        #pragma unroll
        for (int sp = 1; sp < NSPLIT; ++sp) {
            const float4 a = *(const float4*)(Pb + sp * 16384 + cid * 4);
            s.x += a.x; s.y += a.y; s.z += a.z; s.w += a.w;
        }
        float* d = st + row * 132 + c4 * 4;
        d[0] = s.x; d[1] = s.y; d[2] = s.z; d[3] = s.w;
    }
    __syncthreads();

    __nv_bfloat16* Gh = Ghi + (size_t)bz * (C_ * C_);
    __nv_bfloat16* Gl = Glo + (size_t)bz * (C_ * C_);

    #pragma unroll
    for (int j = 0; j < 16; ++j) {
        const int cid = tid + 256 * j;
        const int row = cid >> 5;
        const int c4 = cid & 31;
        const float4 v = *(const float4*)(st + row * 132 + c4 * 4);
        const uint32_t h0 = cvt2(v.x, v.y), h1 = cvt2(v.z, v.w);
        const uint32_t l0 = cvt2(v.x - lof(h0), v.y - hif(h0));
        const uint32_t l1 = cvt2(v.z - lof(h1), v.w - hif(h1));
        const size_t o = (size_t)(bm + row) * C_ + bn + c4 * 4;
        *(uint2*)(Gh + o) = make_uint2(h0, h1);
        *(uint2*)(Gl + o) = make_uint2(l0, l1);
    }

    if (ti != tj) {
        #pragma unroll
        for (int j = 0; j < 16; ++j) {
            const int cid = tid + 256 * j;
            const int mr = cid >> 5;
            const int mc4 = cid & 31;
            float v0 = st[(mc4 * 4 + 0) * 132 + mr];
            float v1 = st[(mc4 * 4 + 1) * 132 + mr];
            float v2 = st[(mc4 * 4 + 2) * 132 + mr];
            float v3 = st[(mc4 * 4 + 3) * 132 + mr];
            const uint32_t h0 = cvt2(v0, v1), h1 = cvt2(v2, v3);
            const uint32_t l0 = cvt2(v0 - lof(h0), v1 - hif(h0));
            const uint32_t l1 = cvt2(v2 - lof(h1), v3 - hif(h1));
            const size_t o = (size_t)(bn + mr) * C_ + bm + mc4 * 4;
            *(uint2*)(Gh + o) = make_uint2(h0, h1);
            *(uint2*)(Gl + o) = make_uint2(l0, l1);
        }
    }
}

// ---------------------------------------------------------------------------
// Fused X prep v3: Xhi/Xlo (bf16) + XT (fp16 hi plane) + row partial sums.
// 32c x 64n tiles, float2 loads, 4B stores. Grid (N/64, C/32, B).
// ---------------------------------------------------------------------------
__global__ void __launch_bounds__(256)
prep_x(const float* __restrict__ x,
       __nv_bfloat16* __restrict__ xhi, __nv_bfloat16* __restrict__ xlo,
       __half* __restrict__ xth, float* __restrict__ rp) {
    __shared__ float t[32][65];
    const int tid = threadIdx.x;
    const int b = blockIdx.z;
    const int c0 = blockIdx.y * 32;
    const int n0 = blockIdx.x * 64;
    const float* s = x + (size_t)b * C_ * N_;
    __nv_bfloat16* xh = xhi + (size_t)b * C_ * N_;
    __nv_bfloat16* xl = xlo + (size_t)b * C_ * N_;
    __half* th = xth + (size_t)b * N_ * C_;

    const int r8 = tid >> 5;
    const int cp = tid & 31;
    #pragma unroll
    for (int k = 0; k < 4; ++k) {
        const int cr = k * 8 + r8;
        const size_t o = (size_t)(c0 + cr) * N_ + n0 + cp * 2;
        const float2 v = *(const float2*)(s + o);
        t[cr][cp * 2]     = v.x;
        t[cr][cp * 2 + 1] = v.y;
        const uint32_t h = cvt2(v.x, v.y);
        const uint32_t l = cvt2(v.x - lof(h), v.y - hif(h));
        *(uint32_t*)(xh + o) = h;
        *(uint32_t*)(xl + o) = l;
        float ps = v.x + v.y;
        #pragma unroll
        for (int off = 16; off > 0; off >>= 1)
            ps += __shfl_down_sync(0xFFFFFFFFu, ps, off);
        if (cp == 0)
            rp[((size_t)b * C_ + c0 + cr) * 64 + blockIdx.x] = ps;
    }
    __syncthreads();

    const int nn0 = tid >> 4;
    const int ccp = tid & 15;
    #pragma unroll
    for (int j = 0; j < 4; ++j) {
        const int nn = j * 16 + nn0;
        const float v0 = t[2 * ccp][nn];
        const float v1 = t[2 * ccp + 1][nn];
        const __half2 h2 = __floats2half2_rn(v0, v1);
        const size_t o = (size_t)(n0 + nn) * C_ + c0 + 2 * ccp;
        *(uint32_t*)(th + o) = *(const uint32_t*)&h2;
    }
}

// ---------------------------------------------------------------------------
// Reduce row partials: r[row] = sum of rp[row][0..63]. One warp per row.
// ---------------------------------------------------------------------------
__global__ void __launch_bounds__(256)
reduce_r(const float* __restrict__ rp, float* __restrict__ r) {
    const int row = blockIdx.x * 8 + (threadIdx.x >> 5);
    const int lane = threadIdx.x & 31;
    float s = rp[(size_t)row * 64 + lane] + rp[(size_t)row * 64 + 32 + lane];
    #pragma unroll
    for (int off = 16; off > 0; off >>= 1)
        s += __shfl_down_sync(0xFFFFFFFFu, s, off);
    if (lane == 0) r[row] = s;
}

// ---------------------------------------------------------------------------
// Fused Wq + Wk split
// ---------------------------------------------------------------------------
__global__ void __launch_bounds__(256)
split_qk(const float* __restrict__ wq, const float* __restrict__ wk,
         __nv_bfloat16* __restrict__ qhi, __nv_bfloat16* __restrict__ qlo,
         __nv_bfloat16* __restrict__ khi, __nv_bfloat16* __restrict__ klo,
         long long n4) {
    long long i = (long long)blockIdx.x * blockDim.x + threadIdx.x;
    const long long stride = (long long)gridDim.x * blockDim.x;
    for (; i < n4; i += stride) {
        float4 v = ((const float4*)wq)[i];
        uint32_t h0 = cvt2(v.x, v.y), h1 = cvt2(v.z, v.w);
        uint32_t l0 = cvt2(v.x - lof(h0), v.y - hif(h0));
        uint32_t l1 = cvt2(v.z - lof(h1), v.w - hif(h1));
        ((uint2*)qhi)[i] = make_uint2(h0, h1);
        ((uint2*)qlo)[i] = make_uint2(l0, l1);
        v = ((const float4*)wk)[i];
        h0 = cvt2(v.x, v.y); h1 = cvt2(v.z, v.w);
        l0 = cvt2(v.x - lof(h0), v.y - hif(h0));
        l1 = cvt2(v.z - lof(h1), v.w - hif(h1));
        ((uint2*)khi)[i] = make_uint2(h0, h1);
        ((uint2*)klo)[i] = make_uint2(l0, l1);
    }
}

// ---------------------------------------------------------------------------
// qr = Wq r, kr = Wk r (all batches)
// ---------------------------------------------------------------------------
__global__ void __launch_bounds__(256) matvec_qk_kernel(const float* __restrict__ Wq,
                                                        const float* __restrict__ Wk,
                                                        const float* __restrict__ r,
                                                        float* __restrict__ qr,
                                                        float* __restrict__ kr) {
    const int b = blockIdx.y;
    const int warp = threadIdx.x >> 5;
    const int lane = threadIdx.x & 31;
    const int o = blockIdx.x * 8 + warp;
    const float* rb = r + b * C_;
    float sq = 0.f, sk = 0.f;
    for (int i = lane; i < C_; i += 32) {
        float rv = rb[i];
        sq += Wq[(size_t)o * C_ + i] * rv;
        sk += Wk[(size_t)o * C_ + i] * rv;
    }
    #pragma unroll
    for (int off = 16; off > 0; off >>= 1) {
        sq += __shfl_down_sync(0xFFFFFFFFu, sq, off);
        sk += __shfl_down_sync(0xFFFFFFFFu, sk, off);
    }
    if (lane == 0) { qr[b * C_ + o] = sq; kr[b * C_ + o] = sk; }
}

// ---------------------------------------------------------------------------
// Transpose + bf16 split (for Wv)
// ---------------------------------------------------------------------------
__global__ void __launch_bounds__(256)
transpose_cvt(const float* __restrict__ s, __nv_bfloat16* __restrict__ dhi,
              __nv_bfloat16* __restrict__ dlo, int R, int Cc) {
    __shared__ float t[32][33];
    const int tx = threadIdx.x & 31, ty = threadIdx.x >> 5;
    const int r0 = blockIdx.y * 32, c0 = blockIdx.x * 32;
    #pragma unroll
    for (int k = 0; k < 4; ++k)
        t[ty + 8 * k][tx] = s[(size_t)(r0 + ty + 8 * k) * Cc + c0 + tx];
    __syncthreads();
    #pragma unroll
    for (int k = 0; k < 4; ++k) {
        const int i = ty + 8 * k;
        const float v = t[tx][i];
        __nv_bfloat16 h = __float2bfloat16(v);
        __nv_bfloat16 l = __float2bfloat16(v - __bfloat162float(h));
        const size_t o = (size_t)(c0 + i) * R + r0 + tx;
        dhi[o] = h; dlo[o] = l;
    }
}

// ---------------------------------------------------------------------------
// Softmax with rank-1 bias corrections; attn -> bf16 hi/lo planes + beta
// ---------------------------------------------------------------------------
__global__ void __launch_bounds__(256)
softmax_beta_kernel(const float* __restrict__ S,
                    const float* __restrict__ qr, const float* __restrict__ kr,
                    const float* __restrict__ bq, const float* __restrict__ bk,
                    const float* __restrict__ bv,
                    __nv_bfloat16* __restrict__ Ahi, __nv_bfloat16* __restrict__ Alo,
                    float* __restrict__ beta) {
    __shared__ float sm[256];
    const int row = blockIdx.x;
    const int b = row >> 9;
    const int c = row & (C_ - 1);
    const float* Sr = S + (size_t)row * C_;
    const float* krb = kr + b * C_;
    const float qrc = qr[row];
    const float bqc = bq[c];
    const float scale = rsqrtf((float)C_);
    const int t = threadIdx.x;

    float v[2];
    float mx = -1e30f;
    #pragma unroll
    for (int u = 0; u < 2; ++u) {
        const int d = t + u * 256;
        float s = (Sr[d] + qrc * bk[d] + bqc * krb[d] + (float)N_ * bqc * bk[d]) * scale;
        v[u] = s;
        mx = fmaxf(mx, s);
    }
    sm[t] = mx; __syncthreads();
    #pragma unroll
    for (int off = 128; off > 0; off >>= 1) {
        if (t < off) sm[t] = fmaxf(sm[t], sm[t + off]);
        __syncthreads();
    }
    mx = sm[0];
    __syncthreads();

    float sum = 0.f;
    #pragma unroll
    for (int u = 0; u < 2; ++u) { v[u] = expf(v[u] - mx); sum += v[u]; }
    sm[t] = sum; __syncthreads();
    #pragma unroll
    for (int off = 128; off > 0; off >>= 1) {
        if (t < off) sm[t] += sm[t + off];
        __syncthreads();
    }
    const float inv = 1.f / sm[0];
    __syncthreads();

    float bc = 0.f;
    #pragma unroll
    for (int u = 0; u < 2; ++u) {
        const int d = t + u * 256;
        const float p = v[u] * inv;
        __nv_bfloat16 h = __float2bfloat16(p);
        __nv_bfloat16 l = __float2bfloat16(p - __bfloat162float(h));
        Ahi[(size_t)row * C_ + d] = h;
        Alo[(size_t)row * C_ + d] = l;
        bc += p * bv[d];
    }
    sm[t] = bc; __syncthreads();
    #pragma unroll
    for (int off = 128; off > 0; off >>= 1) {
        if (t < off) sm[t] += sm[t + off];
        __syncthreads();
    }
    if (t == 0) beta[row] = sm[0];
}

// ---------------------------------------------------------------------------
extern "C" void kernel_launch(void* const* d_in, const int* in_sizes, int n_in,
                              void* d_out, int out_size) {
    const float* x  = (const float*)d_in[0];
    const float* Wq = (const float*)d_in[1];
    const float* bq = (const float*)d_in[2];
    const float* Wk = (const float*)d_in[3];
    const float* bk = (const float*)d_in[4];
    const float* Wv = (const float*)d_in[5];
    const float* bv = (const float*)d_in[6];
    float* out = (float*)d_out;

    __nv_bfloat16 *Xhi, *Xlo, *Ghi, *Glo, *T1hi, *T1lo;
    __nv_bfloat16 *AThi, *ATlo, *Wqhi, *Wqlo, *Wkhi, *Wklo, *WvThi, *WvTlo;
    __half *XTh, *Mvh, *Mvl;
    float *S, *P, *rp, *r, *qr, *kr, *beta;
    cudaGetSymbolAddress((void**)&Xhi, g_Xhi);     cudaGetSymbolAddress((void**)&Xlo, g_Xlo);
    cudaGetSymbolAddress((void**)&XTh, g_XTh);
    cudaGetSymbolAddress((void**)&Ghi, g_Ghi);     cudaGetSymbolAddress((void**)&Glo, g_Glo);
    cudaGetSymbolAddress((void**)&T1hi, g_T1hi);   cudaGetSymbolAddress((void**)&T1lo, g_T1lo);
    cudaGetSymbolAddress((void**)&AThi, g_AThi);   cudaGetSymbolAddress((void**)&ATlo, g_ATlo);
    cudaGetSymbolAddress((void**)&Mvh, g_Mvh);     cudaGetSymbolAddress((void**)&Mvl, g_Mvl);
    cudaGetSymbolAddress((void**)&Wqhi, g_Wqhi);   cudaGetSymbolAddress((void**)&Wqlo, g_Wqlo);
    cudaGetSymbolAddress((void**)&Wkhi, g_Wkhi);   cudaGetSymbolAddress((void**)&Wklo, g_Wklo);
    cudaGetSymbolAddress((void**)&WvThi, g_WvThi); cudaGetSymbolAddress((void**)&WvTlo, g_WvTlo);
    cudaGetSymbolAddress((void**)&S, g_S);         cudaGetSymbolAddress((void**)&P, g_P);
    cudaGetSymbolAddress((void**)&rp, g_rp);       cudaGetSymbolAddress((void**)&r, g_r);
    cudaGetSymbolAddress((void**)&qr, g_qr);
    cudaGetSymbolAddress((void**)&kr, g_kr); cudaGetSymbolAddress((void**)&beta, g_beta);

    const long long CC = (long long)C_ * C_;

    cudaFuncSetAttribute(gemm_mma<0>, cudaFuncAttributeMaxDynamicSharedMemorySize, GEMM_SMEM);
    cudaFuncSetAttribute(gemm_mma<1>, cudaFuncAttributeMaxDynamicSharedMemorySize, GEMM_SMEM);
    cudaFuncSetAttribute(gemm_mma<3>, cudaFuncAttributeMaxDynamicSharedMemorySize, GEMM_SMEM);
    cudaFuncSetAttribute(gemm_sym_k,  cudaFuncAttributeMaxDynamicSharedMemorySize, GEMM_SMEM);
    cudaFuncSetAttribute(gemm_out,    cudaFuncAttributeMaxDynamicSharedMemorySize, OUT_SMEM);
    cudaFuncSetAttribute(combine_sym, cudaFuncAttributeMaxDynamicSharedMemorySize, COMB_SMEM);

    // Launch order keeps gemm_sym_k at index 3 (the slot ncu captures).
    prep_x<<<dim3(N_ / 64, C_ / 32, B_), 256>>>(x, Xhi, Xlo, XTh, rp);               // 0
    reduce_r<<<B_ * C_ / 8, 256>>>(rp, r);                                           // 1
    split_qk<<<256, 256>>>(Wq, Wk, Wqhi, Wqlo, Wkhi, Wklo, CC / 4);                  // 2

    // G = X X^T, symmetric upper-triangle, split-K=NSPLIT -> fp32 partials
    gemm_sym_k<<<dim3(10, NSPLIT, B_), NT, GEMM_SMEM>>>(Xhi, Xlo, P);                // 3

    combine_sym<<<10 * B_, 256, COMB_SMEM>>>(P, Ghi, Glo);                           // 4
    transpose_cvt<<<dim3(C_ / 32, C_ / 32), 256>>>(Wv, WvThi, WvTlo, C_, C_);        // 5
    matvec_qk_kernel<<<dim3(C_ / 8, B_), 256>>>(Wq, Wk, r, qr, kr);                  // 6

    // T1 = Wq G
    gemm_mma<1><<<dim3(4, 4, B_), NT, GEMM_SMEM>>>(
        Wqhi, Wqlo, C_, 0,  Ghi, Glo, C_, CC,
        nullptr, T1hi, T1lo, C_, CC, nullptr, C_);

    // S = T1 Wk^T (fp32 out)
    gemm_mma<0><<<dim3(4, 4, B_), NT, GEMM_SMEM>>>(
        T1hi, T1lo, C_, CC,  Wkhi, Wklo, C_, 0,
        S, nullptr, nullptr, C_, CC, nullptr, C_);

    // softmax(+rank-1 corrections) -> attn hl, beta = attn bv
    softmax_beta_kernel<<<B_ * C_, 256>>>(S, qr, kr, bq, bk, bv, AThi, ATlo, beta);

    // Mv = attn Wv -> fp16 hi/lo planes (OM=3)
    gemm_mma<3><<<dim3(4, 4, B_), NT, GEMM_SMEM>>>(
        AThi, ATlo, C_, CC,  WvThi, WvTlo, C_, 0,
        nullptr, (__nv_bfloat16*)Mvh, (__nv_bfloat16*)Mvl, C_, CC, nullptr, C_);

    // out = (Mvh + Mvl) * XTh^T + beta   (fp16 2-term)
    gemm_out<<<dim3(32, 4, B_), NT, OUT_SMEM>>>(Mvh, Mvl, XTh, out, beta);
}

// round 15
// speedup vs baseline: 1.2584x; 1.0397x over previous
#include <cuda_runtime.h>
#include <cuda_bf16.h>
#include <cuda_fp16.h>
#include <math.h>
#include <stdint.h>

#define B_ 16
#define C_ 512
#define N_ 4096
#define NSPLIT 8

// ---------------------------------------------------------------------------
// Scratch (device globals; allocation in kernel_launch is forbidden)
// ---------------------------------------------------------------------------
__device__ __align__(1024) __nv_bfloat16 g_Xhi [(size_t)B_ * C_ * N_];
__device__ __align__(1024) __nv_bfloat16 g_Xlo [(size_t)B_ * C_ * N_];
__device__ __align__(1024) __half        g_XTh [(size_t)B_ * N_ * C_];   // fp16 hi plane
__device__ __align__(1024) __nv_bfloat16 g_Ghi [B_ * C_ * C_], g_Glo [B_ * C_ * C_];
__device__ __align__(1024) __nv_bfloat16 g_T1hi[B_ * C_ * C_], g_T1lo[B_ * C_ * C_];
__device__ __align__(1024) __half        g_ATh [B_ * C_ * C_], g_ATl [B_ * C_ * C_];
__device__ __align__(1024) __half        g_Mvh [B_ * C_ * C_], g_Mvl [B_ * C_ * C_];
__device__ __align__(1024) __nv_bfloat16 g_Wqhi[C_ * C_], g_Wqlo[C_ * C_];
__device__ __align__(1024) __nv_bfloat16 g_Wkhi[C_ * C_], g_Wklo[C_ * C_];
__device__ __align__(1024) __half        g_WvTh[C_ * C_];
__device__ float g_S[B_ * C_ * C_];
__device__ __align__(1024) float g_P[(size_t)B_ * 10 * NSPLIT * 16384];   // split-K partials
__device__ float g_rp[(size_t)B_ * C_ * 64];
__device__ float g_r[B_ * C_], g_qr[B_ * C_], g_kr[B_ * C_], g_beta[B_ * C_];

__device__ __constant__ int c_ti[10] = {0,0,0,0,1,1,1,2,2,3};
__device__ __constant__ int c_tj[10] = {0,1,2,3,1,2,3,2,3,3};

// ---------------------------------------------------------------------------
// Helpers
// ---------------------------------------------------------------------------
__device__ __forceinline__ uint32_t smem_u32(const void* p) {
    uint32_t a;
    asm("{ .reg .u64 t; cvta.to.shared.u64 t, %1; cvt.u32.u64 %0, t; }" : "=r"(a) : "l"(p));
    return a;
}
__device__ __forceinline__ uint32_t sw128(uint32_t off) { return off ^ ((off >> 3) & 0x70); }

__device__ __forceinline__ uint32_t cvt2(float lo, float hi) {
    uint32_t r; asm("cvt.rn.bf16x2.f32 %0, %1, %2;" : "=r"(r) : "f"(hi), "f"(lo)); return r;
}
__device__ __forceinline__ float lof(uint32_t h) { return __uint_as_float(h << 16); }
__device__ __forceinline__ float hif(uint32_t h) { return __uint_as_float(h & 0xFFFF0000u); }

#define CP_ASYNC16(dst, src) \
    asm volatile("cp.async.cg.shared.global [%0], [%1], 16;" :: "r"(dst), "l"(src))
#define CP_COMMIT() asm volatile("cp.async.commit_group;")
#define CP_WAIT0()  asm volatile("cp.async.wait_group 0;")
#define CP_WAIT1()  asm volatile("cp.async.wait_group 1;")

#define LDSM4(r0, r1, r2, r3, addr) \
    asm volatile("ldmatrix.sync.aligned.m8n8.x4.shared.b16 {%0,%1,%2,%3}, [%4];" \
                 : "=r"(r0), "=r"(r1), "=r"(r2), "=r"(r3) : "r"(addr))

#define MMA16816(c, a, b) \
    asm volatile("mma.sync.aligned.m16n8k16.row.col.f32.bf16.bf16.f32 " \
                 "{%0,%1,%2,%3},{%4,%5,%6,%7},{%8,%9},{%0,%1,%2,%3};" \
                 : "+f"((c)[0]), "+f"((c)[1]), "+f"((c)[2]), "+f"((c)[3]) \
                 : "r"((a)[0]), "r"((a)[1]), "r"((a)[2]), "r"((a)[3]), \
                   "r"((b)[0]), "r"((b)[1]))

#define MMA16816H(c, a, b) \
    asm volatile("mma.sync.aligned.m16n8k16.row.col.f32.f16.f16.f32 " \
                 "{%0,%1,%2,%3},{%4,%5,%6,%7},{%8,%9},{%0,%1,%2,%3};" \
                 : "+f"((c)[0]), "+f"((c)[1]), "+f"((c)[2]), "+f"((c)[3]) \
                 : "r"((a)[0]), "r"((a)[1]), "r"((a)[2]), "r"((a)[3]), \
                   "r"((b)[0]), "r"((b)[1]))

#define GEMM_SMEM 196608    // bf16 3-term core & wide fp16 core: 3 x 64KB
#define MV_SMEM   147456    // fp16 2-term 128x128 core: 3 x 48KB
#define NT 512

// ---------------------------------------------------------------------------
// bf16 3-term GEMM mainloop (measured-best): CTA 128x128, warp 32x32, BK=64,
// 3-stage cp.async, prefetch-before-compute, A-lo reloads into A-hi regs.
// ---------------------------------------------------------------------------
__device__ __forceinline__ void gemm_core(
    const __nv_bfloat16* __restrict__ Ah, const __nv_bfloat16* __restrict__ Al, int lda,
    const __nv_bfloat16* __restrict__ Bh, const __nv_bfloat16* __restrict__ Bl, int ldb,
    int K, uint32_t sb, int tid, int wid, int lane, float acc[2][4][4]) {

    #pragma unroll
    for (int mi = 0; mi < 2; ++mi)
        #pragma unroll
        for (int ni = 0; ni < 4; ++ni)
            #pragma unroll
            for (int e = 0; e < 4; ++e) acc[mi][ni][e] = 0.f;

    const int nit = K >> 6;

    auto load_stage = [&](int s, int k0) {
        const uint32_t S = sb + (uint32_t)s * 65536u;
        #pragma unroll
        for (int j = 0; j < 2; ++j) {
            const int id = tid + NT * j;
            const int row = id >> 3;
            const int c = id & 7;
            const uint32_t off = sw128((uint32_t)row * 128u + (uint32_t)c * 16u);
            const size_t ga = (size_t)row * lda + k0 + c * 8;
            const size_t gb = (size_t)row * ldb + k0 + c * 8;
            CP_ASYNC16(S + off,          Ah + ga);
            CP_ASYNC16(S + 16384 + off,  Al + ga);
            CP_ASYNC16(S + 32768 + off,  Bh + gb);
            CP_ASYNC16(S + 49152 + off,  Bl + gb);
        }
    };

    load_stage(0, 0);
    CP_COMMIT();
    if (nit > 1) { load_stage(1, 64); }
    CP_COMMIT();

    const int m0l = (wid & 3) * 32;
    const int n0l = (wid >> 2) * 32;

    int s = 0;
    for (int it = 0; it < nit; ++it) {
        if (it + 1 < nit) { CP_WAIT1(); } else { CP_WAIT0(); }
        __syncthreads();

        {
            int s2 = s + 2; if (s2 >= 3) s2 -= 3;
            if (it + 2 < nit) load_stage(s2, (it + 2) * 64);
            CP_COMMIT();
        }

        const uint32_t Sa = sb + (uint32_t)s * 65536u;
        const uint32_t Sb = Sa + 32768;

        #pragma unroll
        for (int ks = 0; ks < 4; ++ks) {
            const uint32_t kb = (uint32_t)ks * 32u;
            uint32_t af[2][4];
            uint32_t aaddr[2];
            #pragma unroll
            for (int mi = 0; mi < 2; ++mi) {
                aaddr[mi] = Sa + sw128(
                    (uint32_t)(m0l + mi * 16 + (lane & 15)) * 128u + kb + (uint32_t)(lane >> 4) * 16u);
                LDSM4(af[mi][0], af[mi][1], af[mi][2], af[mi][3], aaddr[mi]);
            }
            uint32_t bh4[4][2], bl4[4][2];
            #pragma unroll
            for (int np = 0; np < 2; ++np) {
                const uint32_t bd = Sb + sw128(
                    (uint32_t)(n0l + np * 16 + (lane >> 4) * 8 + (lane & 7)) * 128u +
                    kb + (uint32_t)((lane >> 3) & 1) * 16u);
                uint32_t r0, r1, r2, r3;
                LDSM4(r0, r1, r2, r3, bd);
                bh4[np * 2][0] = r0; bh4[np * 2][1] = r1;
                bh4[np * 2 + 1][0] = r2; bh4[np * 2 + 1][1] = r3;
                LDSM4(r0, r1, r2, r3, bd + 16384);
                bl4[np * 2][0] = r0; bl4[np * 2][1] = r1;
                bl4[np * 2 + 1][0] = r2; bl4[np * 2 + 1][1] = r3;
            }
            #pragma unroll
            for (int mi = 0; mi < 2; ++mi)
                #pragma unroll
                for (int ni = 0; ni < 4; ++ni) {
                    MMA16816(acc[mi][ni], af[mi], bh4[ni]);
                    MMA16816(acc[mi][ni], af[mi], bl4[ni]);
                }
            #pragma unroll
            for (int mi = 0; mi < 2; ++mi)
                LDSM4(af[mi][0], af[mi][1], af[mi][2], af[mi][3], aaddr[mi] + 16384);
            #pragma unroll
            for (int mi = 0; mi < 2; ++mi)
                #pragma unroll
                for (int ni = 0; ni < 4; ++ni)
                    MMA16816(acc[mi][ni], af[mi], bh4[ni]);
        }

        if (++s == 3) s = 0;
    }
}

// ---------------------------------------------------------------------------
// General bf16 HMMA GEMM. OM: 0 fp32 out, 1 bf16 hi/lo out.
// ---------------------------------------------------------------------------
template <int OM>
__global__ void __launch_bounds__(NT, 1)
gemm_mma(const __nv_bfloat16* __restrict__ Ahi, const __nv_bfloat16* __restrict__ Alo,
         int lda, long long sA,
         const __nv_bfloat16* __restrict__ Bhi, const __nv_bfloat16* __restrict__ Blo,
         int ldb, long long sB,
         float* __restrict__ Cf, __nv_bfloat16* __restrict__ Chi,
         __nv_bfloat16* __restrict__ Clo, int ldc, long long sC, int K) {
    extern __shared__ char smem[];
    const uint32_t sb = smem_u32(smem);
    const int tid = threadIdx.x;
    const int wid = tid >> 5;
    const int lane = tid & 31;
    const int bz = blockIdx.z;
    const int bm = blockIdx.y * 128;
    const int bn = blockIdx.x * 128;

    float acc[2][4][4];
    gemm_core(Ahi + (size_t)bz * sA + (size_t)bm * lda,
              Alo + (size_t)bz * sA + (size_t)bm * lda, lda,
              Bhi + (size_t)bz * sB + (size_t)bn * ldb,
              Blo + (size_t)bz * sB + (size_t)bn * ldb, ldb,
              K, sb, tid, wid, lane, acc);

    float* Cfb = Cf ? (Cf + (size_t)bz * sC) : nullptr;
    __nv_bfloat16* Chb = Chi ? (Chi + (size_t)bz * sC) : nullptr;
    __nv_bfloat16* Clb = Clo ? (Clo + (size_t)bz * sC) : nullptr;

    const int m0l = (wid & 3) * 32;
    const int n0l = (wid >> 2) * 32;

    #pragma unroll
    for (int mi = 0; mi < 2; ++mi) {
        #pragma unroll
        for (int h = 0; h < 2; ++h) {
            const int row = bm + m0l + mi * 16 + (lane >> 2) + h * 8;
            #pragma unroll
            for (int ni = 0; ni < 4; ++ni) {
                const int col = bn + n0l + ni * 8 + (lane & 3) * 2;
                const float v0 = acc[mi][ni][h * 2 + 0];
                const float v1 = acc[mi][ni][h * 2 + 1];
                if (OM == 1) {
                    const uint32_t hh = cvt2(v0, v1);
                    const uint32_t ll = cvt2(v0 - lof(hh), v1 - hif(hh));
                    *(uint32_t*)(Chb + (size_t)row * ldc + col) = hh;
                    *(uint32_t*)(Clb + (size_t)row * ldc + col) = ll;
                } else {
                    float2 v; v.x = v0; v.y = v1;
                    *(float2*)(Cfb + (size_t)row * ldc + col) = v;
                }
            }
        }
    }
}

// ---------------------------------------------------------------------------
// fp16 2-term Mv GEMM: Mv = (ATh+ATl) * WvTh^T, fp16 hi/lo out.
// CTA 128x128, warp 32x32, BK=64, 3-stage (48KB/stage).
// ---------------------------------------------------------------------------
__global__ void __launch_bounds__(NT, 1)
gemm_mv(const __half* __restrict__ Ahi, const __half* __restrict__ Alo,
        const __half* __restrict__ Bh,
        __half* __restrict__ Ch, __half* __restrict__ Cl) {
    extern __shared__ char smem[];
    const uint32_t sb = smem_u32(smem);
    const int tid = threadIdx.x;
    const int wid = tid >> 5;
    const int lane = tid & 31;
    const int bz = blockIdx.z;
    const int bm = blockIdx.y * 128;
    const int bn = blockIdx.x * 128;

    const __half* Ah = Ahi + (size_t)bz * (C_ * C_) + (size_t)bm * C_;
    const __half* Al = Alo + (size_t)bz * (C_ * C_) + (size_t)bm * C_;
    const __half* Bp = Bh + (size_t)bn * C_;

    float acc[2][4][4];
    #pragma unroll
    for (int mi = 0; mi < 2; ++mi)
        #pragma unroll
        for (int ni = 0; ni < 4; ++ni)
            #pragma unroll
            for (int e = 0; e < 4; ++e) acc[mi][ni][e] = 0.f;

    const int nit = C_ >> 6;

    auto load_stage = [&](int s, int k0) {
        const uint32_t S = sb + (uint32_t)s * 49152u;
        #pragma unroll
        for (int j = 0; j < 2; ++j) {
            const int id = tid + NT * j;
            const int row = id >> 3;
            const int c = id & 7;
            const uint32_t off = sw128((uint32_t)row * 128u + (uint32_t)c * 16u);
            const size_t ga = (size_t)row * C_ + k0 + c * 8;
            CP_ASYNC16(S + off,          Ah + ga);
            CP_ASYNC16(S + 16384 + off,  Al + ga);
            CP_ASYNC16(S + 32768 + off,  Bp + ga);
        }
    };

    load_stage(0, 0); CP_COMMIT();
    load_stage(1, 64); CP_COMMIT();

    const int m0l = (wid & 3) * 32;
    const int n0l = (wid >> 2) * 32;

    int s = 0;
    for (int it = 0; it < nit; ++it) {
        if (it + 1 < nit) { CP_WAIT1(); } else { CP_WAIT0(); }
        __syncthreads();
        {
            int s2 = s + 2; if (s2 >= 3) s2 -= 3;
            if (it + 2 < nit) load_stage(s2, (it + 2) * 64);
            CP_COMMIT();
        }
        const uint32_t Sa = sb + (uint32_t)s * 49152u;
        const uint32_t Sb = Sa + 32768u;

        #pragma unroll
        for (int ks = 0; ks < 4; ++ks) {
            const uint32_t kb = (uint32_t)ks * 32u;
            uint32_t ah[2][4];
            uint32_t aad[2];
            #pragma unroll
            for (int mi = 0; mi < 2; ++mi) {
                aad[mi] = Sa + sw128(
                    (uint32_t)(m0l + mi * 16 + (lane & 15)) * 128u + kb + (uint32_t)(lane >> 4) * 16u);
                LDSM4(ah[mi][0], ah[mi][1], ah[mi][2], ah[mi][3], aad[mi]);
            }
            uint32_t bh4[4][2];
            #pragma unroll
            for (int np = 0; np < 2; ++np) {
                const uint32_t bd = Sb + sw128(
                    (uint32_t)(n0l + np * 16 + (lane >> 4) * 8 + (lane & 7)) * 128u +
                    kb + (uint32_t)((lane >> 3) & 1) * 16u);
                uint32_t r0, r1, r2, r3;
                LDSM4(r0, r1, r2, r3, bd);
                bh4[np * 2][0] = r0; bh4[np * 2][1] = r1;
                bh4[np * 2 + 1][0] = r2; bh4[np * 2 + 1][1] = r3;
            }
            #pragma unroll
            for (int mi = 0; mi < 2; ++mi)
                #pragma unroll
                for (int ni = 0; ni < 4; ++ni)
                    MMA16816H(acc[mi][ni], ah[mi], bh4[ni]);
            #pragma unroll
            for (int mi = 0; mi < 2; ++mi)
                LDSM4(ah[mi][0], ah[mi][1], ah[mi][2], ah[mi][3], aad[mi] + 16384);
            #pragma unroll
            for (int mi = 0; mi < 2; ++mi)
                #pragma unroll
                for (int ni = 0; ni < 4; ++ni)
                    MMA16816H(acc[mi][ni], ah[mi], bh4[ni]);
        }
        if (++s == 3) s = 0;
    }

    __half* Chb = Ch + (size_t)bz * (C_ * C_);
    __half* Clb = Cl + (size_t)bz * (C_ * C_);
    const int m0 = (wid & 3) * 32;
    const int n0 = (wid >> 2) * 32;
    #pragma unroll
    for (int mi = 0; mi < 2; ++mi)
        #pragma unroll
        for (int h = 0; h < 2; ++h) {
            const int row = bm + m0 + mi * 16 + (lane >> 2) + h * 8;
            #pragma unroll
            for (int ni = 0; ni < 4; ++ni) {
                const int col = bn + n0 + ni * 8 + (lane & 3) * 2;
                const float v0 = acc[mi][ni][h * 2 + 0];
                const float v1 = acc[mi][ni][h * 2 + 1];
                const __half2 h2 = __floats2half2_rn(v0, v1);
                const float2 hf = __half22float2(h2);
                const __half2 l2 = __floats2half2_rn(v0 - hf.x, v1 - hf.y);
                *(uint32_t*)(Chb + (size_t)row * C_ + col) = *(const uint32_t*)&h2;
                *(uint32_t*)(Clb + (size_t)row * C_ + col) = *(const uint32_t*)&l2;
            }
        }
}

// ---------------------------------------------------------------------------
// fp16 2-term WIDE out-GEMM: D = (Mvh+Mvl) * XTh^T + bias.
// CTA 128x256, 16 warps of 32x64, BK=64, 3-stage (64KB/stage).
// Stage: A hi @0 (16KB), A lo @16K, B @32K (32KB, 256 rows).
// ---------------------------------------------------------------------------
__global__ void __launch_bounds__(NT, 1)
gemm_out(const __half* __restrict__ Ahi, const __half* __restrict__ Alo,
         const __half* __restrict__ Bh,
         float* __restrict__ Cf, const float* __restrict__ bias) {
    extern __shared__ char smem[];
    const uint32_t sb = smem_u32(smem);
    const int tid = threadIdx.x;
    const int wid = tid >> 5;
    const int lane = tid & 31;
    const int bz = blockIdx.z;
    const int bm = blockIdx.y * 128;
    const int bn = blockIdx.x * 256;

    const __half* Ah = Ahi + (size_t)bz * (C_ * C_) + (size_t)bm * C_;
    const __half* Al = Alo + (size_t)bz * (C_ * C_) + (size_t)bm * C_;
    const __half* Bp = Bh + (size_t)bz * ((size_t)N_ * C_) + (size_t)bn * C_;

    float acc[2][8][4];
    #pragma unroll
    for (int mi = 0; mi < 2; ++mi)
        #pragma unroll
        for (int ni = 0; ni < 8; ++ni)
            #pragma unroll
            for (int e = 0; e < 4; ++e) acc[mi][ni][e] = 0.f;

    const int nit = C_ >> 6;   // 8

    auto load_stage = [&](int s, int k0) {
        const uint32_t S = sb + (uint32_t)s * 65536u;
        // A: 2 planes x 128 rows x 8 chunks = 2048
        #pragma unroll
        for (int j = 0; j < 4; ++j) {
            const int id = tid + NT * j;
            const int plane = id >> 10;
            const int row = (id >> 3) & 127;
            const int c = id & 7;
            const uint32_t off = sw128((uint32_t)row * 128u + (uint32_t)c * 16u)
                               + (uint32_t)plane * 16384u;
            const __half* src = (plane ? Al : Ah) + (size_t)row * C_ + k0 + c * 8;
            CP_ASYNC16(S + off, src);
        }
        // B: 256 rows x 8 chunks = 2048
        #pragma unroll
        for (int j = 0; j < 4; ++j) {
            const int id = tid + NT * j;
            const int row = id >> 3;
            const int c = id & 7;
            const uint32_t off = sw128((uint32_t)row * 128u + (uint32_t)c * 16u) + 32768u;
            CP_ASYNC16(S + off, Bp + (size_t)row * C_ + k0 + c * 8);
        }
    };

    load_stage(0, 0); CP_COMMIT();
    load_stage(1, 64); CP_COMMIT();

    const int m0l = (wid & 3) * 32;
    const int n0l = (wid >> 2) * 64;

    int s = 0;
    for (int it = 0; it < nit; ++it) {
        if (it + 1 < nit) { CP_WAIT1(); } else { CP_WAIT0(); }
        __syncthreads();
        {
            int s2 = s + 2; if (s2 >= 3) s2 -= 3;
            if (it + 2 < nit) load_stage(s2, (it + 2) * 64);
            CP_COMMIT();
        }
        const uint32_t Sa = sb + (uint32_t)s * 65536u;
        const uint32_t Sb = Sa + 32768u;

        #pragma unroll
        for (int ks = 0; ks < 4; ++ks) {
            const uint32_t kb = (uint32_t)ks * 32u;
            uint32_t ah[2][4];
            uint32_t aad[2];
            #pragma unroll
            for (int mi = 0; mi < 2; ++mi) {
                aad[mi] = Sa + sw128(
                    (uint32_t)(m0l + mi * 16 + (lane & 15)) * 128u + kb + (uint32_t)(lane >> 4) * 16u);
                LDSM4(ah[mi][0], ah[mi][1], ah[mi][2], ah[mi][3], aad[mi]);
            }
            uint32_t bh4[8][2];
            #pragma unroll
            for (int np = 0; np < 4; ++np) {
                const uint32_t bd = Sb + sw128(
                    (uint32_t)(n0l + np * 16 + (lane >> 4) * 8 + (lane & 7)) * 128u +
                    kb + (uint32_t)((lane >> 3) & 1) * 16u);
                uint32_t r0, r1, r2, r3;
                LDSM4(r0, r1, r2, r3, bd);
                bh4[np * 2][0] = r0; bh4[np * 2][1] = r1;
                bh4[np * 2 + 1][0] = r2; bh4[np * 2 + 1][1] = r3;
            }
            #pragma unroll
            for (int mi = 0; mi < 2; ++mi)
                #pragma unroll
                for (int ni = 0; ni < 8; ++ni)
                    MMA16816H(acc[mi][ni], ah[mi], bh4[ni]);
            #pragma unroll
            for (int mi = 0; mi < 2; ++mi)
                LDSM4(ah[mi][0], ah[mi][1], ah[mi][2], ah[mi][3], aad[mi] + 16384);
            #pragma unroll
            for (int mi = 0; mi < 2; ++mi)
                #pragma unroll
                for (int ni = 0; ni < 8; ++ni)
                    MMA16816H(acc[mi][ni], ah[mi], bh4[ni]);
        }
        if (++s == 3) s = 0;
    }

    float* Cfb = Cf + (size_t)bz * ((size_t)C_ * N_);
    #pragma unroll
    for (int mi = 0; mi < 2; ++mi) {
        #pragma unroll
        for (int h = 0; h < 2; ++h) {
            const int row = bm + m0l + mi * 16 + (lane >> 2) + h * 8;
            const float bb = bias[bz * C_ + row];
            #pragma unroll
            for (int ni = 0; ni < 8; ++ni) {
                const int col = bn + n0l + ni * 8 + (lane & 3) * 2;
                float2 v;
                v.x = acc[mi][ni][h * 2 + 0] + bb;
                v.y = acc[mi][ni][h * 2 + 1] + bb;
                *(float2*)(Cfb + (size_t)row * N_ + col) = v;
            }
        }
    }
}

// ---------------------------------------------------------------------------
// Split-K symmetric GEMM stage 1. Grid (10, NSPLIT, B_). fp32 partial out.
// ---------------------------------------------------------------------------
__global__ void __launch_bounds__(NT, 1)
gemm_sym_k(const __nv_bfloat16* __restrict__ Xhi, const __nv_bfloat16* __restrict__ Xlo,
           float* __restrict__ P) {
    extern __shared__ char smem[];
    const uint32_t sb = smem_u32(smem);
    const int tid = threadIdx.x;
    const int wid = tid >> 5;
    const int lane = tid & 31;
    const int bz = blockIdx.z;
    const int split = blockIdx.y;
    const int ti = c_ti[blockIdx.x];
    const int tj = c_tj[blockIdx.x];
    const int bm = ti * 128;
    const int bn = tj * 128;
    const int k0 = split * (N_ / NSPLIT);

    const size_t xb = (size_t)bz * ((size_t)C_ * N_);
    float acc[2][4][4];
    gemm_core(Xhi + xb + (size_t)bm * N_ + k0, Xlo + xb + (size_t)bm * N_ + k0, N_,
              Xhi + xb + (size_t)bn * N_ + k0, Xlo + xb + (size_t)bn * N_ + k0, N_,
              N_ / NSPLIT, sb, tid, wid, lane, acc);

    float* Pt = P + (((size_t)bz * 10 + blockIdx.x) * NSPLIT + split) * 16384;
    const int m0l = (wid & 3) * 32;
    const int n0l = (wid >> 2) * 32;

    #pragma unroll
    for (int mi = 0; mi < 2; ++mi)
        #pragma unroll
        for (int h = 0; h < 2; ++h) {
            const int row = m0l + mi * 16 + (lane >> 2) + h * 8;
            #pragma unroll
            for (int ni = 0; ni < 4; ++ni) {
                const int col = n0l + ni * 8 + (lane & 3) * 2;
                float2 v;
                v.x = acc[mi][ni][h * 2 + 0];
                v.y = acc[mi][ni][h * 2 + 1];
                *(float2*)(Pt + row * 128 + col) = v;
            }
        }
}

// ---------------------------------------------------------------------------
// Split-K combine (unchanged)
// ---------------------------------------------------------------------------
#define COMB_SMEM (128 * 132 * 4)
__global__ void __launch_bounds__(256, 1)
combine_sym(const float* __restrict__ P,
            __nv_bfloat16* __restrict__ Ghi, __nv_bfloat16* __restrict__ Glo) {
    extern __shared__ char smem[];
    float* st = (float*)smem;
    const int tid = threadIdx.x;
    const int t = blockIdx.x % 10;
    const int bz = blockIdx.x / 10;
    const int ti = c_ti[t];
    const int tj = c_tj[t];
    const int bm = ti * 128;
    const int bn = tj * 128;

    const float* Pb = P + ((size_t)bz * 10 + t) * NSPLIT * 16384;

    #pragma unroll
    for (int j = 0; j < 16; ++j) {
        const int cid = tid + 256 * j;
        const int row = cid >> 5;
        const int c4 = cid & 31;
        float4 s = *(const float4*)(Pb + cid * 4);
        #pragma unroll
        for (int sp = 1; sp < NSPLIT; ++sp) {
            const float4 a = *(const float4*)(Pb + sp * 16384 + cid * 4);
            s.x += a.x; s.y += a.y; s.z += a.z; s.w += a.w;
        }
        float* d = st + row * 132 + c4 * 4;
        d[0] = s.x; d[1] = s.y; d[2] = s.z; d[3] = s.w;
    }
    __syncthreads();

    __nv_bfloat16* Gh = Ghi + (size_t)bz * (C_ * C_);
    __nv_bfloat16* Gl = Glo + (size_t)bz * (C_ * C_);

    #pragma unroll
    for (int j = 0; j < 16; ++j) {
        const int cid = tid + 256 * j;
        const int row = cid >> 5;
        const int c4 = cid & 31;
        const float4 v = *(const float4*)(st + row * 132 + c4 * 4);
        const uint32_t h0 = cvt2(v.x, v.y), h1 = cvt2(v.z, v.w);
        const uint32_t l0 = cvt2(v.x - lof(h0), v.y - hif(h0));
        const uint32_t l1 = cvt2(v.z - lof(h1), v.w - hif(h1));
        const size_t o = (size_t)(bm + row) * C_ + bn + c4 * 4;
        *(uint2*)(Gh + o) = make_uint2(h0, h1);
        *(uint2*)(Gl + o) = make_uint2(l0, l1);
    }

    if (ti != tj) {
        #pragma unroll
        for (int j = 0; j < 16; ++j) {
            const int cid = tid + 256 * j;
            const int mr = cid >> 5;
            const int mc4 = cid & 31;
            float v0 = st[(mc4 * 4 + 0) * 132 + mr];
            float v1 = st[(mc4 * 4 + 1) * 132 + mr];
            float v2 = st[(mc4 * 4 + 2) * 132 + mr];
            float v3 = st[(mc4 * 4 + 3) * 132 + mr];
            const uint32_t h0 = cvt2(v0, v1), h1 = cvt2(v2, v3);
            const uint32_t l0 = cvt2(v0 - lof(h0), v1 - hif(h0));
            const uint32_t l1 = cvt2(v2 - lof(h1), v3 - hif(h1));
            const size_t o = (size_t)(bn + mr) * C_ + bm + mc4 * 4;
            *(uint2*)(Gh + o) = make_uint2(h0, h1);
            *(uint2*)(Gl + o) = make_uint2(l0, l1);
        }
    }
}

// ---------------------------------------------------------------------------
// Fused X prep: Xhi/Xlo (bf16) + XT (fp16 hi plane) + row partial sums.
// ---------------------------------------------------------------------------
__global__ void __launch_bounds__(256)
prep_x(const float* __restrict__ x,
       __nv_bfloat16* __restrict__ xhi, __nv_bfloat16* __restrict__ xlo,
       __half* __restrict__ xth, float* __restrict__ rp) {
    __shared__ float t[32][65];
    const int tid = threadIdx.x;
    const int b = blockIdx.z;
    const int c0 = blockIdx.y * 32;
    const int n0 = blockIdx.x * 64;
    const float* s = x + (size_t)b * C_ * N_;
    __nv_bfloat16* xh = xhi + (size_t)b * C_ * N_;
    __nv_bfloat16* xl = xlo + (size_t)b * C_ * N_;
    __half* th = xth + (size_t)b * N_ * C_;

    const int r8 = tid >> 5;
    const int cp = tid & 31;
    #pragma unroll
    for (int k = 0; k < 4; ++k) {
        const int cr = k * 8 + r8;
        const size_t o = (size_t)(c0 + cr) * N_ + n0 + cp * 2;
        const float2 v = *(const float2*)(s + o);
        t[cr][cp * 2]     = v.x;
        t[cr][cp * 2 + 1] = v.y;
        const uint32_t h = cvt2(v.x, v.y);
        const uint32_t l = cvt2(v.x - lof(h), v.y - hif(h));
        *(uint32_t*)(xh + o) = h;
        *(uint32_t*)(xl + o) = l;
        float ps = v.x + v.y;
        #pragma unroll
        for (int off = 16; off > 0; off >>= 1)
            ps += __shfl_down_sync(0xFFFFFFFFu, ps, off);
        if (cp == 0)
            rp[((size_t)b * C_ + c0 + cr) * 64 + blockIdx.x] = ps;
    }
    __syncthreads();

    const int nn0 = tid >> 4;
    const int ccp = tid & 15;
    #pragma unroll
    for (int j = 0; j < 4; ++j) {
        const int nn = j * 16 + nn0;
        const float v0 = t[2 * ccp][nn];
        const float v1 = t[2 * ccp + 1][nn];
        const __half2 h2 = __floats2half2_rn(v0, v1);
        const size_t o = (size_t)(n0 + nn) * C_ + c0 + 2 * ccp;
        *(uint32_t*)(th + o) = *(const uint32_t*)&h2;
    }
}

// ---------------------------------------------------------------------------
// Reduce row partials
// ---------------------------------------------------------------------------
__global__ void __launch_bounds__(256)
reduce_r(const float* __restrict__ rp, float* __restrict__ r) {
    const int row = blockIdx.x * 8 + (threadIdx.x >> 5);
    const int lane = threadIdx.x & 31;
    float s = rp[(size_t)row * 64 + lane] + rp[(size_t)row * 64 + 32 + lane];
    #pragma unroll
    for (int off = 16; off > 0; off >>= 1)
        s += __shfl_down_sync(0xFFFFFFFFu, s, off);
    if (lane == 0) r[row] = s;
}

// ---------------------------------------------------------------------------
// Fused Wq + Wk split
// ---------------------------------------------------------------------------
__global__ void __launch_bounds__(256)
split_qk(const float* __restrict__ wq, const float* __restrict__ wk,
         __nv_bfloat16* __restrict__ qhi, __nv_bfloat16* __restrict__ qlo,
         __nv_bfloat16* __restrict__ khi, __nv_bfloat16* __restrict__ klo,
         long long n4) {
    long long i = (long long)blockIdx.x * blockDim.x + threadIdx.x;
    const long long stride = (long long)gridDim.x * blockDim.x;
    for (; i < n4; i += stride) {
        float4 v = ((const float4*)wq)[i];
        uint32_t h0 = cvt2(v.x, v.y), h1 = cvt2(v.z, v.w);
        uint32_t l0 = cvt2(v.x - lof(h0), v.y - hif(h0));
        uint32_t l1 = cvt2(v.z - lof(h1), v.w - hif(h1));
        ((uint2*)qhi)[i] = make_uint2(h0, h1);
        ((uint2*)qlo)[i] = make_uint2(l0, l1);
        v = ((const float4*)wk)[i];
        h0 = cvt2(v.x, v.y); h1 = cvt2(v.z, v.w);
        l0 = cvt2(v.x - lof(h0), v.y - hif(h0));
        l1 = cvt2(v.z - lof(h1), v.w - hif(h1));
        ((uint2*)khi)[i] = make_uint2(h0, h1);
        ((uint2*)klo)[i] = make_uint2(l0, l1);
    }
}

// ---------------------------------------------------------------------------
// qr = Wq r, kr = Wk r (all batches)
// ---------------------------------------------------------------------------
__global__ void __launch_bounds__(256) matvec_qk_kernel(const float* __restrict__ Wq,
                                                        const float* __restrict__ Wk,
                                                        const float* __restrict__ r,
                                                        float* __restrict__ qr,
                                                        float* __restrict__ kr) {
    const int b = blockIdx.y;
    const int warp = threadIdx.x >> 5;
    const int lane = threadIdx.x & 31;
    const int o = blockIdx.x * 8 + warp;
    const float* rb = r + b * C_;
    float sq = 0.f, sk = 0.f;
    for (int i = lane; i < C_; i += 32) {
        float rv = rb[i];
        sq += Wq[(size_t)o * C_ + i] * rv;
        sk += Wk[(size_t)o * C_ + i] * rv;
    }
    #pragma unroll
    for (int off = 16; off > 0; off >>= 1) {
        sq += __shfl_down_sync(0xFFFFFFFFu, sq, off);
        sk += __shfl_down_sync(0xFFFFFFFFu, sk, off);
    }
    if (lane == 0) { qr[b * C_ + o] = sq; kr[b * C_ + o] = sk; }
}

// ---------------------------------------------------------------------------
// Transpose + fp16 convert (for Wv -> WvT fp16 hi plane)
// ---------------------------------------------------------------------------
__global__ void __launch_bounds__(256)
transpose_cvt_h(const float* __restrict__ s, __half* __restrict__ dh, int R, int Cc) {
    __shared__ float t[32][33];
    const int tx = threadIdx.x & 31, ty = threadIdx.x >> 5;
    const int r0 = blockIdx.y * 32, c0 = blockIdx.x * 32;
    #pragma unroll
    for (int k = 0; k < 4; ++k)
        t[ty + 8 * k][tx] = s[(size_t)(r0 + ty + 8 * k) * Cc + c0 + tx];
    __syncthreads();
    #pragma unroll
    for (int k = 0; k < 4; ++k) {
        const int i = ty + 8 * k;
        dh[(size_t)(c0 + i) * R + r0 + tx] = __float2half(t[tx][i]);
    }
}

// ---------------------------------------------------------------------------
// Softmax with rank-1 bias corrections; attn -> fp16 hi/lo planes + beta
// ---------------------------------------------------------------------------
__global__ void __launch_bounds__(256)
softmax_beta_kernel(const float* __restrict__ S,
                    const float* __restrict__ qr, const float* __restrict__ kr,
                    const float* __restrict__ bq, const float* __restrict__ bk,
                    const float* __restrict__ bv,
                    __half* __restrict__ Ahi, __half* __restrict__ Alo,
                    float* __restrict__ beta) {
    __shared__ float sm[256];
    const int row = blockIdx.x;
    const int b = row >> 9;
    const int c = row & (C_ - 1);
    const float* Sr = S + (size_t)row * C_;
    const float* krb = kr + b * C_;
    const float qrc = qr[row];
    const float bqc = bq[c];
    const float scale = rsqrtf((float)C_);
    const int t = threadIdx.x;

    float v[2];
    float mx = -1e30f;
    #pragma unroll
    for (int u = 0; u < 2; ++u) {
        const int d = t + u * 256;
        float s = (Sr[d] + qrc * bk[d] + bqc * krb[d] + (float)N_ * bqc * bk[d]) * scale;
        v[u] = s;
        mx = fmaxf(mx, s);
    }
    sm[t] = mx; __syncthreads();
    #pragma unroll
    for (int off = 128; off > 0; off >>= 1) {
        if (t < off) sm[t] = fmaxf(sm[t], sm[t + off]);
        __syncthreads();
    }
    mx = sm[0];
    __syncthreads();

    float sum = 0.f;
    #pragma unroll
    for (int u = 0; u < 2; ++u) { v[u] = expf(v[u] - mx); sum += v[u]; }
    sm[t] = sum; __syncthreads();
    #pragma unroll
    for (int off = 128; off > 0; off >>= 1) {
        if (t < off) sm[t] += sm[t + off];
        __syncthreads();
    }
    const float inv = 1.f / sm[0];
    __syncthreads();

    float bc = 0.f;
    #pragma unroll
    for (int u = 0; u < 2; ++u) {
        const int d = t + u * 256;
        const float p = v[u] * inv;
        const __half h = __float2half(p);
        const __half l = __float2half(p - __half2float(h));
        Ahi[(size_t)row * C_ + d] = h;
        Alo[(size_t)row * C_ + d] = l;
        bc += p * bv[d];
    }
    sm[t] = bc; __syncthreads();
    #pragma unroll
    for (int off = 128; off > 0; off >>= 1) {
        if (t < off) sm[t] += sm[t + off];
        __syncthreads();
    }
    if (t == 0) beta[row] = sm[0];
}

// ---------------------------------------------------------------------------
extern "C" void kernel_launch(void* const* d_in, const int* in_sizes, int n_in,
                              void* d_out, int out_size) {
    const float* x  = (const float*)d_in[0];
    const float* Wq = (const float*)d_in[1];
    const float* bq = (const float*)d_in[2];
    const float* Wk = (const float*)d_in[3];
    const float* bk = (const float*)d_in[4];
    const float* Wv = (const float*)d_in[5];
    const float* bv = (const float*)d_in[6];
    float* out = (float*)d_out;

    __nv_bfloat16 *Xhi, *Xlo, *Ghi, *Glo, *T1hi, *T1lo;
    __nv_bfloat16 *Wqhi, *Wqlo, *Wkhi, *Wklo;
    __half *XTh, *ATh, *ATl, *Mvh, *Mvl, *WvTh;
    float *S, *P, *rp, *r, *qr, *kr, *beta;
    cudaGetSymbolAddress((void**)&Xhi, g_Xhi);     cudaGetSymbolAddress((void**)&Xlo, g_Xlo);
    cudaGetSymbolAddress((void**)&XTh, g_XTh);
    cudaGetSymbolAddress((void**)&Ghi, g_Ghi);     cudaGetSymbolAddress((void**)&Glo, g_Glo);
    cudaGetSymbolAddress((void**)&T1hi, g_T1hi);   cudaGetSymbolAddress((void**)&T1lo, g_T1lo);
    cudaGetSymbolAddress((void**)&ATh, g_ATh);     cudaGetSymbolAddress((void**)&ATl, g_ATl);
    cudaGetSymbolAddress((void**)&Mvh, g_Mvh);     cudaGetSymbolAddress((void**)&Mvl, g_Mvl);
    cudaGetSymbolAddress((void**)&Wqhi, g_Wqhi);   cudaGetSymbolAddress((void**)&Wqlo, g_Wqlo);
    cudaGetSymbolAddress((void**)&Wkhi, g_Wkhi);   cudaGetSymbolAddress((void**)&Wklo, g_Wklo);
    cudaGetSymbolAddress((void**)&WvTh, g_WvTh);
    cudaGetSymbolAddress((void**)&S, g_S);         cudaGetSymbolAddress((void**)&P, g_P);
    cudaGetSymbolAddress((void**)&rp, g_rp);       cudaGetSymbolAddress((void**)&r, g_r);
    cudaGetSymbolAddress((void**)&qr, g_qr);
    cudaGetSymbolAddress((void**)&kr, g_kr); cudaGetSymbolAddress((void**)&beta, g_beta);

    const long long CC = (long long)C_ * C_;

    cudaFuncSetAttribute(gemm_mma<0>, cudaFuncAttributeMaxDynamicSharedMemorySize, GEMM_SMEM);
    cudaFuncSetAttribute(gemm_mma<1>, cudaFuncAttributeMaxDynamicSharedMemorySize, GEMM_SMEM);
    cudaFuncSetAttribute(gemm_sym_k,  cudaFuncAttributeMaxDynamicSharedMemorySize, GEMM_SMEM);
    cudaFuncSetAttribute(gemm_mv,     cudaFuncAttributeMaxDynamicSharedMemorySize, MV_SMEM);
    cudaFuncSetAttribute(gemm_out,    cudaFuncAttributeMaxDynamicSharedMemorySize, GEMM_SMEM);
    cudaFuncSetAttribute(combine_sym, cudaFuncAttributeMaxDynamicSharedMemorySize, COMB_SMEM);

    // Launch order keeps gemm_sym_k at index 3 (the slot ncu captures).
    prep_x<<<dim3(N_ / 64, C_ / 32, B_), 256>>>(x, Xhi, Xlo, XTh, rp);               // 0
    reduce_r<<<B_ * C_ / 8, 256>>>(rp, r);                                           // 1
    split_qk<<<256, 256>>>(Wq, Wk, Wqhi, Wqlo, Wkhi, Wklo, CC / 4);                  // 2

    // G = X X^T, symmetric upper-triangle, split-K=NSPLIT -> fp32 partials
    gemm_sym_k<<<dim3(10, NSPLIT, B_), NT, GEMM_SMEM>>>(Xhi, Xlo, P);                // 3

    combine_sym<<<10 * B_, 256, COMB_SMEM>>>(P, Ghi, Glo);                           // 4
    transpose_cvt_h<<<dim3(C_ / 32, C_ / 32), 256>>>(Wv, WvTh, C_, C_);              // 5
    matvec_qk_kernel<<<dim3(C_ / 8, B_), 256>>>(Wq, Wk, r, qr, kr);                  // 6

    // T1 = Wq G (bf16 3-term)
    gemm_mma<1><<<dim3(4, 4, B_), NT, GEMM_SMEM>>>(
        Wqhi, Wqlo, C_, 0,  Ghi, Glo, C_, CC,
        nullptr, T1hi, T1lo, C_, CC, C_);

    // S = T1 Wk^T (bf16 3-term, fp32 out)
    gemm_mma<0><<<dim3(4, 4, B_), NT, GEMM_SMEM>>>(
        T1hi, T1lo, C_, CC,  Wkhi, Wklo, C_, 0,
        S, nullptr, nullptr, C_, CC, C_);

    // softmax(+rank-1 corrections) -> attn fp16 hi/lo, beta = attn bv
    softmax_beta_kernel<<<B_ * C_, 256>>>(S, qr, kr, bq, bk, bv, ATh, ATl, beta);

    // Mv = (ATh+ATl) WvTh^T (fp16 2-term) -> fp16 hi/lo
    gemm_mv<<<dim3(4, 4, B_), NT, MV_SMEM>>>(ATh, ATl, WvTh, Mvh, Mvl);

    // out = (Mvh+Mvl) XTh^T + beta  (fp16 2-term, wide CTA 128x256)
    gemm_out<<<dim3(16, 4, B_), NT, GEMM_SMEM>>>(Mvh, Mvl, XTh, out, beta);
}

// round 16
// speedup vs baseline: 1.3000x; 1.0330x over previous
#include <cuda_runtime.h>
#include <cuda_bf16.h>
#include <cuda_fp16.h>
#include <math.h>
#include <stdint.h>

#define B_ 16
#define C_ 512
#define N_ 4096
#define NSPLIT 8

// ---------------------------------------------------------------------------
// Scratch (device globals; allocation in kernel_launch is forbidden)
// ---------------------------------------------------------------------------
__device__ __align__(1024) __half        g_Xh  [(size_t)B_ * C_ * N_];
__device__ __align__(1024) __half        g_Xl  [(size_t)B_ * C_ * N_];
__device__ __align__(1024) __nv_bfloat16 g_Ghi [B_ * C_ * C_], g_Glo [B_ * C_ * C_];
__device__ __align__(1024) __nv_bfloat16 g_T1hi[B_ * C_ * C_], g_T1lo[B_ * C_ * C_];
__device__ __align__(1024) __half        g_ATh [B_ * C_ * C_], g_ATl [B_ * C_ * C_];
__device__ __align__(1024) __half        g_Mvh [B_ * C_ * C_], g_Mvl [B_ * C_ * C_];
__device__ __align__(1024) __nv_bfloat16 g_Wqhi[C_ * C_], g_Wqlo[C_ * C_];
__device__ __align__(1024) __nv_bfloat16 g_Wkhi[C_ * C_], g_Wklo[C_ * C_];
__device__ __align__(1024) __half        g_WvTh[C_ * C_];
__device__ float g_S[B_ * C_ * C_];
__device__ __align__(1024) float g_P[(size_t)B_ * 10 * NSPLIT * 16384];   // split-K partials
__device__ float g_rp[(size_t)B_ * C_ * 64];
__device__ float g_r[B_ * C_], g_qr[B_ * C_], g_kr[B_ * C_], g_beta[B_ * C_];

__device__ __constant__ int c_ti[10] = {0,0,0,0,1,1,1,2,2,3};
__device__ __constant__ int c_tj[10] = {0,1,2,3,1,2,3,2,3,3};

// ---------------------------------------------------------------------------
// Helpers
// ---------------------------------------------------------------------------
__device__ __forceinline__ uint32_t smem_u32(const void* p) {
    uint32_t a;
    asm("{ .reg .u64 t; cvta.to.shared.u64 t, %1; cvt.u32.u64 %0, t; }" : "=r"(a) : "l"(p));
    return a;
}
__device__ __forceinline__ uint32_t sw128(uint32_t off) { return off ^ ((off >> 3) & 0x70); }

__device__ __forceinline__ uint32_t cvt2(float lo, float hi) {
    uint32_t r; asm("cvt.rn.bf16x2.f32 %0, %1, %2;" : "=r"(r) : "f"(hi), "f"(lo)); return r;
}
__device__ __forceinline__ float lof(uint32_t h) { return __uint_as_float(h << 16); }
__device__ __forceinline__ float hif(uint32_t h) { return __uint_as_float(h & 0xFFFF0000u); }

#define CP_ASYNC16(dst, src) \
    asm volatile("cp.async.cg.shared.global [%0], [%1], 16;" :: "r"(dst), "l"(src))
#define CP_COMMIT() asm volatile("cp.async.commit_group;")
#define CP_WAIT0()  asm volatile("cp.async.wait_group 0;")
#define CP_WAIT1()  asm volatile("cp.async.wait_group 1;")

#define LDSM4(r0, r1, r2, r3, addr) \
    asm volatile("ldmatrix.sync.aligned.m8n8.x4.shared.b16 {%0,%1,%2,%3}, [%4];" \
                 : "=r"(r0), "=r"(r1), "=r"(r2), "=r"(r3) : "r"(addr))

#define LDSM4T(r0, r1, r2, r3, addr) \
    asm volatile("ldmatrix.sync.aligned.m8n8.x4.trans.shared.b16 {%0,%1,%2,%3}, [%4];" \
                 : "=r"(r0), "=r"(r1), "=r"(r2), "=r"(r3) : "r"(addr))

#define MMA16816(c, a, b) \
    asm volatile("mma.sync.aligned.m16n8k16.row.col.f32.bf16.bf16.f32 " \
                 "{%0,%1,%2,%3},{%4,%5,%6,%7},{%8,%9},{%0,%1,%2,%3};" \
                 : "+f"((c)[0]), "+f"((c)[1]), "+f"((c)[2]), "+f"((c)[3]) \
                 : "r"((a)[0]), "r"((a)[1]), "r"((a)[2]), "r"((a)[3]), \
                   "r"((b)[0]), "r"((b)[1]))

#define MMA16816H(c, a, b) \
    asm volatile("mma.sync.aligned.m16n8k16.row.col.f32.f16.f16.f32 " \
                 "{%0,%1,%2,%3},{%4,%5,%6,%7},{%8,%9},{%0,%1,%2,%3};" \
                 : "+f"((c)[0]), "+f"((c)[1]), "+f"((c)[2]), "+f"((c)[3]) \
                 : "r"((a)[0]), "r"((a)[1]), "r"((a)[2]), "r"((a)[3]), \
                   "r"((b)[0]), "r"((b)[1]))

#define GEMM_SMEM 196608    // 3 x 64KB (bf16 3-term core, fp16 sym core, wide out core)
#define MV_SMEM   147456    // fp16 2-term 128x128 core: 3 x 48KB
#define NT 512

// ---------------------------------------------------------------------------
// bf16 3-term GEMM mainloop (measured-best): CTA 128x128, warp 32x32, BK=64,
// 3-stage cp.async, prefetch-before-compute, A-lo reloads into A-hi regs.
// ---------------------------------------------------------------------------
__device__ __forceinline__ void gemm_core(
    const __nv_bfloat16* __restrict__ Ah, const __nv_bfloat16* __restrict__ Al, int lda,
    const __nv_bfloat16* __restrict__ Bh, const __nv_bfloat16* __restrict__ Bl, int ldb,
    int K, uint32_t sb, int tid, int wid, int lane, float acc[2][4][4]) {

    #pragma unroll
    for (int mi = 0; mi < 2; ++mi)
        #pragma unroll
        for (int ni = 0; ni < 4; ++ni)
            #pragma unroll
            for (int e = 0; e < 4; ++e) acc[mi][ni][e] = 0.f;

    const int nit = K >> 6;

    auto load_stage = [&](int s, int k0) {
        const uint32_t S = sb + (uint32_t)s * 65536u;
        #pragma unroll
        for (int j = 0; j < 2; ++j) {
            const int id = tid + NT * j;
            const int row = id >> 3;
            const int c = id & 7;
            const uint32_t off = sw128((uint32_t)row * 128u + (uint32_t)c * 16u);
            const size_t ga = (size_t)row * lda + k0 + c * 8;
            const size_t gb = (size_t)row * ldb + k0 + c * 8;
            CP_ASYNC16(S + off,          Ah + ga);
            CP_ASYNC16(S + 16384 + off,  Al + ga);
            CP_ASYNC16(S + 32768 + off,  Bh + gb);
            CP_ASYNC16(S + 49152 + off,  Bl + gb);
        }
    };

    load_stage(0, 0);
    CP_COMMIT();
    if (nit > 1) { load_stage(1, 64); }
    CP_COMMIT();

    const int m0l = (wid & 3) * 32;
    const int n0l = (wid >> 2) * 32;

    int s = 0;
    for (int it = 0; it < nit; ++it) {
        if (it + 1 < nit) { CP_WAIT1(); } else { CP_WAIT0(); }
        __syncthreads();
        {
            int s2 = s + 2; if (s2 >= 3) s2 -= 3;
            if (it + 2 < nit) load_stage(s2, (it + 2) * 64);
            CP_COMMIT();
        }
        const uint32_t Sa = sb + (uint32_t)s * 65536u;
        const uint32_t Sb = Sa + 32768;

        #pragma unroll
        for (int ks = 0; ks < 4; ++ks) {
            const uint32_t kb = (uint32_t)ks * 32u;
            uint32_t af[2][4];
            uint32_t aaddr[2];
            #pragma unroll
            for (int mi = 0; mi < 2; ++mi) {
                aaddr[mi] = Sa + sw128(
                    (uint32_t)(m0l + mi * 16 + (lane & 15)) * 128u + kb + (uint32_t)(lane >> 4) * 16u);
                LDSM4(af[mi][0], af[mi][1], af[mi][2], af[mi][3], aaddr[mi]);
            }
            uint32_t bh4[4][2], bl4[4][2];
            #pragma unroll
            for (int np = 0; np < 2; ++np) {
                const uint32_t bd = Sb + sw128(
                    (uint32_t)(n0l + np * 16 + (lane >> 4) * 8 + (lane & 7)) * 128u +
                    kb + (uint32_t)((lane >> 3) & 1) * 16u);
                uint32_t r0, r1, r2, r3;
                LDSM4(r0, r1, r2, r3, bd);
                bh4[np * 2][0] = r0; bh4[np * 2][1] = r1;
                bh4[np * 2 + 1][0] = r2; bh4[np * 2 + 1][1] = r3;
                LDSM4(r0, r1, r2, r3, bd + 16384);
                bl4[np * 2][0] = r0; bl4[np * 2][1] = r1;
                bl4[np * 2 + 1][0] = r2; bl4[np * 2 + 1][1] = r3;
            }
            #pragma unroll
            for (int mi = 0; mi < 2; ++mi)
                #pragma unroll
                for (int ni = 0; ni < 4; ++ni) {
                    MMA16816(acc[mi][ni], af[mi], bh4[ni]);
                    MMA16816(acc[mi][ni], af[mi], bl4[ni]);
                }
            #pragma unroll
            for (int mi = 0; mi < 2; ++mi)
                LDSM4(af[mi][0], af[mi][1], af[mi][2], af[mi][3], aaddr[mi] + 16384);
            #pragma unroll
            for (int mi = 0; mi < 2; ++mi)
                #pragma unroll
                for (int ni = 0; ni < 4; ++ni)
                    MMA16816(acc[mi][ni], af[mi], bh4[ni]);
        }
        if (++s == 3) s = 0;
    }
}

// ---------------------------------------------------------------------------
// fp16 3-term GEMM mainloop for sym_k (identical structure, fp16 operands)
// ---------------------------------------------------------------------------
__device__ __forceinline__ void gemm_core_h(
    const __half* __restrict__ Ah, const __half* __restrict__ Al, int lda,
    const __half* __restrict__ Bh, const __half* __restrict__ Bl, int ldb,
    int K, uint32_t sb, int tid, int wid, int lane, float acc[2][4][4]) {

    #pragma unroll
    for (int mi = 0; mi < 2; ++mi)
        #pragma unroll
        for (int ni = 0; ni < 4; ++ni)
            #pragma unroll
            for (int e = 0; e < 4; ++e) acc[mi][ni][e] = 0.f;

    const int nit = K >> 6;

    auto load_stage = [&](int s, int k0) {
        const uint32_t S = sb + (uint32_t)s * 65536u;
        #pragma unroll
        for (int j = 0; j < 2; ++j) {
            const int id = tid + NT * j;
            const int row = id >> 3;
            const int c = id & 7;
            const uint32_t off = sw128((uint32_t)row * 128u + (uint32_t)c * 16u);
            const size_t ga = (size_t)row * lda + k0 + c * 8;
            const size_t gb = (size_t)row * ldb + k0 + c * 8;
            CP_ASYNC16(S + off,          Ah + ga);
            CP_ASYNC16(S + 16384 + off,  Al + ga);
            CP_ASYNC16(S + 32768 + off,  Bh + gb);
            CP_ASYNC16(S + 49152 + off,  Bl + gb);
        }
    };

    load_stage(0, 0);
    CP_COMMIT();
    if (nit > 1) { load_stage(1, 64); }
    CP_COMMIT();

    const int m0l = (wid & 3) * 32;
    const int n0l = (wid >> 2) * 32;

    int s = 0;
    for (int it = 0; it < nit; ++it) {
        if (it + 1 < nit) { CP_WAIT1(); } else { CP_WAIT0(); }
        __syncthreads();
        {
            int s2 = s + 2; if (s2 >= 3) s2 -= 3;
            if (it + 2 < nit) load_stage(s2, (it + 2) * 64);
            CP_COMMIT();
        }
        const uint32_t Sa = sb + (uint32_t)s * 65536u;
        const uint32_t Sb = Sa + 32768;

        #pragma unroll
        for (int ks = 0; ks < 4; ++ks) {
            const uint32_t kb = (uint32_t)ks * 32u;
            uint32_t af[2][4];
            uint32_t aaddr[2];
            #pragma unroll
            for (int mi = 0; mi < 2; ++mi) {
                aaddr[mi] = Sa + sw128(
                    (uint32_t)(m0l + mi * 16 + (lane & 15)) * 128u + kb + (uint32_t)(lane >> 4) * 16u);
                LDSM4(af[mi][0], af[mi][1], af[mi][2], af[mi][3], aaddr[mi]);
            }
            uint32_t bh4[4][2], bl4[4][2];
            #pragma unroll
            for (int np = 0; np < 2; ++np) {
                const uint32_t bd = Sb + sw128(
                    (uint32_t)(n0l + np * 16 + (lane >> 4) * 8 + (lane & 7)) * 128u +
                    kb + (uint32_t)((lane >> 3) & 1) * 16u);
                uint32_t r0, r1, r2, r3;
                LDSM4(r0, r1, r2, r3, bd);
                bh4[np * 2][0] = r0; bh4[np * 2][1] = r1;
                bh4[np * 2 + 1][0] = r2; bh4[np * 2 + 1][1] = r3;
                LDSM4(r0, r1, r2, r3, bd + 16384);
                bl4[np * 2][0] = r0; bl4[np * 2][1] = r1;
                bl4[np * 2 + 1][0] = r2; bl4[np * 2 + 1][1] = r3;
            }
            #pragma unroll
            for (int mi = 0; mi < 2; ++mi)
                #pragma unroll
                for (int ni = 0; ni < 4; ++ni) {
                    MMA16816H(acc[mi][ni], af[mi], bh4[ni]);
                    MMA16816H(acc[mi][ni], af[mi], bl4[ni]);
                }
            #pragma unroll
            for (int mi = 0; mi < 2; ++mi)
                LDSM4(af[mi][0], af[mi][1], af[mi][2], af[mi][3], aaddr[mi] + 16384);
            #pragma unroll
            for (int mi = 0; mi < 2; ++mi)
                #pragma unroll
                for (int ni = 0; ni < 4; ++ni)
                    MMA16816H(acc[mi][ni], af[mi], bh4[ni]);
        }
        if (++s == 3) s = 0;
    }
}

// ---------------------------------------------------------------------------
// General bf16 HMMA GEMM. OM: 0 fp32 out, 1 bf16 hi/lo out.
// ---------------------------------------------------------------------------
template <int OM>
__global__ void __launch_bounds__(NT, 1)
gemm_mma(const __nv_bfloat16* __restrict__ Ahi, const __nv_bfloat16* __restrict__ Alo,
         int lda, long long sA,
         const __nv_bfloat16* __restrict__ Bhi, const __nv_bfloat16* __restrict__ Blo,
         int ldb, long long sB,
         float* __restrict__ Cf, __nv_bfloat16* __restrict__ Chi,
         __nv_bfloat16* __restrict__ Clo, int ldc, long long sC, int K) {
    extern __shared__ char smem[];
    const uint32_t sb = smem_u32(smem);
    const int tid = threadIdx.x;
    const int wid = tid >> 5;
    const int lane = tid & 31;
    const int bz = blockIdx.z;
    const int bm = blockIdx.y * 128;
    const int bn = blockIdx.x * 128;

    float acc[2][4][4];
    gemm_core(Ahi + (size_t)bz * sA + (size_t)bm * lda,
              Alo + (size_t)bz * sA + (size_t)bm * lda, lda,
              Bhi + (size_t)bz * sB + (size_t)bn * ldb,
              Blo + (size_t)bz * sB + (size_t)bn * ldb, ldb,
              K, sb, tid, wid, lane, acc);

    float* Cfb = Cf ? (Cf + (size_t)bz * sC) : nullptr;
    __nv_bfloat16* Chb = Chi ? (Chi + (size_t)bz * sC) : nullptr;
    __nv_bfloat16* Clb = Clo ? (Clo + (size_t)bz * sC) : nullptr;

    const int m0l = (wid & 3) * 32;
    const int n0l = (wid >> 2) * 32;

    #pragma unroll
    for (int mi = 0; mi < 2; ++mi) {
        #pragma unroll
        for (int h = 0; h < 2; ++h) {
            const int row = bm + m0l + mi * 16 + (lane >> 2) + h * 8;
            #pragma unroll
            for (int ni = 0; ni < 4; ++ni) {
                const int col = bn + n0l + ni * 8 + (lane & 3) * 2;
                const float v0 = acc[mi][ni][h * 2 + 0];
                const float v1 = acc[mi][ni][h * 2 + 1];
                if (OM == 1) {
                    const uint32_t hh = cvt2(v0, v1);
                    const uint32_t ll = cvt2(v0 - lof(hh), v1 - hif(hh));
                    *(uint32_t*)(Chb + (size_t)row * ldc + col) = hh;
                    *(uint32_t*)(Clb + (size_t)row * ldc + col) = ll;
                } else {
                    float2 v; v.x = v0; v.y = v1;
                    *(float2*)(Cfb + (size_t)row * ldc + col) = v;
                }
            }
        }
    }
}

// ---------------------------------------------------------------------------
// fp16 2-term Mv GEMM: Mv = (ATh+ATl) * WvTh^T, fp16 hi/lo out.
// ---------------------------------------------------------------------------
__global__ void __launch_bounds__(NT, 1)
gemm_mv(const __half* __restrict__ Ahi, const __half* __restrict__ Alo,
        const __half* __restrict__ Bh,
        __half* __restrict__ Ch, __half* __restrict__ Cl) {
    extern __shared__ char smem[];
    const uint32_t sb = smem_u32(smem);
    const int tid = threadIdx.x;
    const int wid = tid >> 5;
    const int lane = tid & 31;
    const int bz = blockIdx.z;
    const int bm = blockIdx.y * 128;
    const int bn = blockIdx.x * 128;

    const __half* Ah = Ahi + (size_t)bz * (C_ * C_) + (size_t)bm * C_;
    const __half* Al = Alo + (size_t)bz * (C_ * C_) + (size_t)bm * C_;
    const __half* Bp = Bh + (size_t)bn * C_;

    float acc[2][4][4];
    #pragma unroll
    for (int mi = 0; mi < 2; ++mi)
        #pragma unroll
        for (int ni = 0; ni < 4; ++ni)
            #pragma unroll
            for (int e = 0; e < 4; ++e) acc[mi][ni][e] = 0.f;

    const int nit = C_ >> 6;

    auto load_stage = [&](int s, int k0) {
        const uint32_t S = sb + (uint32_t)s * 49152u;
        #pragma unroll
        for (int j = 0; j < 2; ++j) {
            const int id = tid + NT * j;
            const int row = id >> 3;
            const int c = id & 7;
            const uint32_t off = sw128((uint32_t)row * 128u + (uint32_t)c * 16u);
            const size_t ga = (size_t)row * C_ + k0 + c * 8;
            CP_ASYNC16(S + off,          Ah + ga);
            CP_ASYNC16(S + 16384 + off,  Al + ga);
            CP_ASYNC16(S + 32768 + off,  Bp + ga);
        }
    };

    load_stage(0, 0); CP_COMMIT();
    load_stage(1, 64); CP_COMMIT();

    const int m0l = (wid & 3) * 32;
    const int n0l = (wid >> 2) * 32;

    int s = 0;
    for (int it = 0; it < nit; ++it) {
        if (it + 1 < nit) { CP_WAIT1(); } else { CP_WAIT0(); }
        __syncthreads();
        {
            int s2 = s + 2; if (s2 >= 3) s2 -= 3;
            if (it + 2 < nit) load_stage(s2, (it + 2) * 64);
            CP_COMMIT();
        }
        const uint32_t Sa = sb + (uint32_t)s * 49152u;
        const uint32_t Sb = Sa + 32768u;

        #pragma unroll
        for (int ks = 0; ks < 4; ++ks) {
            const uint32_t kb = (uint32_t)ks * 32u;
            uint32_t ah[2][4];
            uint32_t aad[2];
            #pragma unroll
            for (int mi = 0; mi < 2; ++mi) {
                aad[mi] = Sa + sw128(
                    (uint32_t)(m0l + mi * 16 + (lane & 15)) * 128u + kb + (uint32_t)(lane >> 4) * 16u);
                LDSM4(ah[mi][0], ah[mi][1], ah[mi][2], ah[mi][3], aad[mi]);
            }
            uint32_t bh4[4][2];
            #pragma unroll
            for (int np = 0; np < 2; ++np) {
                const uint32_t bd = Sb + sw128(
                    (uint32_t)(n0l + np * 16 + (lane >> 4) * 8 + (lane & 7)) * 128u +
                    kb + (uint32_t)((lane >> 3) & 1) * 16u);
                uint32_t r0, r1, r2, r3;
                LDSM4(r0, r1, r2, r3, bd);
                bh4[np * 2][0] = r0; bh4[np * 2][1] = r1;
                bh4[np * 2 + 1][0] = r2; bh4[np * 2 + 1][1] = r3;
            }
            #pragma unroll
            for (int mi = 0; mi < 2; ++mi)
                #pragma unroll
                for (int ni = 0; ni < 4; ++ni)
                    MMA16816H(acc[mi][ni], ah[mi], bh4[ni]);
            #pragma unroll
            for (int mi = 0; mi < 2; ++mi)
                LDSM4(ah[mi][0], ah[mi][1], ah[mi][2], ah[mi][3], aad[mi] + 16384);
            #pragma unroll
            for (int mi = 0; mi < 2; ++mi)
                #pragma unroll
                for (int ni = 0; ni < 4; ++ni)
                    MMA16816H(acc[mi][ni], ah[mi], bh4[ni]);
        }
        if (++s == 3) s = 0;
    }

    __half* Chb = Ch + (size_t)bz * (C_ * C_);
    __half* Clb = Cl + (size_t)bz * (C_ * C_);
    #pragma unroll
    for (int mi = 0; mi < 2; ++mi)
        #pragma unroll
        for (int h = 0; h < 2; ++h) {
            const int row = bm + m0l + mi * 16 + (lane >> 2) + h * 8;
            #pragma unroll
            for (int ni = 0; ni < 4; ++ni) {
                const int col = bn + n0l + ni * 8 + (lane & 3) * 2;
                const float v0 = acc[mi][ni][h * 2 + 0];
                const float v1 = acc[mi][ni][h * 2 + 1];
                const __half2 h2 = __floats2half2_rn(v0, v1);
                const float2 hf = __half22float2(h2);
                const __half2 l2 = __floats2half2_rn(v0 - hf.x, v1 - hf.y);
                *(uint32_t*)(Chb + (size_t)row * C_ + col) = *(const uint32_t*)&h2;
                *(uint32_t*)(Clb + (size_t)row * C_ + col) = *(const uint32_t*)&l2;
            }
        }
}

// ---------------------------------------------------------------------------
// fp16 2-term WIDE out-GEMM with trans-B from native X layout:
// D = (Mvh+Mvl) * Xh + bias.  CTA 128x256, 16 warps of 32x64, BK=64.
// B tile = X[k0..k0+63][bn..bn+255] stored k-as-row (512B rows), XOR swizzle
// chunk^= (c&7); fragments via ldmatrix.x4.trans. Stage 64KB, 3 stages.
// ---------------------------------------------------------------------------
__global__ void __launch_bounds__(NT, 1)
gemm_out(const __half* __restrict__ Ahi, const __half* __restrict__ Alo,
         const __half* __restrict__ Xh,
         float* __restrict__ Cf, const float* __restrict__ bias) {
    extern __shared__ char smem[];
    const uint32_t sb = smem_u32(smem);
    const int tid = threadIdx.x;
    const int wid = tid >> 5;
    const int lane = tid & 31;
    const int bz = blockIdx.z;
    const int bm = blockIdx.y * 128;
    const int bn = blockIdx.x * 256;

    const __half* Ah = Ahi + (size_t)bz * (C_ * C_) + (size_t)bm * C_;
    const __half* Al = Alo + (size_t)bz * (C_ * C_) + (size_t)bm * C_;
    const __half* Xp = Xh + (size_t)bz * ((size_t)C_ * N_) + bn;

    float acc[2][8][4];
    #pragma unroll
    for (int mi = 0; mi < 2; ++mi)
        #pragma unroll
        for (int ni = 0; ni < 8; ++ni)
            #pragma unroll
            for (int e = 0; e < 4; ++e) acc[mi][ni][e] = 0.f;

    const int nit = C_ >> 6;   // 8

    auto load_stage = [&](int s, int k0) {
        const uint32_t S = sb + (uint32_t)s * 65536u;
        // A: 2 planes x 128 rows x 8 chunks = 2048 (16KB + 16KB)
        #pragma unroll
        for (int j = 0; j < 4; ++j) {
            const int id = tid + NT * j;
            const int plane = id >> 10;
            const int row = (id >> 3) & 127;
            const int c = id & 7;
            const uint32_t off = sw128((uint32_t)row * 128u + (uint32_t)c * 16u)
                               + (uint32_t)plane * 16384u;
            const __half* src = (plane ? Al : Ah) + (size_t)row * C_ + k0 + c * 8;
            CP_ASYNC16(S + off, src);
        }
        // B: X rows (c) k0..k0+63, 512B per row = 32 chunks; chunk ^= (c&7)
        #pragma unroll
        for (int j = 0; j < 4; ++j) {
            const int id = tid + NT * j;          // 0..2047
            const int c = id >> 5;                // 0..63
            const int ch = id & 31;
            const uint32_t sc = (uint32_t)(ch ^ (c & 7));
            const uint32_t off = 32768u + (uint32_t)c * 512u + sc * 16u;
            CP_ASYNC16(S + off, Xp + (size_t)(k0 + c) * N_ + ch * 8);
        }
    };

    load_stage(0, 0); CP_COMMIT();
    load_stage(1, 64); CP_COMMIT();

    const int m0l = (wid & 3) * 32;
    const int n0l = (wid >> 2) * 64;

    int s = 0;
    for (int it = 0; it < nit; ++it) {
        if (it + 1 < nit) { CP_WAIT1(); } else { CP_WAIT0(); }
        __syncthreads();
        {
            int s2 = s + 2; if (s2 >= 3) s2 -= 3;
            if (it + 2 < nit) load_stage(s2, (it + 2) * 64);
            CP_COMMIT();
        }
        const uint32_t Sa = sb + (uint32_t)s * 65536u;
        const uint32_t Sb = Sa + 32768u;

        #pragma unroll
        for (int ks = 0; ks < 4; ++ks) {
            const uint32_t kb = (uint32_t)ks * 32u;      // A: k16 byte offset
            uint32_t ah[2][4];
            uint32_t aad[2];
            #pragma unroll
            for (int mi = 0; mi < 2; ++mi) {
                aad[mi] = Sa + sw128(
                    (uint32_t)(m0l + mi * 16 + (lane & 15)) * 128u + kb + (uint32_t)(lane >> 4) * 16u);
                LDSM4(ah[mi][0], ah[mi][1], ah[mi][2], ah[mi][3], aad[mi]);
            }
            // B via trans: blocks (k8 x n8); lane l: c-row = ks*16 + (l&7) + ((l>>3)&1)*8,
            // n = n0l + np*16 + ((l>>4)&1)*8; chunk = n/8 ^ (c&7)
            uint32_t bh4[8][2];
            const int crow = ks * 16 + (lane & 7) + ((lane >> 3) & 1) * 8;
            #pragma unroll
            for (int np = 0; np < 4; ++np) {
                const int n = n0l + np * 16 + ((lane >> 4) & 1) * 8;
                const uint32_t bd = Sb + (uint32_t)crow * 512u +
                    (uint32_t)((n >> 3) ^ (crow & 7)) * 16u;
                uint32_t r0, r1, r2, r3;
                LDSM4T(r0, r1, r2, r3, bd);
                bh4[np * 2][0] = r0; bh4[np * 2][1] = r1;
                bh4[np * 2 + 1][0] = r2; bh4[np * 2 + 1][1] = r3;
            }
            #pragma unroll
            for (int mi = 0; mi < 2; ++mi)
                #pragma unroll
                for (int ni = 0; ni < 8; ++ni)
                    MMA16816H(acc[mi][ni], ah[mi], bh4[ni]);
            #pragma unroll
            for (int mi = 0; mi < 2; ++mi)
                LDSM4(ah[mi][0], ah[mi][1], ah[mi][2], ah[mi][3], aad[mi] + 16384);
            #pragma unroll
            for (int mi = 0; mi < 2; ++mi)
                #pragma unroll
                for (int ni = 0; ni < 8; ++ni)
                    MMA16816H(acc[mi][ni], ah[mi], bh4[ni]);
        }
        if (++s == 3) s = 0;
    }

    float* Cfb = Cf + (size_t)bz * ((size_t)C_ * N_);
    #pragma unroll
    for (int mi = 0; mi < 2; ++mi) {
        #pragma unroll
        for (int h = 0; h < 2; ++h) {
            const int row = bm + m0l + mi * 16 + (lane >> 2) + h * 8;
            const float bb = bias[bz * C_ + row];
            #pragma unroll
            for (int ni = 0; ni < 8; ++ni) {
                const int col = bn + n0l + ni * 8 + (lane & 3) * 2;
                float2 v;
                v.x = acc[mi][ni][h * 2 + 0] + bb;
                v.y = acc[mi][ni][h * 2 + 1] + bb;
                *(float2*)(Cfb + (size_t)row * N_ + col) = v;
            }
        }
    }
}

// ---------------------------------------------------------------------------
// Split-K symmetric GEMM stage 1 (fp16 X planes). Grid (10, NSPLIT, B_).
// ---------------------------------------------------------------------------
__global__ void __launch_bounds__(NT, 1)
gemm_sym_k(const __half* __restrict__ Xh, const __half* __restrict__ Xl,
           float* __restrict__ P) {
    extern __shared__ char smem[];
    const uint32_t sb = smem_u32(smem);
    const int tid = threadIdx.x;
    const int wid = tid >> 5;
    const int lane = tid & 31;
    const int bz = blockIdx.z;
    const int split = blockIdx.y;
    const int ti = c_ti[blockIdx.x];
    const int tj = c_tj[blockIdx.x];
    const int bm = ti * 128;
    const int bn = tj * 128;
    const int k0 = split * (N_ / NSPLIT);

    const size_t xb = (size_t)bz * ((size_t)C_ * N_);
    float acc[2][4][4];
    gemm_core_h(Xh + xb + (size_t)bm * N_ + k0, Xl + xb + (size_t)bm * N_ + k0, N_,
                Xh + xb + (size_t)bn * N_ + k0, Xl + xb + (size_t)bn * N_ + k0, N_,
                N_ / NSPLIT, sb, tid, wid, lane, acc);

    float* Pt = P + (((size_t)bz * 10 + blockIdx.x) * NSPLIT + split) * 16384;
    const int m0l = (wid & 3) * 32;
    const int n0l = (wid >> 2) * 32;

    #pragma unroll
    for (int mi = 0; mi < 2; ++mi)
        #pragma unroll
        for (int h = 0; h < 2; ++h) {
            const int row = m0l + mi * 16 + (lane >> 2) + h * 8;
            #pragma unroll
            for (int ni = 0; ni < 4; ++ni) {
                const int col = n0l + ni * 8 + (lane & 3) * 2;
                float2 v;
                v.x = acc[mi][ni][h * 2 + 0];
                v.y = acc[mi][ni][h * 2 + 1];
                *(float2*)(Pt + row * 128 + col) = v;
            }
        }
}

// ---------------------------------------------------------------------------
// Split-K combine (unchanged)
// ---------------------------------------------------------------------------
#define COMB_SMEM (128 * 132 * 4)
__global__ void __launch_bounds__(256, 1)
combine_sym(const float* __restrict__ P,
            __nv_bfloat16* __restrict__ Ghi, __nv_bfloat16* __restrict__ Glo) {
    extern __shared__ char smem[];
    float* st = (float*)smem;
    const int tid = threadIdx.x;
    const int t = blockIdx.x % 10;
    const int bz = blockIdx.x / 10;
    const int ti = c_ti[t];
    const int tj = c_tj[t];
    const int bm = ti * 128;
    const int bn = tj * 128;

    const float* Pb = P + ((size_t)bz * 10 + t) * NSPLIT * 16384;

    #pragma unroll
    for (int j = 0; j < 16; ++j) {
        const int cid = tid + 256 * j;
        const int row = cid >> 5;
        const int c4 = cid & 31;
        float4 s = *(const float4*)(Pb + cid * 4);
        #pragma unroll
        for (int sp = 1; sp < NSPLIT; ++sp) {
            const float4 a = *(const float4*)(Pb + sp * 16384 + cid * 4);
            s.x += a.x; s.y += a.y; s.z += a.z; s.w += a.w;
        }
        float* d = st + row * 132 + c4 * 4;
        d[0] = s.x; d[1] = s.y; d[2] = s.z; d[3] = s.w;
    }
    __syncthreads();

    __nv_bfloat16* Gh = Ghi + (size_t)bz * (C_ * C_);
    __nv_bfloat16* Gl = Glo + (size_t)bz * (C_ * C_);

    #pragma unroll
    for (int j = 0; j < 16; ++j) {
        const int cid = tid + 256 * j;
        const int row = cid >> 5;
        const int c4 = cid & 31;
        const float4 v = *(const float4*)(st + row * 132 + c4 * 4);
        const uint32_t h0 = cvt2(v.x, v.y), h1 = cvt2(v.z, v.w);
        const uint32_t l0 = cvt2(v.x - lof(h0), v.y - hif(h0));
        const uint32_t l1 = cvt2(v.z - lof(h1), v.w - hif(h1));
        const size_t o = (size_t)(bm + row) * C_ + bn + c4 * 4;
        *(uint2*)(Gh + o) = make_uint2(h0, h1);
        *(uint2*)(Gl + o) = make_uint2(l0, l1);
    }

    if (ti != tj) {
        #pragma unroll
        for (int j = 0; j < 16; ++j) {
            const int cid = tid + 256 * j;
            const int mr = cid >> 5;
            const int mc4 = cid & 31;
            float v0 = st[(mc4 * 4 + 0) * 132 + mr];
            float v1 = st[(mc4 * 4 + 1) * 132 + mr];
            float v2 = st[(mc4 * 4 + 2) * 132 + mr];
            float v3 = st[(mc4 * 4 + 3) * 132 + mr];
            const uint32_t h0 = cvt2(v0, v1), h1 = cvt2(v2, v3);
            const uint32_t l0 = cvt2(v0 - lof(h0), v1 - hif(h0));
            const uint32_t l1 = cvt2(v2 - lof(h1), v3 - hif(h1));
            const size_t o = (size_t)(bn + mr) * C_ + bm + mc4 * 4;
            *(uint2*)(Gh + o) = make_uint2(h0, h1);
            *(uint2*)(Gl + o) = make_uint2(l0, l1);
        }
    }
}

// ---------------------------------------------------------------------------
// X prep v4: PURE STREAMING fp32 -> fp16 hi/lo planes + row partial sums.
// No smem, no transpose. Grid (N/64, C/32, B), 256 threads.
// ---------------------------------------------------------------------------
__global__ void __launch_bounds__(256)
prep_x(const float* __restrict__ x,
       __half* __restrict__ xh, __half* __restrict__ xl, float* __restrict__ rp) {
    const int tid = threadIdx.x;
    const int b = blockIdx.z;
    const int c0 = blockIdx.y * 32;
    const int n0 = blockIdx.x * 64;
    const float* s = x + (size_t)b * C_ * N_;
    __half* xhb = xh + (size_t)b * C_ * N_;
    __half* xlb = xl + (size_t)b * C_ * N_;

    const int r8 = tid >> 5;
    const int cp = tid & 31;
    #pragma unroll
    for (int k = 0; k < 4; ++k) {
        const int cr = k * 8 + r8;
        const size_t o = (size_t)(c0 + cr) * N_ + n0 + cp * 2;
        const float2 v = *(const float2*)(s + o);
        const __half2 h2 = __floats2half2_rn(v.x, v.y);
        const float2 hf = __half22float2(h2);
        const __half2 l2 = __floats2half2_rn(v.x - hf.x, v.y - hf.y);
        *(uint32_t*)(xhb + o) = *(const uint32_t*)&h2;
        *(uint32_t*)(xlb + o) = *(const uint32_t*)&l2;
        float ps = v.x + v.y;
        #pragma unroll
        for (int off = 16; off > 0; off >>= 1)
            ps += __shfl_down_sync(0xFFFFFFFFu, ps, off);
        if (cp == 0)
            rp[((size_t)b * C_ + c0 + cr) * 64 + blockIdx.x] = ps;
    }
}

// ---------------------------------------------------------------------------
// Reduce row partials
// ---------------------------------------------------------------------------
__global__ void __launch_bounds__(256)
reduce_r(const float* __restrict__ rp, float* __restrict__ r) {
    const int row = blockIdx.x * 8 + (threadIdx.x >> 5);
    const int lane = threadIdx.x & 31;
    float s = rp[(size_t)row * 64 + lane] + rp[(size_t)row * 64 + 32 + lane];
    #pragma unroll
    for (int off = 16; off > 0; off >>= 1)
        s += __shfl_down_sync(0xFFFFFFFFu, s, off);
    if (lane == 0) r[row] = s;
}

// ---------------------------------------------------------------------------
// Fused Wq + Wk split
// ---------------------------------------------------------------------------
__global__ void __launch_bounds__(256)
split_qk(const float* __restrict__ wq, const float* __restrict__ wk,
         __nv_bfloat16* __restrict__ qhi, __nv_bfloat16* __restrict__ qlo,
         __nv_bfloat16* __restrict__ khi, __nv_bfloat16* __restrict__ klo,
         long long n4) {
    long long i = (long long)blockIdx.x * blockDim.x + threadIdx.x;
    const long long stride = (long long)gridDim.x * blockDim.x;
    for (; i < n4; i += stride) {
        float4 v = ((const float4*)wq)[i];
        uint32_t h0 = cvt2(v.x, v.y), h1 = cvt2(v.z, v.w);
        uint32_t l0 = cvt2(v.x - lof(h0), v.y - hif(h0));
        uint32_t l1 = cvt2(v.z - lof(h1), v.w - hif(h1));
        ((uint2*)qhi)[i] = make_uint2(h0, h1);
        ((uint2*)qlo)[i] = make_uint2(l0, l1);
        v = ((const float4*)wk)[i];
        h0 = cvt2(v.x, v.y); h1 = cvt2(v.z, v.w);
        l0 = cvt2(v.x - lof(h0), v.y - hif(h0));
        l1 = cvt2(v.z - lof(h1), v.w - hif(h1));
        ((uint2*)khi)[i] = make_uint2(h0, h1);
        ((uint2*)klo)[i] = make_uint2(l0, l1);
    }
}

// ---------------------------------------------------------------------------
// qr = Wq r, kr = Wk r (all batches)
// ---------------------------------------------------------------------------
__global__ void __launch_bounds__(256) matvec_qk_kernel(const float* __restrict__ Wq,
                                                        const float* __restrict__ Wk,
                                                        const float* __restrict__ r,
                                                        float* __restrict__ qr,
                                                        float* __restrict__ kr) {
    const int b = blockIdx.y;
    const int warp = threadIdx.x >> 5;
    const int lane = threadIdx.x & 31;
    const int o = blockIdx.x * 8 + warp;
    const float* rb = r + b * C_;
    float sq = 0.f, sk = 0.f;
    for (int i = lane; i < C_; i += 32) {
        float rv = rb[i];
        sq += Wq[(size_t)o * C_ + i] * rv;
        sk += Wk[(size_t)o * C_ + i] * rv;
    }
    #pragma unroll
    for (int off = 16; off > 0; off >>= 1) {
        sq += __shfl_down_sync(0xFFFFFFFFu, sq, off);
        sk += __shfl_down_sync(0xFFFFFFFFu, sk, off);
    }
    if (lane == 0) { qr[b * C_ + o] = sq; kr[b * C_ + o] = sk; }
}

// ---------------------------------------------------------------------------
// Transpose + fp16 convert (for Wv -> WvT fp16 hi plane)
// ---------------------------------------------------------------------------
__global__ void __launch_bounds__(256)
transpose_cvt_h(const float* __restrict__ s, __half* __restrict__ dh, int R, int Cc) {
    __shared__ float t[32][33];
    const int tx = threadIdx.x & 31, ty = threadIdx.x >> 5;
    const int r0 = blockIdx.y * 32, c0 = blockIdx.x * 32;
    #pragma unroll
    for (int k = 0; k < 4; ++k)
        t[ty + 8 * k][tx] = s[(size_t)(r0 + ty + 8 * k) * Cc + c0 + tx];
    __syncthreads();
    #pragma unroll
    for (int k = 0; k < 4; ++k) {
        const int i = ty + 8 * k;
        dh[(size_t)(c0 + i) * R + r0 + tx] = __float2half(t[tx][i]);
    }
}

// ---------------------------------------------------------------------------
// Softmax with rank-1 bias corrections; attn -> fp16 hi/lo planes + beta
// ---------------------------------------------------------------------------
__global__ void __launch_bounds__(256)
softmax_beta_kernel(const float* __restrict__ S,
                    const float* __restrict__ qr, const float* __restrict__ kr,
                    const float* __restrict__ bq, const float* __restrict__ bk,
                    const float* __restrict__ bv,
                    __half* __restrict__ Ahi, __half* __restrict__ Alo,
                    float* __restrict__ beta) {
    __shared__ float sm[256];
    const int row = blockIdx.x;
    const int b = row >> 9;
    const int c = row & (C_ - 1);
    const float* Sr = S + (size_t)row * C_;
    const float* krb = kr + b * C_;
    const float qrc = qr[row];
    const float bqc = bq[c];
    const float scale = rsqrtf((float)C_);
    const int t = threadIdx.x;

    float v[2];
    float mx = -1e30f;
    #pragma unroll
    for (int u = 0; u < 2; ++u) {
        const int d = t + u * 256;
        float s = (Sr[d] + qrc * bk[d] + bqc * krb[d] + (float)N_ * bqc * bk[d]) * scale;
        v[u] = s;
        mx = fmaxf(mx, s);
    }
    sm[t] = mx; __syncthreads();
    #pragma unroll
    for (int off = 128; off > 0; off >>= 1) {
        if (t < off) sm[t] = fmaxf(sm[t], sm[t + off]);
        __syncthreads();
    }
    mx = sm[0];
    __syncthreads();

    float sum = 0.f;
    #pragma unroll
    for (int u = 0; u < 2; ++u) { v[u] = expf(v[u] - mx); sum += v[u]; }
    sm[t] = sum; __syncthreads();
    #pragma unroll
    for (int off = 128; off > 0; off >>= 1) {
        if (t < off) sm[t] += sm[t + off];
        __syncthreads();
    }
    const float inv = 1.f / sm[0];
    __syncthreads();

    float bc = 0.f;
    #pragma unroll
    for (int u = 0; u < 2; ++u) {
        const int d = t + u * 256;
        const float p = v[u] * inv;
        const __half h = __float2half(p);
        const __half l = __float2half(p - __half2float(h));
        Ahi[(size_t)row * C_ + d] = h;
        Alo[(size_t)row * C_ + d] = l;
        bc += p * bv[d];
    }
    sm[t] = bc; __syncthreads();
    #pragma unroll
    for (int off = 128; off > 0; off >>= 1) {
        if (t < off) sm[t] += sm[t + off];
        __syncthreads();
    }
    if (t == 0) beta[row] = sm[0];
}

// ---------------------------------------------------------------------------
extern "C" void kernel_launch(void* const* d_in, const int* in_sizes, int n_in,
                              void* d_out, int out_size) {
    const float* x  = (const float*)d_in[0];
    const float* Wq = (const float*)d_in[1];
    const float* bq = (const float*)d_in[2];
    const float* Wk = (const float*)d_in[3];
    const float* bk = (const float*)d_in[4];
    const float* Wv = (const float*)d_in[5];
    const float* bv = (const float*)d_in[6];
    float* out = (float*)d_out;

    __nv_bfloat16 *Ghi, *Glo, *T1hi, *T1lo, *Wqhi, *Wqlo, *Wkhi, *Wklo;
    __half *Xh, *Xl, *ATh, *ATl, *Mvh, *Mvl, *WvTh;
    float *S, *P, *rp, *r, *qr, *kr, *beta;
    cudaGetSymbolAddress((void**)&Xh, g_Xh);       cudaGetSymbolAddress((void**)&Xl, g_Xl);
    cudaGetSymbolAddress((void**)&Ghi, g_Ghi);     cudaGetSymbolAddress((void**)&Glo, g_Glo);
    cudaGetSymbolAddress((void**)&T1hi, g_T1hi);   cudaGetSymbolAddress((void**)&T1lo, g_T1lo);
    cudaGetSymbolAddress((void**)&ATh, g_ATh);     cudaGetSymbolAddress((void**)&ATl, g_ATl);
    cudaGetSymbolAddress((void**)&Mvh, g_Mvh);     cudaGetSymbolAddress((void**)&Mvl, g_Mvl);
    cudaGetSymbolAddress((void**)&Wqhi, g_Wqhi);   cudaGetSymbolAddress((void**)&Wqlo, g_Wqlo);
    cudaGetSymbolAddress((void**)&Wkhi, g_Wkhi);   cudaGetSymbolAddress((void**)&Wklo, g_Wklo);
    cudaGetSymbolAddress((void**)&WvTh, g_WvTh);
    cudaGetSymbolAddress((void**)&S, g_S);         cudaGetSymbolAddress((void**)&P, g_P);
    cudaGetSymbolAddress((void**)&rp, g_rp);       cudaGetSymbolAddress((void**)&r, g_r);
    cudaGetSymbolAddress((void**)&qr, g_qr);
    cudaGetSymbolAddress((void**)&kr, g_kr); cudaGetSymbolAddress((void**)&beta, g_beta);

    const long long CC = (long long)C_ * C_;

    cudaFuncSetAttribute(gemm_mma<0>, cudaFuncAttributeMaxDynamicSharedMemorySize, GEMM_SMEM);
    cudaFuncSetAttribute(gemm_mma<1>, cudaFuncAttributeMaxDynamicSharedMemorySize, GEMM_SMEM);
    cudaFuncSetAttribute(gemm_sym_k,  cudaFuncAttributeMaxDynamicSharedMemorySize, GEMM_SMEM);
    cudaFuncSetAttribute(gemm_mv,     cudaFuncAttributeMaxDynamicSharedMemorySize, MV_SMEM);
    cudaFuncSetAttribute(gemm_out,    cudaFuncAttributeMaxDynamicSharedMemorySize, GEMM_SMEM);
    cudaFuncSetAttribute(combine_sym, cudaFuncAttributeMaxDynamicSharedMemorySize, COMB_SMEM);

    // Launch order keeps gemm_sym_k at index 3 (the slot ncu captures).
    prep_x<<<dim3(N_ / 64, C_ / 32, B_), 256>>>(x, Xh, Xl, rp);                      // 0
    reduce_r<<<B_ * C_ / 8, 256>>>(rp, r);                                           // 1
    split_qk<<<256, 256>>>(Wq, Wk, Wqhi, Wqlo, Wkhi, Wklo, CC / 4);                  // 2

    // G = X X^T, symmetric upper-triangle, split-K=NSPLIT -> fp32 partials
    gemm_sym_k<<<dim3(10, NSPLIT, B_), NT, GEMM_SMEM>>>(Xh, Xl, P);                  // 3

    combine_sym<<<10 * B_, 256, COMB_SMEM>>>(P, Ghi, Glo);                           // 4
    transpose_cvt_h<<<dim3(C_ / 32, C_ / 32), 256>>>(Wv, WvTh, C_, C_);              // 5
    matvec_qk_kernel<<<dim3(C_ / 8, B_), 256>>>(Wq, Wk, r, qr, kr);                  // 6

    // T1 = Wq G (bf16 3-term)
    gemm_mma<1><<<dim3(4, 4, B_), NT, GEMM_SMEM>>>(
        Wqhi, Wqlo, C_, 0,  Ghi, Glo, C_, CC,
        nullptr, T1hi, T1lo, C_, CC, C_);

    // S = T1 Wk^T (bf16 3-term, fp32 out)
    gemm_mma<0><<<dim3(4, 4, B_), NT, GEMM_SMEM>>>(
        T1hi, T1lo, C_, CC,  Wkhi, Wklo, C_, 0,
        S, nullptr, nullptr, C_, CC, C_);

    // softmax(+rank-1 corrections) -> attn fp16 hi/lo, beta = attn bv
    softmax_beta_kernel<<<B_ * C_, 256>>>(S, qr, kr, bq, bk, bv, ATh, ATl, beta);

    // Mv = (ATh+ATl) WvTh^T (fp16 2-term) -> fp16 hi/lo
    gemm_mv<<<dim3(4, 4, B_), NT, MV_SMEM>>>(ATh, ATl, WvTh, Mvh, Mvl);

    // out = (Mvh+Mvl) * Xh + beta  (fp16 2-term, wide CTA 128x256, trans-B)
    gemm_out<<<dim3(16, 4, B_), NT, GEMM_SMEM>>>(Mvh, Mvl, Xh, out, beta);
}

// round 17
// speedup vs baseline: 1.4785x; 1.1373x over previous
#include <cuda_runtime.h>
#include <cuda_bf16.h>
#include <cuda_fp16.h>
#include <math.h>
#include <stdint.h>

#define B_ 16
#define C_ 512
#define N_ 4096
#define NSPLIT 8

// ---------------------------------------------------------------------------
// Scratch (device globals; allocation in kernel_launch is forbidden)
// ---------------------------------------------------------------------------
__device__ __align__(1024) __half        g_Xh  [(size_t)B_ * C_ * N_];
__device__ __align__(1024) __half        g_Xl  [(size_t)B_ * C_ * N_];
__device__ __align__(1024) __nv_bfloat16 g_Ghi [B_ * C_ * C_], g_Glo [B_ * C_ * C_];
__device__ __align__(1024) __nv_bfloat16 g_T1hi[B_ * C_ * C_], g_T1lo[B_ * C_ * C_];
__device__ __align__(1024) __half        g_ATh [B_ * C_ * C_], g_ATl [B_ * C_ * C_];
__device__ __align__(1024) __half        g_Mvh [B_ * C_ * C_];
__device__ __align__(1024) __nv_bfloat16 g_Wqhi[C_ * C_], g_Wqlo[C_ * C_];
__device__ __align__(1024) __nv_bfloat16 g_Wkhi[C_ * C_], g_Wklo[C_ * C_];
__device__ __align__(1024) __half        g_WvTh[C_ * C_];
__device__ float g_S[B_ * C_ * C_];
__device__ __align__(1024) float g_P[(size_t)B_ * 10 * NSPLIT * 16384];   // split-K partials
__device__ float g_rp[(size_t)B_ * C_ * 64];
__device__ float g_r[B_ * C_], g_qr[B_ * C_], g_kr[B_ * C_], g_beta[B_ * C_];

__device__ __constant__ int c_ti[10] = {0,0,0,0,1,1,1,2,2,3};
__device__ __constant__ int c_tj[10] = {0,1,2,3,1,2,3,2,3,3};

// ---------------------------------------------------------------------------
// Helpers
// ---------------------------------------------------------------------------
__device__ __forceinline__ uint32_t smem_u32(const void* p) {
    uint32_t a;
    asm("{ .reg .u64 t; cvta.to.shared.u64 t, %1; cvt.u32.u64 %0, t; }" : "=r"(a) : "l"(p));
    return a;
}
__device__ __forceinline__ uint32_t sw128(uint32_t off) { return off ^ ((off >> 3) & 0x70); }

__device__ __forceinline__ uint32_t cvt2(float lo, float hi) {
    uint32_t r; asm("cvt.rn.bf16x2.f32 %0, %1, %2;" : "=r"(r) : "f"(hi), "f"(lo)); return r;
}
__device__ __forceinline__ float lof(uint32_t h) { return __uint_as_float(h << 16); }
__device__ __forceinline__ float hif(uint32_t h) { return __uint_as_float(h & 0xFFFF0000u); }

#define CP_ASYNC16(dst, src) \
    asm volatile("cp.async.cg.shared.global [%0], [%1], 16;" :: "r"(dst), "l"(src))
#define CP_COMMIT() asm volatile("cp.async.commit_group;")
#define CP_WAIT0()  asm volatile("cp.async.wait_group 0;")
#define CP_WAIT1()  asm volatile("cp.async.wait_group 1;")

#define LDSM4(r0, r1, r2, r3, addr) \
    asm volatile("ldmatrix.sync.aligned.m8n8.x4.shared.b16 {%0,%1,%2,%3}, [%4];" \
                 : "=r"(r0), "=r"(r1), "=r"(r2), "=r"(r3) : "r"(addr))

#define LDSM4T(r0, r1, r2, r3, addr) \
    asm volatile("ldmatrix.sync.aligned.m8n8.x4.trans.shared.b16 {%0,%1,%2,%3}, [%4];" \
                 : "=r"(r0), "=r"(r1), "=r"(r2), "=r"(r3) : "r"(addr))

#define MMA16816(c, a, b) \
    asm volatile("mma.sync.aligned.m16n8k16.row.col.f32.bf16.bf16.f32 " \
                 "{%0,%1,%2,%3},{%4,%5,%6,%7},{%8,%9},{%0,%1,%2,%3};" \
                 : "+f"((c)[0]), "+f"((c)[1]), "+f"((c)[2]), "+f"((c)[3]) \
                 : "r"((a)[0]), "r"((a)[1]), "r"((a)[2]), "r"((a)[3]), \
                   "r"((b)[0]), "r"((b)[1]))

#define MMA16816H(c, a, b) \
    asm volatile("mma.sync.aligned.m16n8k16.row.col.f32.f16.f16.f32 " \
                 "{%0,%1,%2,%3},{%4,%5,%6,%7},{%8,%9},{%0,%1,%2,%3};" \
                 : "+f"((c)[0]), "+f"((c)[1]), "+f"((c)[2]), "+f"((c)[3]) \
                 : "r"((a)[0]), "r"((a)[1]), "r"((a)[2]), "r"((a)[3]), \
                   "r"((b)[0]), "r"((b)[1]))

#define GEMM_SMEM 196608    // 3 x 64KB (3-term cores)
#define MV_SMEM   147456    // fp16 2-term 128x128 core & 1-term wide out core: 3 x 48KB
#define NT 512

// ---------------------------------------------------------------------------
// bf16 3-term GEMM mainloop (measured-best): CTA 128x128, warp 32x32, BK=64,
// 3-stage cp.async, prefetch-before-compute, A-lo reloads into A-hi regs.
// ---------------------------------------------------------------------------
__device__ __forceinline__ void gemm_core(
    const __nv_bfloat16* __restrict__ Ah, const __nv_bfloat16* __restrict__ Al, int lda,
    const __nv_bfloat16* __restrict__ Bh, const __nv_bfloat16* __restrict__ Bl, int ldb,
    int K, uint32_t sb, int tid, int wid, int lane, float acc[2][4][4]) {

    #pragma unroll
    for (int mi = 0; mi < 2; ++mi)
        #pragma unroll
        for (int ni = 0; ni < 4; ++ni)
            #pragma unroll
            for (int e = 0; e < 4; ++e) acc[mi][ni][e] = 0.f;

    const int nit = K >> 6;

    auto load_stage = [&](int s, int k0) {
        const uint32_t S = sb + (uint32_t)s * 65536u;
        #pragma unroll
        for (int j = 0; j < 2; ++j) {
            const int id = tid + NT * j;
            const int row = id >> 3;
            const int c = id & 7;
            const uint32_t off = sw128((uint32_t)row * 128u + (uint32_t)c * 16u);
            const size_t ga = (size_t)row * lda + k0 + c * 8;
            const size_t gb = (size_t)row * ldb + k0 + c * 8;
            CP_ASYNC16(S + off,          Ah + ga);
            CP_ASYNC16(S + 16384 + off,  Al + ga);
            CP_ASYNC16(S + 32768 + off,  Bh + gb);
            CP_ASYNC16(S + 49152 + off,  Bl + gb);
        }
    };

    load_stage(0, 0);
    CP_COMMIT();
    if (nit > 1) { load_stage(1, 64); }
    CP_COMMIT();

    const int m0l = (wid & 3) * 32;
    const int n0l = (wid >> 2) * 32;

    int s = 0;
    for (int it = 0; it < nit; ++it) {
        if (it + 1 < nit) { CP_WAIT1(); } else { CP_WAIT0(); }
        __syncthreads();
        {
            int s2 = s + 2; if (s2 >= 3) s2 -= 3;
            if (it + 2 < nit) load_stage(s2, (it + 2) * 64);
            CP_COMMIT();
        }
        const uint32_t Sa = sb + (uint32_t)s * 65536u;
        const uint32_t Sb = Sa + 32768;

        #pragma unroll
        for (int ks = 0; ks < 4; ++ks) {
            const uint32_t kb = (uint32_t)ks * 32u;
            uint32_t af[2][4];
            uint32_t aaddr[2];
            #pragma unroll
            for (int mi = 0; mi < 2; ++mi) {
                aaddr[mi] = Sa + sw128(
                    (uint32_t)(m0l + mi * 16 + (lane & 15)) * 128u + kb + (uint32_t)(lane >> 4) * 16u);
                LDSM4(af[mi][0], af[mi][1], af[mi][2], af[mi][3], aaddr[mi]);
            }
            uint32_t bh4[4][2], bl4[4][2];
            #pragma unroll
            for (int np = 0; np < 2; ++np) {
                const uint32_t bd = Sb + sw128(
                    (uint32_t)(n0l + np * 16 + (lane >> 4) * 8 + (lane & 7)) * 128u +
                    kb + (uint32_t)((lane >> 3) & 1) * 16u);
                uint32_t r0, r1, r2, r3;
                LDSM4(r0, r1, r2, r3, bd);
                bh4[np * 2][0] = r0; bh4[np * 2][1] = r1;
                bh4[np * 2 + 1][0] = r2; bh4[np * 2 + 1][1] = r3;
                LDSM4(r0, r1, r2, r3, bd + 16384);
                bl4[np * 2][0] = r0; bl4[np * 2][1] = r1;
                bl4[np * 2 + 1][0] = r2; bl4[np * 2 + 1][1] = r3;
            }
            #pragma unroll
            for (int mi = 0; mi < 2; ++mi)
                #pragma unroll
                for (int ni = 0; ni < 4; ++ni) {
                    MMA16816(acc[mi][ni], af[mi], bh4[ni]);
                    MMA16816(acc[mi][ni], af[mi], bl4[ni]);
                }
            #pragma unroll
            for (int mi = 0; mi < 2; ++mi)
                LDSM4(af[mi][0], af[mi][1], af[mi][2], af[mi][3], aaddr[mi] + 16384);
            #pragma unroll
            for (int mi = 0; mi < 2; ++mi)
                #pragma unroll
                for (int ni = 0; ni < 4; ++ni)
                    MMA16816(acc[mi][ni], af[mi], bh4[ni]);
        }
        if (++s == 3) s = 0;
    }
}

// ---------------------------------------------------------------------------
// fp16 3-term GEMM mainloop for sym_k (identical structure, fp16 operands)
// ---------------------------------------------------------------------------
__device__ __forceinline__ void gemm_core_h(
    const __half* __restrict__ Ah, const __half* __restrict__ Al, int lda,
    const __half* __restrict__ Bh, const __half* __restrict__ Bl, int ldb,
    int K, uint32_t sb, int tid, int wid, int lane, float acc[2][4][4]) {

    #pragma unroll
    for (int mi = 0; mi < 2; ++mi)
        #pragma unroll
        for (int ni = 0; ni < 4; ++ni)
            #pragma unroll
            for (int e = 0; e < 4; ++e) acc[mi][ni][e] = 0.f;

    const int nit = K >> 6;

    auto load_stage = [&](int s, int k0) {
        const uint32_t S = sb + (uint32_t)s * 65536u;
        #pragma unroll
        for (int j = 0; j < 2; ++j) {
            const int id = tid + NT * j;
            const int row = id >> 3;
            const int c = id & 7;
            const uint32_t off = sw128((uint32_t)row * 128u + (uint32_t)c * 16u);
            const size_t ga = (size_t)row * lda + k0 + c * 8;
            const size_t gb = (size_t)row * ldb + k0 + c * 8;
            CP_ASYNC16(S + off,          Ah + ga);
            CP_ASYNC16(S + 16384 + off,  Al + ga);
            CP_ASYNC16(S + 32768 + off,  Bh + gb);
            CP_ASYNC16(S + 49152 + off,  Bl + gb);
        }
    };

    load_stage(0, 0);
    CP_COMMIT();
    if (nit > 1) { load_stage(1, 64); }
    CP_COMMIT();

    const int m0l = (wid & 3) * 32;
    const int n0l = (wid >> 2) * 32;

    int s = 0;
    for (int it = 0; it < nit; ++it) {
        if (it + 1 < nit) { CP_WAIT1(); } else { CP_WAIT0(); }
        __syncthreads();
        {
            int s2 = s + 2; if (s2 >= 3) s2 -= 3;
            if (it + 2 < nit) load_stage(s2, (it + 2) * 64);
            CP_COMMIT();
        }
        const uint32_t Sa = sb + (uint32_t)s * 65536u;
        const uint32_t Sb = Sa + 32768;

        #pragma unroll
        for (int ks = 0; ks < 4; ++ks) {
            const uint32_t kb = (uint32_t)ks * 32u;
            uint32_t af[2][4];
            uint32_t aaddr[2];
            #pragma unroll
            for (int mi = 0; mi < 2; ++mi) {
                aaddr[mi] = Sa + sw128(
                    (uint32_t)(m0l + mi * 16 + (lane & 15)) * 128u + kb + (uint32_t)(lane >> 4) * 16u);
                LDSM4(af[mi][0], af[mi][1], af[mi][2], af[mi][3], aaddr[mi]);
            }
            uint32_t bh4[4][2], bl4[4][2];
            #pragma unroll
            for (int np = 0; np < 2; ++np) {
                const uint32_t bd = Sb + sw128(
                    (uint32_t)(n0l + np * 16 + (lane >> 4) * 8 + (lane & 7)) * 128u +
                    kb + (uint32_t)((lane >> 3) & 1) * 16u);
                uint32_t r0, r1, r2, r3;
                LDSM4(r0, r1, r2, r3, bd);
                bh4[np * 2][0] = r0; bh4[np * 2][1] = r1;
                bh4[np * 2 + 1][0] = r2; bh4[np * 2 + 1][1] = r3;
                LDSM4(r0, r1, r2, r3, bd + 16384);
                bl4[np * 2][0] = r0; bl4[np * 2][1] = r1;
                bl4[np * 2 + 1][0] = r2; bl4[np * 2 + 1][1] = r3;
            }
            #pragma unroll
            for (int mi = 0; mi < 2; ++mi)
                #pragma unroll
                for (int ni = 0; ni < 4; ++ni) {
                    MMA16816H(acc[mi][ni], af[mi], bh4[ni]);
                    MMA16816H(acc[mi][ni], af[mi], bl4[ni]);
                }
            #pragma unroll
            for (int mi = 0; mi < 2; ++mi)
                LDSM4(af[mi][0], af[mi][1], af[mi][2], af[mi][3], aaddr[mi] + 16384);
            #pragma unroll
            for (int mi = 0; mi < 2; ++mi)
                #pragma unroll
                for (int ni = 0; ni < 4; ++ni)
                    MMA16816H(acc[mi][ni], af[mi], bh4[ni]);
        }
        if (++s == 3) s = 0;
    }
}

// ---------------------------------------------------------------------------
// General bf16 HMMA GEMM. OM: 0 fp32 out, 1 bf16 hi/lo out.
// ---------------------------------------------------------------------------
template <int OM>
__global__ void __launch_bounds__(NT, 1)
gemm_mma(const __nv_bfloat16* __restrict__ Ahi, const __nv_bfloat16* __restrict__ Alo,
         int lda, long long sA,
         const __nv_bfloat16* __restrict__ Bhi, const __nv_bfloat16* __restrict__ Blo,
         int ldb, long long sB,
         float* __restrict__ Cf, __nv_bfloat16* __restrict__ Chi,
         __nv_bfloat16* __restrict__ Clo, int ldc, long long sC, int K) {
    extern __shared__ char smem[];
    const uint32_t sb = smem_u32(smem);
    const int tid = threadIdx.x;
    const int wid = tid >> 5;
    const int lane = tid & 31;
    const int bz = blockIdx.z;
    const int bm = blockIdx.y * 128;
    const int bn = blockIdx.x * 128;

    float acc[2][4][4];
    gemm_core(Ahi + (size_t)bz * sA + (size_t)bm * lda,
              Alo + (size_t)bz * sA + (size_t)bm * lda, lda,
              Bhi + (size_t)bz * sB + (size_t)bn * ldb,
              Blo + (size_t)bz * sB + (size_t)bn * ldb, ldb,
              K, sb, tid, wid, lane, acc);

    float* Cfb = Cf ? (Cf + (size_t)bz * sC) : nullptr;
    __nv_bfloat16* Chb = Chi ? (Chi + (size_t)bz * sC) : nullptr;
    __nv_bfloat16* Clb = Clo ? (Clo + (size_t)bz * sC) : nullptr;

    const int m0l = (wid & 3) * 32;
    const int n0l = (wid >> 2) * 32;

    #pragma unroll
    for (int mi = 0; mi < 2; ++mi) {
        #pragma unroll
        for (int h = 0; h < 2; ++h) {
            const int row = bm + m0l + mi * 16 + (lane >> 2) + h * 8;
            #pragma unroll
            for (int ni = 0; ni < 4; ++ni) {
                const int col = bn + n0l + ni * 8 + (lane & 3) * 2;
                const float v0 = acc[mi][ni][h * 2 + 0];
                const float v1 = acc[mi][ni][h * 2 + 1];
                if (OM == 1) {
                    const uint32_t hh = cvt2(v0, v1);
                    const uint32_t ll = cvt2(v0 - lof(hh), v1 - hif(hh));
                    *(uint32_t*)(Chb + (size_t)row * ldc + col) = hh;
                    *(uint32_t*)(Clb + (size_t)row * ldc + col) = ll;
                } else {
                    float2 v; v.x = v0; v.y = v1;
                    *(float2*)(Cfb + (size_t)row * ldc + col) = v;
                }
            }
        }
    }
}

// ---------------------------------------------------------------------------
// fp16 2-term Mv GEMM: Mv = (ATh+ATl) * WvTh^T, fp16 HI-ONLY out.
// ---------------------------------------------------------------------------
__global__ void __launch_bounds__(NT, 1)
gemm_mv(const __half* __restrict__ Ahi, const __half* __restrict__ Alo,
        const __half* __restrict__ Bh, __half* __restrict__ Ch) {
    extern __shared__ char smem[];
    const uint32_t sb = smem_u32(smem);
    const int tid = threadIdx.x;
    const int wid = tid >> 5;
    const int lane = tid & 31;
    const int bz = blockIdx.z;
    const int bm = blockIdx.y * 128;
    const int bn = blockIdx.x * 128;

    const __half* Ah = Ahi + (size_t)bz * (C_ * C_) + (size_t)bm * C_;
    const __half* Al = Alo + (size_t)bz * (C_ * C_) + (size_t)bm * C_;
    const __half* Bp = Bh + (size_t)bn * C_;

    float acc[2][4][4];
    #pragma unroll
    for (int mi = 0; mi < 2; ++mi)
        #pragma unroll
        for (int ni = 0; ni < 4; ++ni)
            #pragma unroll
            for (int e = 0; e < 4; ++e) acc[mi][ni][e] = 0.f;

    const int nit = C_ >> 6;

    auto load_stage = [&](int s, int k0) {
        const uint32_t S = sb + (uint32_t)s * 49152u;
        #pragma unroll
        for (int j = 0; j < 2; ++j) {
            const int id = tid + NT * j;
            const int row = id >> 3;
            const int c = id & 7;
            const uint32_t off = sw128((uint32_t)row * 128u + (uint32_t)c * 16u);
            const size_t ga = (size_t)row * C_ + k0 + c * 8;
            CP_ASYNC16(S + off,          Ah + ga);
            CP_ASYNC16(S + 16384 + off,  Al + ga);
            CP_ASYNC16(S + 32768 + off,  Bp + ga);
        }
    };

    load_stage(0, 0); CP_COMMIT();
    load_stage(1, 64); CP_COMMIT();

    const int m0l = (wid & 3) * 32;
    const int n0l = (wid >> 2) * 32;

    int s = 0;
    for (int it = 0; it < nit; ++it) {
        if (it + 1 < nit) { CP_WAIT1(); } else { CP_WAIT0(); }
        __syncthreads();
        {
            int s2 = s + 2; if (s2 >= 3) s2 -= 3;
            if (it + 2 < nit) load_stage(s2, (it + 2) * 64);
            CP_COMMIT();
        }
        const uint32_t Sa = sb + (uint32_t)s * 49152u;
        const uint32_t Sb = Sa + 32768u;

        #pragma unroll
        for (int ks = 0; ks < 4; ++ks) {
            const uint32_t kb = (uint32_t)ks * 32u;
            uint32_t ah[2][4];
            uint32_t aad[2];
            #pragma unroll
            for (int mi = 0; mi < 2; ++mi) {
                aad[mi] = Sa + sw128(
                    (uint32_t)(m0l + mi * 16 + (lane & 15)) * 128u + kb + (uint32_t)(lane >> 4) * 16u);
                LDSM4(ah[mi][0], ah[mi][1], ah[mi][2], ah[mi][3], aad[mi]);
            }
            uint32_t bh4[4][2];
            #pragma unroll
            for (int np = 0; np < 2; ++np) {
                const uint32_t bd = Sb + sw128(
                    (uint32_t)(n0l + np * 16 + (lane >> 4) * 8 + (lane & 7)) * 128u +
                    kb + (uint32_t)((lane >> 3) & 1) * 16u);
                uint32_t r0, r1, r2, r3;
                LDSM4(r0, r1, r2, r3, bd);
                bh4[np * 2][0] = r0; bh4[np * 2][1] = r1;
                bh4[np * 2 + 1][0] = r2; bh4[np * 2 + 1][1] = r3;
            }
            #pragma unroll
            for (int mi = 0; mi < 2; ++mi)
                #pragma unroll
                for (int ni = 0; ni < 4; ++ni)
                    MMA16816H(acc[mi][ni], ah[mi], bh4[ni]);
            #pragma unroll
            for (int mi = 0; mi < 2; ++mi)
                LDSM4(ah[mi][0], ah[mi][1], ah[mi][2], ah[mi][3], aad[mi] + 16384);
            #pragma unroll
            for (int mi = 0; mi < 2; ++mi)
                #pragma unroll
                for (int ni = 0; ni < 4; ++ni)
                    MMA16816H(acc[mi][ni], ah[mi], bh4[ni]);
        }
        if (++s == 3) s = 0;
    }

    __half* Chb = Ch + (size_t)bz * (C_ * C_);
    #pragma unroll
    for (int mi = 0; mi < 2; ++mi)
        #pragma unroll
        for (int h = 0; h < 2; ++h) {
            const int row = bm + m0l + mi * 16 + (lane >> 2) + h * 8;
            #pragma unroll
            for (int ni = 0; ni < 4; ++ni) {
                const int col = bn + n0l + ni * 8 + (lane & 3) * 2;
                const __half2 h2 = __floats2half2_rn(acc[mi][ni][h * 2 + 0],
                                                     acc[mi][ni][h * 2 + 1]);
                *(uint32_t*)(Chb + (size_t)row * C_ + col) = *(const uint32_t*)&h2;
            }
        }
}

// ---------------------------------------------------------------------------
// fp16 1-TERM WIDE out-GEMM with trans-B from native X layout:
// D = Mvh * Xh + bias.  CTA 128x256, 16 warps of 32x64, BK=64.
// Stage = A 16KB + B 32KB = 48KB, 3 stages. B rows XOR-swizzled (chunk^=(c&7)),
// fragments via ldmatrix.x4.trans.
// ---------------------------------------------------------------------------
__global__ void __launch_bounds__(NT, 1)
gemm_out(const __half* __restrict__ Ahi, const __half* __restrict__ Xh,
         float* __restrict__ Cf, const float* __restrict__ bias) {
    extern __shared__ char smem[];
    const uint32_t sb = smem_u32(smem);
    const int tid = threadIdx.x;
    const int wid = tid >> 5;
    const int lane = tid & 31;
    const int bz = blockIdx.z;
    const int bm = blockIdx.y * 128;
    const int bn = blockIdx.x * 256;

    const __half* Ah = Ahi + (size_t)bz * (C_ * C_) + (size_t)bm * C_;
    const __half* Xp = Xh + (size_t)bz * ((size_t)C_ * N_) + bn;

    float acc[2][8][4];
    #pragma unroll
    for (int mi = 0; mi < 2; ++mi)
        #pragma unroll
        for (int ni = 0; ni < 8; ++ni)
            #pragma unroll
            for (int e = 0; e < 4; ++e) acc[mi][ni][e] = 0.f;

    const int nit = C_ >> 6;   // 8

    auto load_stage = [&](int s, int k0) {
        const uint32_t S = sb + (uint32_t)s * 49152u;
        // A: 128 rows x 8 chunks = 1024 (16KB)
        #pragma unroll
        for (int j = 0; j < 2; ++j) {
            const int id = tid + NT * j;
            const int row = id >> 3;
            const int c = id & 7;
            const uint32_t off = sw128((uint32_t)row * 128u + (uint32_t)c * 16u);
            CP_ASYNC16(S + off, Ah + (size_t)row * C_ + k0 + c * 8);
        }
        // B: X rows (c) k0..k0+63, 512B per row = 32 chunks; chunk ^= (c&7)
        #pragma unroll
        for (int j = 0; j < 4; ++j) {
            const int id = tid + NT * j;          // 0..2047
            const int c = id >> 5;                // 0..63
            const int ch = id & 31;
            const uint32_t sc = (uint32_t)(ch ^ (c & 7));
            const uint32_t off = 16384u + (uint32_t)c * 512u + sc * 16u;
            CP_ASYNC16(S + off, Xp + (size_t)(k0 + c) * N_ + ch * 8);
        }
    };

    load_stage(0, 0); CP_COMMIT();
    load_stage(1, 64); CP_COMMIT();

    const int m0l = (wid & 3) * 32;
    const int n0l = (wid >> 2) * 64;

    int s = 0;
    for (int it = 0; it < nit; ++it) {
        if (it + 1 < nit) { CP_WAIT1(); } else { CP_WAIT0(); }
        __syncthreads();
        {
            int s2 = s + 2; if (s2 >= 3) s2 -= 3;
            if (it + 2 < nit) load_stage(s2, (it + 2) * 64);
            CP_COMMIT();
        }
        const uint32_t Sa = sb + (uint32_t)s * 49152u;
        const uint32_t Sb = Sa + 16384u;

        #pragma unroll
        for (int ks = 0; ks < 4; ++ks) {
            const uint32_t kb = (uint32_t)ks * 32u;
            uint32_t ah[2][4];
            #pragma unroll
            for (int mi = 0; mi < 2; ++mi) {
                const uint32_t ad = Sa + sw128(
                    (uint32_t)(m0l + mi * 16 + (lane & 15)) * 128u + kb + (uint32_t)(lane >> 4) * 16u);
                LDSM4(ah[mi][0], ah[mi][1], ah[mi][2], ah[mi][3], ad);
            }
            uint32_t bh4[8][2];
            const int crow = ks * 16 + (lane & 7) + ((lane >> 3) & 1) * 8;
            #pragma unroll
            for (int np = 0; np < 4; ++np) {
                const int n = n0l + np * 16 + ((lane >> 4) & 1) * 8;
                const uint32_t bd = Sb + (uint32_t)crow * 512u +
                    (uint32_t)((n >> 3) ^ (crow & 7)) * 16u;
                uint32_t r0, r1, r2, r3;
                LDSM4T(r0, r1, r2, r3, bd);
                bh4[np * 2][0] = r0; bh4[np * 2][1] = r1;
                bh4[np * 2 + 1][0] = r2; bh4[np * 2 + 1][1] = r3;
            }
            #pragma unroll
            for (int mi = 0; mi < 2; ++mi)
                #pragma unroll
                for (int ni = 0; ni < 8; ++ni)
                    MMA16816H(acc[mi][ni], ah[mi], bh4[ni]);
        }
        if (++s == 3) s = 0;
    }

    float* Cfb = Cf + (size_t)bz * ((size_t)C_ * N_);
    #pragma unroll
    for (int mi = 0; mi < 2; ++mi) {
        #pragma unroll
        for (int h = 0; h < 2; ++h) {
            const int row = bm + m0l + mi * 16 + (lane >> 2) + h * 8;
            const float bb = bias[bz * C_ + row];
            #pragma unroll
            for (int ni = 0; ni < 8; ++ni) {
                const int col = bn + n0l + ni * 8 + (lane & 3) * 2;
                float2 v;
                v.x = acc[mi][ni][h * 2 + 0] + bb;
                v.y = acc[mi][ni][h * 2 + 1] + bb;
                *(float2*)(Cfb + (size_t)row * N_ + col) = v;
            }
        }
    }
}

// ---------------------------------------------------------------------------
// Split-K symmetric GEMM stage 1 (fp16 X planes). Grid (10, NSPLIT, B_).
// ---------------------------------------------------------------------------
__global__ void __launch_bounds__(NT, 1)
gemm_sym_k(const __half* __restrict__ Xh, const __half* __restrict__ Xl,
           float* __restrict__ P) {
    extern __shared__ char smem[];
    const uint32_t sb = smem_u32(smem);
    const int tid = threadIdx.x;
    const int wid = tid >> 5;
    const int lane = tid & 31;
    const int bz = blockIdx.z;
    const int split = blockIdx.y;
    const int ti = c_ti[blockIdx.x];
    const int tj = c_tj[blockIdx.x];
    const int bm = ti * 128;
    const int bn = tj * 128;
    const int k0 = split * (N_ / NSPLIT);

    const size_t xb = (size_t)bz * ((size_t)C_ * N_);
    float acc[2][4][4];
    gemm_core_h(Xh + xb + (size_t)bm * N_ + k0, Xl + xb + (size_t)bm * N_ + k0, N_,
                Xh + xb + (size_t)bn * N_ + k0, Xl + xb + (size_t)bn * N_ + k0, N_,
                N_ / NSPLIT, sb, tid, wid, lane, acc);

    float* Pt = P + (((size_t)bz * 10 + blockIdx.x) * NSPLIT + split) * 16384;
    const int m0l = (wid & 3) * 32;
    const int n0l = (wid >> 2) * 32;

    #pragma unroll
    for (int mi = 0; mi < 2; ++mi)
        #pragma unroll
        for (int h = 0; h < 2; ++h) {
            const int row = m0l + mi * 16 + (lane >> 2) + h * 8;
            #pragma unroll
            for (int ni = 0; ni < 4; ++ni) {
                const int col = n0l + ni * 8 + (lane & 3) * 2;
                float2 v;
                v.x = acc[mi][ni][h * 2 + 0];
                v.y = acc[mi][ni][h * 2 + 1];
                *(float2*)(Pt + row * 128 + col) = v;
            }
        }
}

// ---------------------------------------------------------------------------
// Split-K combine (unchanged)
// ---------------------------------------------------------------------------
#define COMB_SMEM (128 * 132 * 4)
__global__ void __launch_bounds__(256, 1)
combine_sym(const float* __restrict__ P,
            __nv_bfloat16* __restrict__ Ghi, __nv_bfloat16* __restrict__ Glo) {
    extern __shared__ char smem[];
    float* st = (float*)smem;
    const int tid = threadIdx.x;
    const int t = blockIdx.x % 10;
    const int bz = blockIdx.x / 10;
    const int ti = c_ti[t];
    const int tj = c_tj[t];
    const int bm = ti * 128;
    const int bn = tj * 128;

    const float* Pb = P + ((size_t)bz * 10 + t) * NSPLIT * 16384;

    #pragma unroll
    for (int j = 0; j < 16; ++j) {
        const int cid = tid + 256 * j;
        const int row = cid >> 5;
        const int c4 = cid & 31;
        float4 s = *(const float4*)(Pb + cid * 4);
        #pragma unroll
        for (int sp = 1; sp < NSPLIT; ++sp) {
            const float4 a = *(const float4*)(Pb + sp * 16384 + cid * 4);
            s.x += a.x; s.y += a.y; s.z += a.z; s.w += a.w;
        }
        float* d = st + row * 132 + c4 * 4;
        d[0] = s.x; d[1] = s.y; d[2] = s.z; d[3] = s.w;
    }
    __syncthreads();

    __nv_bfloat16* Gh = Ghi + (size_t)bz * (C_ * C_);
    __nv_bfloat16* Gl = Glo + (size_t)bz * (C_ * C_);

    #pragma unroll
    for (int j = 0; j < 16; ++j) {
        const int cid = tid + 256 * j;
        const int row = cid >> 5;
        const int c4 = cid & 31;
        const float4 v = *(const float4*)(st + row * 132 + c4 * 4);
        const uint32_t h0 = cvt2(v.x, v.y), h1 = cvt2(v.z, v.w);
        const uint32_t l0 = cvt2(v.x - lof(h0), v.y - hif(h0));
        const uint32_t l1 = cvt2(v.z - lof(h1), v.w - hif(h1));
        const size_t o = (size_t)(bm + row) * C_ + bn + c4 * 4;
        *(uint2*)(Gh + o) = make_uint2(h0, h1);
        *(uint2*)(Gl + o) = make_uint2(l0, l1);
    }

    if (ti != tj) {
        #pragma unroll
        for (int j = 0; j < 16; ++j) {
            const int cid = tid + 256 * j;
            const int mr = cid >> 5;
            const int mc4 = cid & 31;
            float v0 = st[(mc4 * 4 + 0) * 132 + mr];
            float v1 = st[(mc4 * 4 + 1) * 132 + mr];
            float v2 = st[(mc4 * 4 + 2) * 132 + mr];
            float v3 = st[(mc4 * 4 + 3) * 132 + mr];
            const uint32_t h0 = cvt2(v0, v1), h1 = cvt2(v2, v3);
            const uint32_t l0 = cvt2(v0 - lof(h0), v1 - hif(h0));
            const uint32_t l1 = cvt2(v2 - lof(h1), v3 - hif(h1));
            const size_t o = (size_t)(bn + mr) * C_ + bm + mc4 * 4;
            *(uint2*)(Gh + o) = make_uint2(h0, h1);
            *(uint2*)(Gl + o) = make_uint2(l0, l1);
        }
    }
}

// ---------------------------------------------------------------------------
// X prep: PURE STREAMING fp32 -> fp16 hi/lo planes + row partial sums.
// ---------------------------------------------------------------------------
__global__ void __launch_bounds__(256)
prep_x(const float* __restrict__ x,
       __half* __restrict__ xh, __half* __restrict__ xl, float* __restrict__ rp) {
    const int tid = threadIdx.x;
    const int b = blockIdx.z;
    const int c0 = blockIdx.y * 32;
    const int n0 = blockIdx.x * 64;
    const float* s = x + (size_t)b * C_ * N_;
    __half* xhb = xh + (size_t)b * C_ * N_;
    __half* xlb = xl + (size_t)b * C_ * N_;

    const int r8 = tid >> 5;
    const int cp = tid & 31;
    #pragma unroll
    for (int k = 0; k < 4; ++k) {
        const int cr = k * 8 + r8;
        const size_t o = (size_t)(c0 + cr) * N_ + n0 + cp * 2;
        const float2 v = *(const float2*)(s + o);
        const __half2 h2 = __floats2half2_rn(v.x, v.y);
        const float2 hf = __half22float2(h2);
        const __half2 l2 = __floats2half2_rn(v.x - hf.x, v.y - hf.y);
        *(uint32_t*)(xhb + o) = *(const uint32_t*)&h2;
        *(uint32_t*)(xlb + o) = *(const uint32_t*)&l2;
        float ps = v.x + v.y;
        #pragma unroll
        for (int off = 16; off > 0; off >>= 1)
            ps += __shfl_down_sync(0xFFFFFFFFu, ps, off);
        if (cp == 0)
            rp[((size_t)b * C_ + c0 + cr) * 64 + blockIdx.x] = ps;
    }
}

// ---------------------------------------------------------------------------
// Reduce row partials
// ---------------------------------------------------------------------------
__global__ void __launch_bounds__(256)
reduce_r(const float* __restrict__ rp, float* __restrict__ r) {
    const int row = blockIdx.x * 8 + (threadIdx.x >> 5);
    const int lane = threadIdx.x & 31;
    float s = rp[(size_t)row * 64 + lane] + rp[(size_t)row * 64 + 32 + lane];
    #pragma unroll
    for (int off = 16; off > 0; off >>= 1)
        s += __shfl_down_sync(0xFFFFFFFFu, s, off);
    if (lane == 0) r[row] = s;
}

// ---------------------------------------------------------------------------
// Fused Wq + Wk split
// ---------------------------------------------------------------------------
__global__ void __launch_bounds__(256)
split_qk(const float* __restrict__ wq, const float* __restrict__ wk,
         __nv_bfloat16* __restrict__ qhi, __nv_bfloat16* __restrict__ qlo,
         __nv_bfloat16* __restrict__ khi, __nv_bfloat16* __restrict__ klo,
         long long n4) {
    long long i = (long long)blockIdx.x * blockDim.x + threadIdx.x;
    const long long stride = (long long)gridDim.x * blockDim.x;
    for (; i < n4; i += stride) {
        float4 v = ((const float4*)wq)[i];
        uint32_t h0 = cvt2(v.x, v.y), h1 = cvt2(v.z, v.w);
        uint32_t l0 = cvt2(v.x - lof(h0), v.y - hif(h0));
        uint32_t l1 = cvt2(v.z - lof(h1), v.w - hif(h1));
        ((uint2*)qhi)[i] = make_uint2(h0, h1);
        ((uint2*)qlo)[i] = make_uint2(l0, l1);
        v = ((const float4*)wk)[i];
        h0 = cvt2(v.x, v.y); h1 = cvt2(v.z, v.w);
        l0 = cvt2(v.x - lof(h0), v.y - hif(h0));
        l1 = cvt2(v.z - lof(h1), v.w - hif(h1));
        ((uint2*)khi)[i] = make_uint2(h0, h1);
        ((uint2*)klo)[i] = make_uint2(l0, l1);
    }
}

// ---------------------------------------------------------------------------
// qr = Wq r, kr = Wk r (all batches)
// ---------------------------------------------------------------------------
__global__ void __launch_bounds__(256) matvec_qk_kernel(const float* __restrict__ Wq,
                                                        const float* __restrict__ Wk,
                                                        const float* __restrict__ r,
                                                        float* __restrict__ qr,
                                                        float* __restrict__ kr) {
    const int b = blockIdx.y;
    const int warp = threadIdx.x >> 5;
    const int lane = threadIdx.x & 31;
    const int o = blockIdx.x * 8 + warp;
    const float* rb = r + b * C_;
    float sq = 0.f, sk = 0.f;
    for (int i = lane; i < C_; i += 32) {
        float rv = rb[i];
        sq += Wq[(size_t)o * C_ + i] * rv;
        sk += Wk[(size_t)o * C_ + i] * rv;
    }
    #pragma unroll
    for (int off = 16; off > 0; off >>= 1) {
        sq += __shfl_down_sync(0xFFFFFFFFu, sq, off);
        sk += __shfl_down_sync(0xFFFFFFFFu, sk, off);
    }
    if (lane == 0) { qr[b * C_ + o] = sq; kr[b * C_ + o] = sk; }
}

// ---------------------------------------------------------------------------
// Transpose + fp16 convert (for Wv -> WvT fp16 hi plane)
// ---------------------------------------------------------------------------
__global__ void __launch_bounds__(256)
transpose_cvt_h(const float* __restrict__ s, __half* __restrict__ dh, int R, int Cc) {
    __shared__ float t[32][33];
    const int tx = threadIdx.x & 31, ty = threadIdx.x >> 5;
    const int r0 = blockIdx.y * 32, c0 = blockIdx.x * 32;
    #pragma unroll
    for (int k = 0; k < 4; ++k)
        t[ty + 8 * k][tx] = s[(size_t)(r0 + ty + 8 * k) * Cc + c0 + tx];
    __syncthreads();
    #pragma unroll
    for (int k = 0; k < 4; ++k) {
        const int i = ty + 8 * k;
        dh[(size_t)(c0 + i) * R + r0 + tx] = __float2half(t[tx][i]);
    }
}

// ---------------------------------------------------------------------------
// Softmax with rank-1 bias corrections; attn -> fp16 hi/lo planes + beta
// ---------------------------------------------------------------------------
__global__ void __launch_bounds__(256)
softmax_beta_kernel(const float* __restrict__ S,
                    const float* __restrict__ qr, const float* __restrict__ kr,
                    const float* __restrict__ bq, const float* __restrict__ bk,
                    const float* __restrict__ bv,
                    __half* __restrict__ Ahi, __half* __restrict__ Alo,
                    float* __restrict__ beta) {
    __shared__ float sm[256];
    const int row = blockIdx.x;
    const int b = row >> 9;
    const int c = row & (C_ - 1);
    const float* Sr = S + (size_t)row * C_;
    const float* krb = kr + b * C_;
    const float qrc = qr[row];
    const float bqc = bq[c];
    const float scale = rsqrtf((float)C_);
    const int t = threadIdx.x;

    float v[2];
    float mx = -1e30f;
    #pragma unroll
    for (int u = 0; u < 2; ++u) {
        const int d = t + u * 256;
        float s = (Sr[d] + qrc * bk[d] + bqc * krb[d] + (float)N_ * bqc * bk[d]) * scale;
        v[u] = s;
        mx = fmaxf(mx, s);
    }
    sm[t] = mx; __syncthreads();
    #pragma unroll
    for (int off = 128; off > 0; off >>= 1) {
        if (t < off) sm[t] = fmaxf(sm[t], sm[t + off]);
        __syncthreads();
    }
    mx = sm[0];
    __syncthreads();

    float sum = 0.f;
    #pragma unroll
    for (int u = 0; u < 2; ++u) { v[u] = expf(v[u] - mx); sum += v[u]; }
    sm[t] = sum; __syncthreads();
    #pragma unroll
    for (int off = 128; off > 0; off >>= 1) {
        if (t < off) sm[t] += sm[t + off];
        __syncthreads();
    }
    const float inv = 1.f / sm[0];
    __syncthreads();

    float bc = 0.f;
    #pragma unroll
    for (int u = 0; u < 2; ++u) {
        const int d = t + u * 256;
        const float p = v[u] * inv;
        const __half h = __float2half(p);
        const __half l = __float2half(p - __half2float(h));
        Ahi[(size_t)row * C_ + d] = h;
        Alo[(size_t)row * C_ + d] = l;
        bc += p * bv[d];
    }
    sm[t] = bc; __syncthreads();
    #pragma unroll
    for (int off = 128; off > 0; off >>= 1) {
        if (t < off) sm[t] += sm[t + off];
        __syncthreads();
    }
    if (t == 0) beta[row] = sm[0];
}

// ---------------------------------------------------------------------------
extern "C" void kernel_launch(void* const* d_in, const int* in_sizes, int n_in,
                              void* d_out, int out_size) {
    const float* x  = (const float*)d_in[0];
    const float* Wq = (const float*)d_in[1];
    const float* bq = (const float*)d_in[2];
    const float* Wk = (const float*)d_in[3];
    const float* bk = (const float*)d_in[4];
    const float* Wv = (const float*)d_in[5];
    const float* bv = (const float*)d_in[6];
    float* out = (float*)d_out;

    __nv_bfloat16 *Ghi, *Glo, *T1hi, *T1lo, *Wqhi, *Wqlo, *Wkhi, *Wklo;
    __half *Xh, *Xl, *ATh, *ATl, *Mvh, *WvTh;
    float *S, *P, *rp, *r, *qr, *kr, *beta;
    cudaGetSymbolAddress((void**)&Xh, g_Xh);       cudaGetSymbolAddress((void**)&Xl, g_Xl);
    cudaGetSymbolAddress((void**)&Ghi, g_Ghi);     cudaGetSymbolAddress((void**)&Glo, g_Glo);
    cudaGetSymbolAddress((void**)&T1hi, g_T1hi);   cudaGetSymbolAddress((void**)&T1lo, g_T1lo);
    cudaGetSymbolAddress((void**)&ATh, g_ATh);     cudaGetSymbolAddress((void**)&ATl, g_ATl);
    cudaGetSymbolAddress((void**)&Mvh, g_Mvh);
    cudaGetSymbolAddress((void**)&Wqhi, g_Wqhi);   cudaGetSymbolAddress((void**)&Wqlo, g_Wqlo);
    cudaGetSymbolAddress((void**)&Wkhi, g_Wkhi);   cudaGetSymbolAddress((void**)&Wklo, g_Wklo);
    cudaGetSymbolAddress((void**)&WvTh, g_WvTh);
    cudaGetSymbolAddress((void**)&S, g_S);         cudaGetSymbolAddress((void**)&P, g_P);
    cudaGetSymbolAddress((void**)&rp, g_rp);       cudaGetSymbolAddress((void**)&r, g_r);
    cudaGetSymbolAddress((void**)&qr, g_qr);
    cudaGetSymbolAddress((void**)&kr, g_kr); cudaGetSymbolAddress((void**)&beta, g_beta);

    const long long CC = (long long)C_ * C_;

    cudaFuncSetAttribute(gemm_mma<0>, cudaFuncAttributeMaxDynamicSharedMemorySize, GEMM_SMEM);
    cudaFuncSetAttribute(gemm_mma<1>, cudaFuncAttributeMaxDynamicSharedMemorySize, GEMM_SMEM);
    cudaFuncSetAttribute(gemm_sym_k,  cudaFuncAttributeMaxDynamicSharedMemorySize, GEMM_SMEM);
    cudaFuncSetAttribute(gemm_mv,     cudaFuncAttributeMaxDynamicSharedMemorySize, MV_SMEM);
    cudaFuncSetAttribute(gemm_out,    cudaFuncAttributeMaxDynamicSharedMemorySize, MV_SMEM);
    cudaFuncSetAttribute(combine_sym, cudaFuncAttributeMaxDynamicSharedMemorySize, COMB_SMEM);

    // Launch order keeps gemm_sym_k at index 3 (the slot ncu captures).
    prep_x<<<dim3(N_ / 64, C_ / 32, B_), 256>>>(x, Xh, Xl, rp);                      // 0
    reduce_r<<<B_ * C_ / 8, 256>>>(rp, r);                                           // 1
    split_qk<<<256, 256>>>(Wq, Wk, Wqhi, Wqlo, Wkhi, Wklo, CC / 4);                  // 2

    // G = X X^T, symmetric upper-triangle, split-K=NSPLIT -> fp32 partials
    gemm_sym_k<<<dim3(10, NSPLIT, B_), NT, GEMM_SMEM>>>(Xh, Xl, P);                  // 3

    combine_sym<<<10 * B_, 256, COMB_SMEM>>>(P, Ghi, Glo);                           // 4
    transpose_cvt_h<<<dim3(C_ / 32, C_ / 32), 256>>>(Wv, WvTh, C_, C_);              // 5
    matvec_qk_kernel<<<dim3(C_ / 8, B_), 256>>>(Wq, Wk, r, qr, kr);                  // 6

    // T1 = Wq G (bf16 3-term)
    gemm_mma<1><<<dim3(4, 4, B_), NT, GEMM_SMEM>>>(
        Wqhi, Wqlo, C_, 0,  Ghi, Glo, C_, CC,
        nullptr, T1hi, T1lo, C_, CC, C_);

    // S = T1 Wk^T (bf16 3-term, fp32 out)
    gemm_mma<0><<<dim3(4, 4, B_), NT, GEMM_SMEM>>>(
        T1hi, T1lo, C_, CC,  Wkhi, Wklo, C_, 0,
        S, nullptr, nullptr, C_, CC, C_);

    // softmax(+rank-1 corrections) -> attn fp16 hi/lo, beta = attn bv
    softmax_beta_kernel<<<B_ * C_, 256>>>(S, qr, kr, bq, bk, bv, ATh, ATl, beta);

    // Mv = (ATh+ATl) WvTh^T (fp16 2-term) -> fp16 hi only
    gemm_mv<<<dim3(4, 4, B_), NT, MV_SMEM>>>(ATh, ATl, WvTh, Mvh);

    // out = Mvh * Xh + beta  (fp16 1-term, wide CTA 128x256, trans-B)
    gemm_out<<<dim3(16, 4, B_), NT, MV_SMEM>>>(Mvh, Xh, out, beta);
}